// round 2
// baseline (speedup 1.0000x reference)
#include <cuda_runtime.h>
#include <math.h>

#define Hh   4
#define Cc   64
#define HC   256
#define INC  256
#define HIDD 64
#define OUTC 40
#define NEG  0.2f

#define N_MAX  50048
#define E_MAX  800000
#define ET_MAX (E_MAX + N_MAX)

// ---------------- static scratch (no allocations allowed) ----------------
__device__ float    g_h[(size_t)N_MAX * HC];       // lin-transformed features [N,256]
__device__ float    g_agg[(size_t)N_MAX * HC];     // attention-aggregated output [N,256]
__device__ float    g_hid[(size_t)N_MAX * HIDD];   // MLP hidden [N,64]
__device__ float    g_asrc[N_MAX * Hh];
__device__ float    g_adst[N_MAX * Hh];
__device__ unsigned g_m[N_MAX * Hh];               // segment max, ordered-uint encoded
__device__ float    g_den[N_MAX * Hh];             // segment softmax denom
__device__ float    g_e[(size_t)ET_MAX * Hh];      // per-edge logits, then exp()

// ordered encoding so unsigned atomicMax == float max
__device__ __forceinline__ unsigned fenc(float f) {
    unsigned u = __float_as_uint(f);
    return (u & 0x80000000u) ? ~u : (u | 0x80000000u);
}
__device__ __forceinline__ float fdec(unsigned k) {
    return __uint_as_float((k & 0x80000000u) ? (k ^ 0x80000000u) : ~k);
}

__device__ __forceinline__ int clampi(int v, int n) {
    return (v < 0) ? 0 : ((v >= n) ? n - 1 : v);
}

// ---------------- init: zero agg/denom, reset max keys ----------------
__global__ void gnn_init_kernel(int Nn) {
    int i = blockIdx.x * blockDim.x + threadIdx.x;
    int tot4 = Nn * (HC / 4);
    if (i < tot4) ((float4*)g_agg)[i] = make_float4(0.f, 0.f, 0.f, 0.f);
    if (i < Nn * Hh) { g_m[i] = 0u; g_den[i] = 0.f; }
}

// ---------------- h = x @ W  (M x 256 x 256), 128x128x16 tiles, 8x8 micro ----------------
__global__ void sgemm_h_kernel(const float* __restrict__ X,
                               const float* __restrict__ Wm, int M) {
    __shared__ float As[16][128];
    __shared__ float Bs[16][128];
    int t  = threadIdx.x;
    int tx = t & 15, ty = t >> 4;
    int m0 = blockIdx.x * 128;
    int n0 = blockIdx.y * 128;

    float acc[8][8];
#pragma unroll
    for (int i = 0; i < 8; i++)
#pragma unroll
        for (int j = 0; j < 8; j++) acc[i][j] = 0.f;

    int lr = t >> 2;          // 0..63
    int lc = (t & 3) << 2;    // 0,4,8,12
    int wr = t >> 5;          // 0..7
    int wc = (t & 31) << 2;   // 0..124

    for (int kk = 0; kk < 256; kk += 16) {
#pragma unroll
        for (int p = 0; p < 2; p++) {
            int row = lr + p * 64;
            float4 v = make_float4(0.f, 0.f, 0.f, 0.f);
            if (m0 + row < M)
                v = *(const float4*)(X + (size_t)(m0 + row) * 256 + kk + lc);
            As[lc + 0][row] = v.x; As[lc + 1][row] = v.y;
            As[lc + 2][row] = v.z; As[lc + 3][row] = v.w;
        }
#pragma unroll
        for (int p = 0; p < 2; p++) {
            int row = wr + p * 8;
            *(float4*)(&Bs[row][wc]) =
                *(const float4*)(Wm + (size_t)(kk + row) * 256 + n0 + wc);
        }
        __syncthreads();
#pragma unroll
        for (int k = 0; k < 16; k++) {
            float a[8], b[8];
#pragma unroll
            for (int i = 0; i < 8; i++) a[i] = As[k][ty * 8 + i];
#pragma unroll
            for (int j = 0; j < 8; j++) b[j] = Bs[k][tx * 8 + j];
#pragma unroll
            for (int i = 0; i < 8; i++)
#pragma unroll
                for (int j = 0; j < 8; j++) acc[i][j] = fmaf(a[i], b[j], acc[i][j]);
        }
        __syncthreads();
    }
#pragma unroll
    for (int i = 0; i < 8; i++) {
        int row = m0 + ty * 8 + i;
        if (row < M) {
#pragma unroll
            for (int j = 0; j < 8; j += 4) {
                float4 v = make_float4(acc[i][j], acc[i][j+1], acc[i][j+2], acc[i][j+3]);
                *(float4*)(g_h + (size_t)row * 256 + n0 + tx * 8 + j) = v;
            }
        }
    }
}

// ---------------- a_src / a_dst: warp per (node, head) ----------------
__global__ void att_kernel(const float* __restrict__ att_src,
                           const float* __restrict__ att_dst, int Nn) {
    int w    = (blockIdx.x * blockDim.x + threadIdx.x) >> 5;
    int lane = threadIdx.x & 31;
    if (w >= Nn * Hh) return;
    int n = w >> 2, hd = w & 3;
    const float* hrow = g_h + (size_t)n * HC + hd * Cc;
    float v1 = hrow[lane], v2 = hrow[lane + 32];
    float s = v1 * __ldg(att_src + hd * Cc + lane) + v2 * __ldg(att_src + hd * Cc + lane + 32);
    float d = v1 * __ldg(att_dst + hd * Cc + lane) + v2 * __ldg(att_dst + hd * Cc + lane + 32);
#pragma unroll
    for (int o = 16; o; o >>= 1) {
        s += __shfl_xor_sync(0xffffffffu, s, o);
        d += __shfl_xor_sync(0xffffffffu, d, o);
    }
    if (lane == 0) { g_asrc[n * Hh + hd] = s; g_adst[n * Hh + hd] = d; }
}

// ---------------- edge pass 1: logits + segment max ----------------
__global__ void edge1_kernel(const int* __restrict__ ei, int E, int ET, int Nn) {
    int e = blockIdx.x * blockDim.x + threadIdx.x;
    if (e >= ET) return;
    int s, d;
    if (e < E) { s = clampi(ei[e], Nn); d = clampi(ei[(size_t)E + e], Nn); }
    else       { s = d = e - E; }
    float4 as = *(const float4*)(g_asrc + (size_t)s * Hh);
    float4 ad = *(const float4*)(g_adst + (size_t)d * Hh);
    float v[4];
    v[0] = as.x + ad.x; v[1] = as.y + ad.y; v[2] = as.z + ad.z; v[3] = as.w + ad.w;
#pragma unroll
    for (int h = 0; h < 4; h++) v[h] = (v[h] > 0.f) ? v[h] : NEG * v[h];
    *(float4*)(g_e + (size_t)e * Hh) = make_float4(v[0], v[1], v[2], v[3]);
    unsigned* mb = g_m + (size_t)d * Hh;
#pragma unroll
    for (int h = 0; h < 4; h++) atomicMax(mb + h, fenc(v[h]));
}

// ---------------- edge pass 2: exp + segment sum (denom) ----------------
__global__ void edge2_kernel(const int* __restrict__ ei, int E, int ET, int Nn) {
    int e = blockIdx.x * blockDim.x + threadIdx.x;
    if (e >= ET) return;
    int d = (e < E) ? clampi(ei[(size_t)E + e], Nn) : (e - E);
    float4 ev = *(const float4*)(g_e + (size_t)e * Hh);
    uint4  mk = *(const uint4*)(g_m + (size_t)d * Hh);
    float ex[4];
    ex[0] = expf(ev.x - fdec(mk.x));
    ex[1] = expf(ev.y - fdec(mk.y));
    ex[2] = expf(ev.z - fdec(mk.z));
    ex[3] = expf(ev.w - fdec(mk.w));
    *(float4*)(g_e + (size_t)e * Hh) = make_float4(ex[0], ex[1], ex[2], ex[3]);
    float* db = g_den + (size_t)d * Hh;
#pragma unroll
    for (int h = 0; h < 4; h++) atomicAdd(db + h, ex[h]);
}

// ---------------- scatter: agg[dst] += alpha * h[src]; 64 threads/edge ----------------
__global__ void scatter_kernel(const int* __restrict__ ei, int E, int ET, int Nn) {
    int gid = blockIdx.x * blockDim.x + threadIdx.x;
    int e = gid >> 6;
    if (e >= ET) return;
    int c4 = (gid & 63) << 2;     // float4 offset within 256-wide row
    int hd = c4 >> 6;             // head for this column block
    int s, d;
    if (e < E) { s = clampi(ei[e], Nn); d = clampi(ei[(size_t)E + e], Nn); }
    else       { s = d = e - E; }
    float alpha = g_e[(size_t)e * Hh + hd] / g_den[(size_t)d * Hh + hd];
    float4 hv = *(const float4*)(g_h + (size_t)s * HC + c4);
    float* base = g_agg + (size_t)d * HC + c4;
    atomicAdd(base + 0, alpha * hv.x);
    atomicAdd(base + 1, alpha * hv.y);
    atomicAdd(base + 2, alpha * hv.z);
    atomicAdd(base + 3, alpha * hv.w);
}

// ---------------- hid = relu(relu(agg+bias_conv) @ W1 + b1); 256x64x16 tiles ----------------
__global__ void mlp1_kernel(const float* __restrict__ bias_conv,
                            const float* __restrict__ W1,
                            const float* __restrict__ b1, int M) {
    __shared__ float As[16][256];
    __shared__ float Bs[16][64];
    int t  = threadIdx.x;
    int tx = t & 15, ty = t >> 4;
    int m0 = blockIdx.x * 256;

    float acc[16][4];
#pragma unroll
    for (int i = 0; i < 16; i++)
#pragma unroll
        for (int j = 0; j < 4; j++) acc[i][j] = 0.f;

    int lr = t >> 2;         // 0..63
    int lc = (t & 3) << 2;
    int wr = t >> 4;         // 0..15
    int wc = (t & 15) << 2;  // 0..60

    for (int kk = 0; kk < 256; kk += 16) {
        float4 bv = *(const float4*)(bias_conv + kk + lc);
#pragma unroll
        for (int p = 0; p < 4; p++) {
            int row = lr + p * 64;
            float4 v = make_float4(0.f, 0.f, 0.f, 0.f);
            if (m0 + row < M)
                v = *(const float4*)(g_agg + (size_t)(m0 + row) * 256 + kk + lc);
            As[lc + 0][row] = fmaxf(v.x + bv.x, 0.f);
            As[lc + 1][row] = fmaxf(v.y + bv.y, 0.f);
            As[lc + 2][row] = fmaxf(v.z + bv.z, 0.f);
            As[lc + 3][row] = fmaxf(v.w + bv.w, 0.f);
        }
        *(float4*)(&Bs[wr][wc]) = *(const float4*)(W1 + (size_t)(kk + wr) * 64 + wc);
        __syncthreads();
#pragma unroll
        for (int k = 0; k < 16; k++) {
            float a[16], b[4];
#pragma unroll
            for (int i = 0; i < 16; i++) a[i] = As[k][ty * 16 + i];
#pragma unroll
            for (int j = 0; j < 4; j++)  b[j] = Bs[k][tx * 4 + j];
#pragma unroll
            for (int i = 0; i < 16; i++)
#pragma unroll
                for (int j = 0; j < 4; j++) acc[i][j] = fmaf(a[i], b[j], acc[i][j]);
        }
        __syncthreads();
    }
    float4 b1v = *(const float4*)(b1 + tx * 4);
#pragma unroll
    for (int i = 0; i < 16; i++) {
        int row = m0 + ty * 16 + i;
        if (row < M) {
            float4 v;
            v.x = fmaxf(acc[i][0] + b1v.x, 0.f);
            v.y = fmaxf(acc[i][1] + b1v.y, 0.f);
            v.z = fmaxf(acc[i][2] + b1v.z, 0.f);
            v.w = fmaxf(acc[i][3] + b1v.w, 0.f);
            *(float4*)(g_hid + (size_t)row * HIDD + tx * 4) = v;
        }
    }
}

// ---------------- out = hid @ W2 + b2 ----------------
__global__ void mlp2_kernel(const float* __restrict__ W2, const float* __restrict__ b2,
                            float* __restrict__ out, int M) {
    __shared__ float sW2[HIDD * OUTC];
    __shared__ float sb2[OUTC];
    __shared__ float sX[128 * 65];
    int t = threadIdx.x;
    for (int i = t; i < HIDD * OUTC; i += 128) sW2[i] = W2[i];
    if (t < OUTC) sb2[t] = b2[t];
    int base = blockIdx.x * 128;
    for (int i = t; i < 128 * HIDD; i += 128) {
        int r = i >> 6, c = i & 63;
        float v = (base + r < M) ? g_hid[(size_t)(base + r) * HIDD + c] : 0.f;
        sX[r * 65 + c] = v;
    }
    __syncthreads();
    int node = base + t;
    if (node >= M) return;
    float acc[OUTC];
#pragma unroll
    for (int j = 0; j < OUTC; j++) acc[j] = sb2[j];
#pragma unroll 4
    for (int k = 0; k < HIDD; k++) {
        float xv = sX[t * 65 + k];
#pragma unroll
        for (int j = 0; j < OUTC; j++) acc[j] = fmaf(xv, sW2[k * OUTC + j], acc[j]);
    }
#pragma unroll
    for (int j = 0; j < OUTC; j++) out[(size_t)node * OUTC + j] = acc[j];
}

// ---------------- launch ----------------
extern "C" void kernel_launch(void* const* d_in, const int* in_sizes, int n_in,
                              void* d_out, int out_size) {
    const float* x         = (const float*)d_in[0];
    const int*   ei        = (const int*)d_in[1];      // int32 (JAX x64 disabled downcasts int64)
    const float* W         = (const float*)d_in[2];
    const float* att_src   = (const float*)d_in[3];
    const float* att_dst   = (const float*)d_in[4];
    const float* bias_conv = (const float*)d_in[5];
    const float* W1        = (const float*)d_in[6];
    const float* b1        = (const float*)d_in[7];
    const float* W2        = (const float*)d_in[8];
    const float* b2        = (const float*)d_in[9];
    float*       out       = (float*)d_out;

    int Nn = in_sizes[0] / INC;
    int E  = in_sizes[1] / 2;
    int ET = E + Nn;

    gnn_init_kernel<<<(Nn * 64 + 255) / 256, 256>>>(Nn);

    dim3 g1((Nn + 127) / 128, 2);
    sgemm_h_kernel<<<g1, 256>>>(x, W, Nn);

    att_kernel<<<(Nn * Hh * 32 + 255) / 256, 256>>>(att_src, att_dst, Nn);

    edge1_kernel<<<(ET + 255) / 256, 256>>>(ei, E, ET, Nn);
    edge2_kernel<<<(ET + 255) / 256, 256>>>(ei, E, ET, Nn);

    long long sthreads = (long long)ET * 64;
    scatter_kernel<<<(unsigned)((sthreads + 255) / 256), 256>>>(ei, E, ET, Nn);

    mlp1_kernel<<<(Nn + 255) / 256, 256>>>(bias_conv, W1, b1, Nn);
    mlp2_kernel<<<(Nn + 127) / 128, 128>>>(W2, b2, out, Nn);
}

// round 3
// speedup vs baseline: 2.1316x; 2.1316x over previous
#include <cuda_runtime.h>
#include <math.h>

#define Hh   4
#define Cc   64
#define HC   256
#define INC  256
#define HIDD 64
#define OUTC 40
#define NEG  0.2f

#define N_MAX  50048
#define E_MAX  800000
#define ET_MAX (E_MAX + N_MAX)

// ---------------- static scratch ----------------
__device__ float g_h[(size_t)N_MAX * HC];       // lin-transformed features [N,256]
__device__ float g_agg[(size_t)N_MAX * HC];     // relu(agg/den + bias) [N,256]
__device__ float g_hid[(size_t)N_MAX * HIDD];   // MLP hidden [N,64]
__device__ float g_asrc[N_MAX * Hh];
__device__ float g_adst[N_MAX * Hh];
__device__ int   g_deg[N_MAX];                  // in-degree (incl self-loop)
__device__ int   g_cnt[N_MAX];                  // fill cursor per node
__device__ int   g_off[N_MAX];                  // CSR range start per node
__device__ int   g_cursor;                      // global slot cursor
__device__ int   g_csr_src[ET_MAX];             // CSR: src node per slot
__device__ float g_ee[(size_t)ET_MAX * Hh];     // CSR: exp(logit) per slot per head

__device__ __forceinline__ int clampi(int v, int n) {
    return (v < 0) ? 0 : ((v >= n) ? n - 1 : v);
}

// ---------------- init: zero counters ----------------
__global__ void gnn_init_kernel(int Nn) {
    int i = blockIdx.x * blockDim.x + threadIdx.x;
    if (i < Nn) { g_deg[i] = 0; g_cnt[i] = 0; }
    if (i == 0) g_cursor = 0;
}

// ---------------- h = x @ W, 128x128x16 tiles, 8x8 micro, double-buffered smem ----------------
__global__ void sgemm_h_kernel(const float* __restrict__ X,
                               const float* __restrict__ Wm, int M) {
    __shared__ float As[2][16][128];
    __shared__ float Bs[2][16][128];
    int t  = threadIdx.x;
    int tx = t & 15, ty = t >> 4;
    int m0 = blockIdx.x * 128;
    int n0 = blockIdx.y * 128;

    float acc[8][8];
#pragma unroll
    for (int i = 0; i < 8; i++)
#pragma unroll
        for (int j = 0; j < 8; j++) acc[i][j] = 0.f;

    int lr = t >> 2;          // 0..63
    int lc = (t & 3) << 2;    // 0,4,8,12
    int wr = t >> 5;          // 0..7
    int wc = (t & 31) << 2;   // 0..124

    // prologue: load k-tile 0 into buffer 0
    {
#pragma unroll
        for (int p = 0; p < 2; p++) {
            int row = lr + p * 64;
            float4 v = make_float4(0.f, 0.f, 0.f, 0.f);
            if (m0 + row < M)
                v = *(const float4*)(X + (size_t)(m0 + row) * 256 + lc);
            As[0][lc + 0][row] = v.x; As[0][lc + 1][row] = v.y;
            As[0][lc + 2][row] = v.z; As[0][lc + 3][row] = v.w;
        }
#pragma unroll
        for (int p = 0; p < 2; p++) {
            int row = wr + p * 8;
            *(float4*)(&Bs[0][row][wc]) =
                *(const float4*)(Wm + (size_t)row * 256 + n0 + wc);
        }
    }
    __syncthreads();

    int buf = 0;
    for (int kk = 0; kk < 256; kk += 16) {
        bool more = (kk + 16) < 256;
        float4 na[2], nb[2];
        if (more) {
#pragma unroll
            for (int p = 0; p < 2; p++) {
                int row = lr + p * 64;
                na[p] = make_float4(0.f, 0.f, 0.f, 0.f);
                if (m0 + row < M)
                    na[p] = *(const float4*)(X + (size_t)(m0 + row) * 256 + kk + 16 + lc);
            }
#pragma unroll
            for (int p = 0; p < 2; p++) {
                int row = wr + p * 8;
                nb[p] = *(const float4*)(Wm + (size_t)(kk + 16 + row) * 256 + n0 + wc);
            }
        }
#pragma unroll
        for (int k = 0; k < 16; k++) {
            float a[8], b[8];
#pragma unroll
            for (int i = 0; i < 8; i++) a[i] = As[buf][k][ty * 8 + i];
#pragma unroll
            for (int j = 0; j < 8; j++) b[j] = Bs[buf][k][tx * 8 + j];
#pragma unroll
            for (int i = 0; i < 8; i++)
#pragma unroll
                for (int j = 0; j < 8; j++) acc[i][j] = fmaf(a[i], b[j], acc[i][j]);
        }
        if (more) {
            int nb_ = buf ^ 1;
#pragma unroll
            for (int p = 0; p < 2; p++) {
                int row = lr + p * 64;
                As[nb_][lc + 0][row] = na[p].x; As[nb_][lc + 1][row] = na[p].y;
                As[nb_][lc + 2][row] = na[p].z; As[nb_][lc + 3][row] = na[p].w;
            }
#pragma unroll
            for (int p = 0; p < 2; p++) {
                int row = wr + p * 8;
                *(float4*)(&Bs[nb_][row][wc]) = nb[p];
            }
        }
        __syncthreads();
        buf ^= 1;
    }
#pragma unroll
    for (int i = 0; i < 8; i++) {
        int row = m0 + ty * 8 + i;
        if (row < M) {
#pragma unroll
            for (int j = 0; j < 8; j += 4) {
                float4 v = make_float4(acc[i][j], acc[i][j+1], acc[i][j+2], acc[i][j+3]);
                *(float4*)(g_h + (size_t)row * 256 + n0 + tx * 8 + j) = v;
            }
        }
    }
}

// ---------------- a_src / a_dst: warp per (node, head) ----------------
__global__ void att_kernel(const float* __restrict__ att_src,
                           const float* __restrict__ att_dst, int Nn) {
    int w    = (blockIdx.x * blockDim.x + threadIdx.x) >> 5;
    int lane = threadIdx.x & 31;
    if (w >= Nn * Hh) return;
    int n = w >> 2, hd = w & 3;
    const float* hrow = g_h + (size_t)n * HC + hd * Cc;
    float v1 = hrow[lane], v2 = hrow[lane + 32];
    float s = v1 * __ldg(att_src + hd * Cc + lane) + v2 * __ldg(att_src + hd * Cc + lane + 32);
    float d = v1 * __ldg(att_dst + hd * Cc + lane) + v2 * __ldg(att_dst + hd * Cc + lane + 32);
#pragma unroll
    for (int o = 16; o; o >>= 1) {
        s += __shfl_xor_sync(0xffffffffu, s, o);
        d += __shfl_xor_sync(0xffffffffu, d, o);
    }
    if (lane == 0) { g_asrc[n * Hh + hd] = s; g_adst[n * Hh + hd] = d; }
}

// ---------------- edge pass 1: count in-degrees ----------------
__global__ void edge_deg_kernel(const int* __restrict__ ei, int E, int ET, int Nn) {
    int e = blockIdx.x * blockDim.x + threadIdx.x;
    if (e >= ET) return;
    int d = (e < E) ? clampi(ei[(size_t)E + e], Nn) : (e - E);
    atomicAdd(&g_deg[d], 1);
}

// ---------------- offsets: contiguous range per node (order-free) ----------------
__global__ void offsets_kernel(int Nn) {
    int n = blockIdx.x * blockDim.x + threadIdx.x;
    if (n >= Nn) return;
    g_off[n] = atomicAdd(&g_cursor, g_deg[n]);
}

// ---------------- edge pass 2: exp(leaky(logit)) -> CSR slots ----------------
__global__ void edge_fill_kernel(const int* __restrict__ ei, int E, int ET, int Nn) {
    int e = blockIdx.x * blockDim.x + threadIdx.x;
    if (e >= ET) return;
    int s, d;
    if (e < E) { s = clampi(ei[e], Nn); d = clampi(ei[(size_t)E + e], Nn); }
    else       { s = d = e - E; }
    float4 as = *(const float4*)(g_asrc + (size_t)s * Hh);
    float4 ad = *(const float4*)(g_adst + (size_t)d * Hh);
    float v[4];
    v[0] = as.x + ad.x; v[1] = as.y + ad.y; v[2] = as.z + ad.z; v[3] = as.w + ad.w;
#pragma unroll
    for (int h = 0; h < 4; h++) {
        float lv = (v[h] > 0.f) ? v[h] : NEG * v[h];
        v[h] = __expf(lv);
    }
    int slot = g_off[d] + atomicAdd(&g_cnt[d], 1);
    g_csr_src[slot] = s;
    *(float4*)(g_ee + (size_t)slot * Hh) = make_float4(v[0], v[1], v[2], v[3]);
}

// ---------------- aggregation: 64 threads/node, register acc, inline denom ----------------
__global__ void agg_kernel(const float* __restrict__ bias_conv, int Nn) {
    int node = blockIdx.x * 4 + (threadIdx.x >> 6);
    int l    = threadIdx.x & 63;      // float4 column index 0..63
    if (node >= Nn) return;
    int beg = g_off[node];
    int deg = g_deg[node];
    int hd  = l >> 4;                 // head of this column block

    float4 acc = make_float4(0.f, 0.f, 0.f, 0.f);
    float den = 0.f;
#pragma unroll 2
    for (int i = 0; i < deg; i++) {
        int slot = beg + i;
        int s    = g_csr_src[slot];
        float a  = g_ee[(size_t)slot * Hh + hd];
        float4 hv = *(const float4*)(g_h + (size_t)s * HC + l * 4);
        den += a;
        acc.x = fmaf(a, hv.x, acc.x);
        acc.y = fmaf(a, hv.y, acc.y);
        acc.z = fmaf(a, hv.z, acc.z);
        acc.w = fmaf(a, hv.w, acc.w);
    }
    float r = 1.f / den;
    float4 bv = *(const float4*)(bias_conv + l * 4);
    float4 o;
    o.x = fmaxf(fmaf(acc.x, r, bv.x), 0.f);
    o.y = fmaxf(fmaf(acc.y, r, bv.y), 0.f);
    o.z = fmaxf(fmaf(acc.z, r, bv.z), 0.f);
    o.w = fmaxf(fmaf(acc.w, r, bv.w), 0.f);
    *(float4*)(g_agg + (size_t)node * HC + l * 4) = o;
}

// ---------------- hid = relu(g_agg @ W1 + b1) (bias/relu already in g_agg) ----------------
__global__ void mlp1_kernel(const float* __restrict__ W1,
                            const float* __restrict__ b1, int M) {
    __shared__ float As[16][256];
    __shared__ float Bs[16][64];
    int t  = threadIdx.x;
    int tx = t & 15, ty = t >> 4;
    int m0 = blockIdx.x * 256;

    float acc[16][4];
#pragma unroll
    for (int i = 0; i < 16; i++)
#pragma unroll
        for (int j = 0; j < 4; j++) acc[i][j] = 0.f;

    int lr = t >> 2;         // 0..63
    int lc = (t & 3) << 2;
    int wr = t >> 4;         // 0..15
    int wc = (t & 15) << 2;  // 0..60

    for (int kk = 0; kk < 256; kk += 16) {
#pragma unroll
        for (int p = 0; p < 4; p++) {
            int row = lr + p * 64;
            float4 v = make_float4(0.f, 0.f, 0.f, 0.f);
            if (m0 + row < M)
                v = *(const float4*)(g_agg + (size_t)(m0 + row) * 256 + kk + lc);
            As[lc + 0][row] = v.x;
            As[lc + 1][row] = v.y;
            As[lc + 2][row] = v.z;
            As[lc + 3][row] = v.w;
        }
        *(float4*)(&Bs[wr][wc]) = *(const float4*)(W1 + (size_t)(kk + wr) * 64 + wc);
        __syncthreads();
#pragma unroll
        for (int k = 0; k < 16; k++) {
            float a[16], b[4];
#pragma unroll
            for (int i = 0; i < 16; i++) a[i] = As[k][ty * 16 + i];
#pragma unroll
            for (int j = 0; j < 4; j++)  b[j] = Bs[k][tx * 4 + j];
#pragma unroll
            for (int i = 0; i < 16; i++)
#pragma unroll
                for (int j = 0; j < 4; j++) acc[i][j] = fmaf(a[i], b[j], acc[i][j]);
        }
        __syncthreads();
    }
    float4 b1v = *(const float4*)(b1 + tx * 4);
#pragma unroll
    for (int i = 0; i < 16; i++) {
        int row = m0 + ty * 16 + i;
        if (row < M) {
            float4 v;
            v.x = fmaxf(acc[i][0] + b1v.x, 0.f);
            v.y = fmaxf(acc[i][1] + b1v.y, 0.f);
            v.z = fmaxf(acc[i][2] + b1v.z, 0.f);
            v.w = fmaxf(acc[i][3] + b1v.w, 0.f);
            *(float4*)(g_hid + (size_t)row * HIDD + tx * 4) = v;
        }
    }
}

// ---------------- out = hid @ W2 + b2 ----------------
__global__ void mlp2_kernel(const float* __restrict__ W2, const float* __restrict__ b2,
                            float* __restrict__ out, int M) {
    __shared__ float sW2[HIDD * OUTC];
    __shared__ float sb2[OUTC];
    __shared__ float sX[128 * 65];
    int t = threadIdx.x;
    for (int i = t; i < HIDD * OUTC; i += 128) sW2[i] = W2[i];
    if (t < OUTC) sb2[t] = b2[t];
    int base = blockIdx.x * 128;
    for (int i = t; i < 128 * HIDD; i += 128) {
        int r = i >> 6, c = i & 63;
        float v = (base + r < M) ? g_hid[(size_t)(base + r) * HIDD + c] : 0.f;
        sX[r * 65 + c] = v;
    }
    __syncthreads();
    int node = base + t;
    if (node >= M) return;
    float acc[OUTC];
#pragma unroll
    for (int j = 0; j < OUTC; j++) acc[j] = sb2[j];
#pragma unroll 4
    for (int k = 0; k < HIDD; k++) {
        float xv = sX[t * 65 + k];
#pragma unroll
        for (int j = 0; j < OUTC; j++) acc[j] = fmaf(xv, sW2[k * OUTC + j], acc[j]);
    }
#pragma unroll
    for (int j = 0; j < OUTC; j++) out[(size_t)node * OUTC + j] = acc[j];
}

// ---------------- launch ----------------
extern "C" void kernel_launch(void* const* d_in, const int* in_sizes, int n_in,
                              void* d_out, int out_size) {
    const float* x         = (const float*)d_in[0];
    const int*   ei        = (const int*)d_in[1];      // int32
    const float* W         = (const float*)d_in[2];
    const float* att_src   = (const float*)d_in[3];
    const float* att_dst   = (const float*)d_in[4];
    const float* bias_conv = (const float*)d_in[5];
    const float* W1        = (const float*)d_in[6];
    const float* b1        = (const float*)d_in[7];
    const float* W2        = (const float*)d_in[8];
    const float* b2        = (const float*)d_in[9];
    float*       out       = (float*)d_out;

    int Nn = in_sizes[0] / INC;
    int E  = in_sizes[1] / 2;
    int ET = E + Nn;

    gnn_init_kernel<<<(Nn + 255) / 256, 256>>>(Nn);

    dim3 g1((Nn + 127) / 128, 2);
    sgemm_h_kernel<<<g1, 256>>>(x, W, Nn);

    att_kernel<<<(Nn * Hh * 32 + 255) / 256, 256>>>(att_src, att_dst, Nn);

    edge_deg_kernel<<<(ET + 255) / 256, 256>>>(ei, E, ET, Nn);
    offsets_kernel<<<(Nn + 255) / 256, 256>>>(Nn);
    edge_fill_kernel<<<(ET + 255) / 256, 256>>>(ei, E, ET, Nn);

    agg_kernel<<<(Nn + 3) / 4, 256>>>(bias_conv, Nn);

    mlp1_kernel<<<(Nn + 255) / 256, 256>>>(W1, b1, Nn);
    mlp2_kernel<<<(Nn + 127) / 128, 128>>>(W2, b2, out, Nn);
}

// round 4
// speedup vs baseline: 2.1804x; 1.0229x over previous
#include <cuda_runtime.h>
#include <math.h>

#define Hh   4
#define Cc   64
#define HC   256
#define INC  256
#define HIDD 64
#define OUTC 40
#define NEG  0.2f

#define N_MAX  50048
#define E_MAX  800000
#define ET_MAX (E_MAX + N_MAX)

// ---------------- static scratch ----------------
__device__ float g_h[(size_t)N_MAX * HC];       // lin-transformed features [N,256]
__device__ float g_agg[(size_t)N_MAX * HC];     // relu(agg/den + bias) [N,256]
__device__ float g_hid[(size_t)N_MAX * HIDD];   // MLP hidden [N,64]
__device__ float g_asrc[N_MAX * Hh];
__device__ float g_adst[N_MAX * Hh];
__device__ int   g_deg[N_MAX];                  // in-degree (incl self-loop)
__device__ int   g_cnt[N_MAX];                  // fill cursor per node
__device__ int   g_off[N_MAX];                  // CSR range start per node
__device__ int   g_cursor;                      // global slot cursor
__device__ int   g_csr_src[ET_MAX];             // CSR: src node per slot
__device__ float g_ee[(size_t)ET_MAX * Hh];     // CSR: exp(logit) per slot per head

__device__ __forceinline__ int clampi(int v, int n) {
    return (v < 0) ? 0 : ((v >= n) ? n - 1 : v);
}

// ---------------- packed fp32x2 helpers (Blackwell 2xFP32 pipe) ----------------
__device__ __forceinline__ unsigned long long pk2(float lo, float hi) {
    unsigned long long r;
    asm("mov.b64 %0, {%1, %2};" : "=l"(r) : "f"(lo), "f"(hi));
    return r;
}
__device__ __forceinline__ float2 upk2(unsigned long long v) {
    float lo, hi;
    asm("mov.b64 {%0, %1}, %2;" : "=f"(lo), "=f"(hi) : "l"(v));
    return make_float2(lo, hi);
}
__device__ __forceinline__ unsigned long long ffma2(unsigned long long a,
                                                    unsigned long long b,
                                                    unsigned long long c) {
    unsigned long long d;
    asm("fma.rn.f32x2 %0, %1, %2, %3;" : "=l"(d) : "l"(a), "l"(b), "l"(c));
    return d;
}

// ---------------- init: zero counters ----------------
__global__ void gnn_init_kernel(int Nn) {
    int i = blockIdx.x * blockDim.x + threadIdx.x;
    if (i < Nn) { g_deg[i] = 0; g_cnt[i] = 0; }
    if (i == 0) g_cursor = 0;
}

// ---------------- h = x @ W, 128x128x16 tiles, 8x8 micro (f32x2), dbl-buffered ----------------
__global__ void sgemm_h_kernel(const float* __restrict__ X,
                               const float* __restrict__ Wm, int M) {
    __shared__ float As[2][16][128];
    __shared__ float Bs[2][16][128];
    int t  = threadIdx.x;
    int tx = t & 15, ty = t >> 4;
    int m0 = blockIdx.x * 128;
    int n0 = blockIdx.y * 128;

    unsigned long long acc2[8][4];
#pragma unroll
    for (int i = 0; i < 8; i++)
#pragma unroll
        for (int j = 0; j < 4; j++) acc2[i][j] = 0ull;

    int lr = t >> 2;          // 0..63
    int lc = (t & 3) << 2;    // 0,4,8,12
    int wr = t >> 5;          // 0..7
    int wc = (t & 31) << 2;   // 0..124

    // prologue: k-tile 0 -> buffer 0
    {
#pragma unroll
        for (int p = 0; p < 2; p++) {
            int row = lr + p * 64;
            float4 v = make_float4(0.f, 0.f, 0.f, 0.f);
            if (m0 + row < M)
                v = *(const float4*)(X + (size_t)(m0 + row) * 256 + lc);
            As[0][lc + 0][row] = v.x; As[0][lc + 1][row] = v.y;
            As[0][lc + 2][row] = v.z; As[0][lc + 3][row] = v.w;
        }
#pragma unroll
        for (int p = 0; p < 2; p++) {
            int row = wr + p * 8;
            *(float4*)(&Bs[0][row][wc]) =
                *(const float4*)(Wm + (size_t)row * 256 + n0 + wc);
        }
    }
    __syncthreads();

    int buf = 0;
    for (int kk = 0; kk < 256; kk += 16) {
        bool more = (kk + 16) < 256;
        float4 na[2], nb[2];
        if (more) {
#pragma unroll
            for (int p = 0; p < 2; p++) {
                int row = lr + p * 64;
                na[p] = make_float4(0.f, 0.f, 0.f, 0.f);
                if (m0 + row < M)
                    na[p] = *(const float4*)(X + (size_t)(m0 + row) * 256 + kk + 16 + lc);
            }
#pragma unroll
            for (int p = 0; p < 2; p++) {
                int row = wr + p * 8;
                nb[p] = *(const float4*)(Wm + (size_t)(kk + 16 + row) * 256 + n0 + wc);
            }
        }
#pragma unroll
        for (int k = 0; k < 16; k++) {
            unsigned long long a2[8], b2[4];
#pragma unroll
            for (int i = 0; i < 8; i++) {
                float av = As[buf][k][ty * 8 + i];
                a2[i] = pk2(av, av);
            }
#pragma unroll
            for (int j = 0; j < 4; j++) {
                float2 bv = *(const float2*)(&Bs[buf][k][tx * 8 + j * 2]);
                b2[j] = pk2(bv.x, bv.y);
            }
#pragma unroll
            for (int i = 0; i < 8; i++)
#pragma unroll
                for (int j = 0; j < 4; j++)
                    acc2[i][j] = ffma2(a2[i], b2[j], acc2[i][j]);
        }
        if (more) {
            int nb_ = buf ^ 1;
#pragma unroll
            for (int p = 0; p < 2; p++) {
                int row = lr + p * 64;
                As[nb_][lc + 0][row] = na[p].x; As[nb_][lc + 1][row] = na[p].y;
                As[nb_][lc + 2][row] = na[p].z; As[nb_][lc + 3][row] = na[p].w;
            }
#pragma unroll
            for (int p = 0; p < 2; p++) {
                int row = wr + p * 8;
                *(float4*)(&Bs[nb_][row][wc]) = nb[p];
            }
        }
        __syncthreads();
        buf ^= 1;
    }
#pragma unroll
    for (int i = 0; i < 8; i++) {
        int row = m0 + ty * 8 + i;
        if (row < M) {
#pragma unroll
            for (int j = 0; j < 2; j++) {
                float2 p0 = upk2(acc2[i][j * 2 + 0]);
                float2 p1 = upk2(acc2[i][j * 2 + 1]);
                float4 v = make_float4(p0.x, p0.y, p1.x, p1.y);
                *(float4*)(g_h + (size_t)row * 256 + n0 + tx * 8 + j * 4) = v;
            }
        }
    }
}

// ---------------- a_src / a_dst: warp per (node, head) ----------------
__global__ void att_kernel(const float* __restrict__ att_src,
                           const float* __restrict__ att_dst, int Nn) {
    int w    = (blockIdx.x * blockDim.x + threadIdx.x) >> 5;
    int lane = threadIdx.x & 31;
    if (w >= Nn * Hh) return;
    int n = w >> 2, hd = w & 3;
    const float* hrow = g_h + (size_t)n * HC + hd * Cc;
    float v1 = hrow[lane], v2 = hrow[lane + 32];
    float s = v1 * __ldg(att_src + hd * Cc + lane) + v2 * __ldg(att_src + hd * Cc + lane + 32);
    float d = v1 * __ldg(att_dst + hd * Cc + lane) + v2 * __ldg(att_dst + hd * Cc + lane + 32);
#pragma unroll
    for (int o = 16; o; o >>= 1) {
        s += __shfl_xor_sync(0xffffffffu, s, o);
        d += __shfl_xor_sync(0xffffffffu, d, o);
    }
    if (lane == 0) { g_asrc[n * Hh + hd] = s; g_adst[n * Hh + hd] = d; }
}

// ---------------- edge pass 1: count in-degrees ----------------
__global__ void edge_deg_kernel(const int* __restrict__ ei, int E, int ET, int Nn) {
    int e = blockIdx.x * blockDim.x + threadIdx.x;
    if (e >= ET) return;
    int d = (e < E) ? clampi(ei[(size_t)E + e], Nn) : (e - E);
    atomicAdd(&g_deg[d], 1);
}

// ---------------- offsets: contiguous range per node (order-free) ----------------
__global__ void offsets_kernel(int Nn) {
    int n = blockIdx.x * blockDim.x + threadIdx.x;
    if (n >= Nn) return;
    g_off[n] = atomicAdd(&g_cursor, g_deg[n]);
}

// ---------------- edge pass 2: exp(leaky(logit)) -> CSR slots ----------------
__global__ void edge_fill_kernel(const int* __restrict__ ei, int E, int ET, int Nn) {
    int e = blockIdx.x * blockDim.x + threadIdx.x;
    if (e >= ET) return;
    int s, d;
    if (e < E) { s = clampi(ei[e], Nn); d = clampi(ei[(size_t)E + e], Nn); }
    else       { s = d = e - E; }
    float4 as = *(const float4*)(g_asrc + (size_t)s * Hh);
    float4 ad = *(const float4*)(g_adst + (size_t)d * Hh);
    float v[4];
    v[0] = as.x + ad.x; v[1] = as.y + ad.y; v[2] = as.z + ad.z; v[3] = as.w + ad.w;
#pragma unroll
    for (int h = 0; h < 4; h++) {
        float lv = (v[h] > 0.f) ? v[h] : NEG * v[h];
        v[h] = __expf(lv);
    }
    int slot = g_off[d] + atomicAdd(&g_cnt[d], 1);
    g_csr_src[slot] = s;
    *(float4*)(g_ee + (size_t)slot * Hh) = make_float4(v[0], v[1], v[2], v[3]);
}

// ---------------- aggregation: 64 threads/node, register acc, inline denom ----------------
__global__ void agg_kernel(const float* __restrict__ bias_conv, int Nn) {
    int node = blockIdx.x * 4 + (threadIdx.x >> 6);
    int l    = threadIdx.x & 63;      // float4 column index 0..63
    if (node >= Nn) return;
    int beg = g_off[node];
    int deg = g_deg[node];
    int hd  = l >> 4;                 // head of this column block

    float4 acc = make_float4(0.f, 0.f, 0.f, 0.f);
    float den = 0.f;
#pragma unroll 2
    for (int i = 0; i < deg; i++) {
        int slot = beg + i;
        int s    = g_csr_src[slot];
        float a  = g_ee[(size_t)slot * Hh + hd];
        float4 hv = *(const float4*)(g_h + (size_t)s * HC + l * 4);
        den += a;
        acc.x = fmaf(a, hv.x, acc.x);
        acc.y = fmaf(a, hv.y, acc.y);
        acc.z = fmaf(a, hv.z, acc.z);
        acc.w = fmaf(a, hv.w, acc.w);
    }
    float r = 1.f / den;
    float4 bv = *(const float4*)(bias_conv + l * 4);
    float4 o;
    o.x = fmaxf(fmaf(acc.x, r, bv.x), 0.f);
    o.y = fmaxf(fmaf(acc.y, r, bv.y), 0.f);
    o.z = fmaxf(fmaf(acc.z, r, bv.z), 0.f);
    o.w = fmaxf(fmaf(acc.w, r, bv.w), 0.f);
    *(float4*)(g_agg + (size_t)node * HC + l * 4) = o;
}

// ---------------- hid = relu(g_agg @ W1 + b1), f32x2 inner ----------------
__global__ void mlp1_kernel(const float* __restrict__ W1,
                            const float* __restrict__ b1, int M) {
    __shared__ float As[16][256];
    __shared__ float Bs[16][64];
    int t  = threadIdx.x;
    int tx = t & 15, ty = t >> 4;
    int m0 = blockIdx.x * 256;

    unsigned long long acc2[16][2];
#pragma unroll
    for (int i = 0; i < 16; i++) { acc2[i][0] = 0ull; acc2[i][1] = 0ull; }

    int lr = t >> 2;         // 0..63
    int lc = (t & 3) << 2;
    int wr = t >> 4;         // 0..15
    int wc = (t & 15) << 2;  // 0..60

    for (int kk = 0; kk < 256; kk += 16) {
#pragma unroll
        for (int p = 0; p < 4; p++) {
            int row = lr + p * 64;
            float4 v = make_float4(0.f, 0.f, 0.f, 0.f);
            if (m0 + row < M)
                v = *(const float4*)(g_agg + (size_t)(m0 + row) * 256 + kk + lc);
            As[lc + 0][row] = v.x;
            As[lc + 1][row] = v.y;
            As[lc + 2][row] = v.z;
            As[lc + 3][row] = v.w;
        }
        *(float4*)(&Bs[wr][wc]) = *(const float4*)(W1 + (size_t)(kk + wr) * 64 + wc);
        __syncthreads();
#pragma unroll
        for (int k = 0; k < 16; k++) {
            unsigned long long a2[16], b2[2];
#pragma unroll
            for (int i = 0; i < 16; i++) {
                float av = As[k][ty * 16 + i];
                a2[i] = pk2(av, av);
            }
#pragma unroll
            for (int j = 0; j < 2; j++) {
                float2 bv = *(const float2*)(&Bs[k][tx * 4 + j * 2]);
                b2[j] = pk2(bv.x, bv.y);
            }
#pragma unroll
            for (int i = 0; i < 16; i++) {
                acc2[i][0] = ffma2(a2[i], b2[0], acc2[i][0]);
                acc2[i][1] = ffma2(a2[i], b2[1], acc2[i][1]);
            }
        }
        __syncthreads();
    }
    float4 b1v = *(const float4*)(b1 + tx * 4);
#pragma unroll
    for (int i = 0; i < 16; i++) {
        int row = m0 + ty * 16 + i;
        if (row < M) {
            float2 p0 = upk2(acc2[i][0]);
            float2 p1 = upk2(acc2[i][1]);
            float4 v;
            v.x = fmaxf(p0.x + b1v.x, 0.f);
            v.y = fmaxf(p0.y + b1v.y, 0.f);
            v.z = fmaxf(p1.x + b1v.z, 0.f);
            v.w = fmaxf(p1.y + b1v.w, 0.f);
            *(float4*)(g_hid + (size_t)row * HIDD + tx * 4) = v;
        }
    }
}

// ---------------- out = hid @ W2 + b2 ----------------
__global__ void mlp2_kernel(const float* __restrict__ W2, const float* __restrict__ b2,
                            float* __restrict__ out, int M) {
    __shared__ float sW2[HIDD * OUTC];
    __shared__ float sb2[OUTC];
    __shared__ float sX[128 * 65];
    int t = threadIdx.x;
    for (int i = t; i < HIDD * OUTC; i += 128) sW2[i] = W2[i];
    if (t < OUTC) sb2[t] = b2[t];
    int base = blockIdx.x * 128;
    for (int i = t; i < 128 * HIDD; i += 128) {
        int r = i >> 6, c = i & 63;
        float v = (base + r < M) ? g_hid[(size_t)(base + r) * HIDD + c] : 0.f;
        sX[r * 65 + c] = v;
    }
    __syncthreads();
    int node = base + t;
    if (node >= M) return;
    float acc[OUTC];
#pragma unroll
    for (int j = 0; j < OUTC; j++) acc[j] = sb2[j];
#pragma unroll 4
    for (int k = 0; k < HIDD; k++) {
        float xv = sX[t * 65 + k];
#pragma unroll
        for (int j = 0; j < OUTC; j++) acc[j] = fmaf(xv, sW2[k * OUTC + j], acc[j]);
    }
#pragma unroll
    for (int j = 0; j < OUTC; j++) out[(size_t)node * OUTC + j] = acc[j];
}

// ---------------- launch ----------------
extern "C" void kernel_launch(void* const* d_in, const int* in_sizes, int n_in,
                              void* d_out, int out_size) {
    const float* x         = (const float*)d_in[0];
    const int*   ei        = (const int*)d_in[1];      // int32
    const float* W         = (const float*)d_in[2];
    const float* att_src   = (const float*)d_in[3];
    const float* att_dst   = (const float*)d_in[4];
    const float* bias_conv = (const float*)d_in[5];
    const float* W1        = (const float*)d_in[6];
    const float* b1        = (const float*)d_in[7];
    const float* W2        = (const float*)d_in[8];
    const float* b2        = (const float*)d_in[9];
    float*       out       = (float*)d_out;

    int Nn = in_sizes[0] / INC;
    int E  = in_sizes[1] / 2;
    int ET = E + Nn;

    gnn_init_kernel<<<(Nn + 255) / 256, 256>>>(Nn);

    dim3 g1((Nn + 127) / 128, 2);
    sgemm_h_kernel<<<g1, 256>>>(x, W, Nn);

    att_kernel<<<(Nn * Hh * 32 + 255) / 256, 256>>>(att_src, att_dst, Nn);

    edge_deg_kernel<<<(ET + 255) / 256, 256>>>(ei, E, ET, Nn);
    offsets_kernel<<<(Nn + 255) / 256, 256>>>(Nn);
    edge_fill_kernel<<<(ET + 255) / 256, 256>>>(ei, E, ET, Nn);

    agg_kernel<<<(Nn + 3) / 4, 256>>>(bias_conv, Nn);

    mlp1_kernel<<<(Nn + 255) / 256, 256>>>(W1, b1, Nn);
    mlp2_kernel<<<(Nn + 127) / 128, 128>>>(W2, b2, out, Nn);
}

// round 6
// speedup vs baseline: 2.4986x; 1.1459x over previous
#include <cuda_runtime.h>
#include <cuda_bf16.h>
#include <cstdint>
#include <math.h>

#define Hh   4
#define Cc   64
#define HC   256
#define INC  256
#define HIDD 64
#define OUTC 40
#define NEG  0.2f

#define N_MAX  50048
#define E_MAX  800000
#define ET_MAX (E_MAX + N_MAX)

// ---------------- static scratch ----------------
__device__ float g_h[(size_t)N_MAX * HC];       // lin-transformed features [N,256]
__device__ float g_agg[(size_t)N_MAX * HC];     // relu(agg/den + bias) [N,256]
__device__ float g_hid[(size_t)N_MAX * HIDD];   // MLP hidden [N,64]
__device__ float g_asrc[N_MAX * Hh];
__device__ float g_adst[N_MAX * Hh];
__device__ int   g_deg[N_MAX];
__device__ int   g_cnt[N_MAX];
__device__ int   g_off[N_MAX];
__device__ int   g_cursor;
__device__ int   g_csr_src[ET_MAX];
__device__ float g_ee[(size_t)ET_MAX * Hh];

// bf16 split operands for tensor-core GEMM
__device__ __align__(16) __nv_bfloat16 g_xhi[(size_t)N_MAX * 256];
__device__ __align__(16) __nv_bfloat16 g_xlo[(size_t)N_MAX * 256];
__device__ __align__(16) __nv_bfloat16 g_bhi[256 * 256];   // B[n,k] = W[k,n]
__device__ __align__(16) __nv_bfloat16 g_blo[256 * 256];

__device__ __forceinline__ int clampi(int v, int n) {
    return (v < 0) ? 0 : ((v >= n) ? n - 1 : v);
}

// ---------------- packed fp32x2 helpers ----------------
__device__ __forceinline__ unsigned long long pk2(float lo, float hi) {
    unsigned long long r;
    asm("mov.b64 %0, {%1, %2};" : "=l"(r) : "f"(lo), "f"(hi));
    return r;
}
__device__ __forceinline__ float2 upk2(unsigned long long v) {
    float lo, hi;
    asm("mov.b64 {%0, %1}, %2;" : "=f"(lo), "=f"(hi) : "l"(v));
    return make_float2(lo, hi);
}
__device__ __forceinline__ unsigned long long ffma2(unsigned long long a,
                                                    unsigned long long b,
                                                    unsigned long long c) {
    unsigned long long d;
    asm("fma.rn.f32x2 %0, %1, %2, %3;" : "=l"(d) : "l"(a), "l"(b), "l"(c));
    return d;
}

// ---------------- warp-level bf16 MMA (m16n8k16, sm_80+ PTX, no 'a'-gating) ----------------
__device__ __forceinline__ void mma_bf16(float* d, const uint32_t* a, const uint32_t* b) {
    asm volatile(
        "mma.sync.aligned.m16n8k16.row.col.f32.bf16.bf16.f32 "
        "{%0,%1,%2,%3}, {%4,%5,%6,%7}, {%8,%9}, {%0,%1,%2,%3};"
        : "+f"(d[0]), "+f"(d[1]), "+f"(d[2]), "+f"(d[3])
        : "r"(a[0]), "r"(a[1]), "r"(a[2]), "r"(a[3]), "r"(b[0]), "r"(b[1]));
}

// ---------------- init ----------------
__global__ void gnn_init_kernel(int Nn) {
    int i = blockIdx.x * blockDim.x + threadIdx.x;
    if (i < Nn) { g_deg[i] = 0; g_cnt[i] = 0; }
    if (i == 0) g_cursor = 0;
}

// ---------------- fp32 -> bf16 hi/lo split of x ----------------
__global__ void convert_x_kernel(const float* __restrict__ x, int Nn) {
    int i = blockIdx.x * blockDim.x + threadIdx.x;     // one float4
    int tot = Nn * 64;
    if (i >= tot) return;
    float4 v = ((const float4*)x)[i];
    float f[4] = {v.x, v.y, v.z, v.w};
    __nv_bfloat16 h[4], l[4];
#pragma unroll
    for (int q = 0; q < 4; q++) {
        h[q] = __float2bfloat16(f[q]);
        l[q] = __float2bfloat16(f[q] - __bfloat162float(h[q]));
    }
    __nv_bfloat162* ph = (__nv_bfloat162*)g_xhi;
    __nv_bfloat162* pl = (__nv_bfloat162*)g_xlo;
    ph[i * 2 + 0] = __halves2bfloat162(h[0], h[1]);
    ph[i * 2 + 1] = __halves2bfloat162(h[2], h[3]);
    pl[i * 2 + 0] = __halves2bfloat162(l[0], l[1]);
    pl[i * 2 + 1] = __halves2bfloat162(l[2], l[3]);
}

// ---------------- W[k,n] -> B[n,k] bf16 hi/lo ----------------
__global__ void convert_w_kernel(const float* __restrict__ W) {
    int idx = blockIdx.x * blockDim.x + threadIdx.x;   // 65536
    if (idx >= 256 * 256) return;
    int n = idx & 255, k = idx >> 8;
    float w = W[k * 256 + n];                          // coalesced in n
    __nv_bfloat16 h = __float2bfloat16(w);
    __nv_bfloat16 l = __float2bfloat16(w - __bfloat162float(h));
    g_bhi[n * 256 + k] = h;
    g_blo[n * 256 + k] = l;
}

// ---------------- tensor-core GEMM via mma.sync: g_h = x @ W (bf16 2-term split) ----------------
// CTA: 128M x 128N; 8 warps 4x2; warp tile 32M x 64N = 2x8 m16n8k16 frags.
// K: 3 phases (hi*hi, hi*lo, lo*hi) x 4 chunks of 64.
#define APAD 72   // bf16 row stride (64 + 8): conflict-free frag loads

__global__ void __launch_bounds__(256)
gemm_mma_kernel(int Nn) {
    __shared__ __nv_bfloat16 As[128 * APAD];
    __shared__ __nv_bfloat16 Bs[128 * APAD];
    int tid  = threadIdx.x;
    int wid  = tid >> 5;
    int lane = tid & 31;
    int gid  = lane >> 2;     // group of 4
    int tig  = lane & 3;      // thread in group
    int wm   = (wid & 3) * 32;
    int wn   = (wid >> 2) * 64;
    int m0 = blockIdx.x * 128;
    int n0 = blockIdx.y * 128;

    float acc[2][8][4];
#pragma unroll
    for (int mt = 0; mt < 2; mt++)
#pragma unroll
        for (int nt = 0; nt < 8; nt++)
#pragma unroll
            for (int q = 0; q < 4; q++) acc[mt][nt][q] = 0.f;

    const __nv_bfloat16* Aph[3] = {g_xhi, g_xhi, g_xlo};
    const __nv_bfloat16* Bph[3] = {g_bhi, g_blo, g_bhi};

    for (int ph = 0; ph < 3; ph++) {
        const __nv_bfloat16* Ag = Aph[ph];
        const __nv_bfloat16* Bg = Bph[ph];
        for (int kk = 0; kk < 256; kk += 64) {
            __syncthreads();
            for (int j = tid; j < 1024; j += 256) {
                int r = j >> 3, u = (j & 7) * 8;
                uint4 va = make_uint4(0u, 0u, 0u, 0u);
                if (m0 + r < Nn)
                    va = *(const uint4*)(Ag + (size_t)(m0 + r) * 256 + kk + u);
                *(uint4*)(As + r * APAD + u) = va;
                uint4 vb = *(const uint4*)(Bg + (size_t)(n0 + r) * 256 + kk + u);
                *(uint4*)(Bs + r * APAD + u) = vb;
            }
            __syncthreads();
#pragma unroll
            for (int ks = 0; ks < 64; ks += 16) {
                uint32_t a[2][4];
#pragma unroll
                for (int mt = 0; mt < 2; mt++) {
                    int row = wm + mt * 16 + gid;
                    a[mt][0] = *(const uint32_t*)(As + row * APAD + ks + tig * 2);
                    a[mt][1] = *(const uint32_t*)(As + (row + 8) * APAD + ks + tig * 2);
                    a[mt][2] = *(const uint32_t*)(As + row * APAD + ks + tig * 2 + 8);
                    a[mt][3] = *(const uint32_t*)(As + (row + 8) * APAD + ks + tig * 2 + 8);
                }
                uint32_t b[8][2];
#pragma unroll
                for (int nt = 0; nt < 8; nt++) {
                    int col = wn + nt * 8 + gid;
                    b[nt][0] = *(const uint32_t*)(Bs + col * APAD + ks + tig * 2);
                    b[nt][1] = *(const uint32_t*)(Bs + col * APAD + ks + tig * 2 + 8);
                }
#pragma unroll
                for (int mt = 0; mt < 2; mt++)
#pragma unroll
                    for (int nt = 0; nt < 8; nt++)
                        mma_bf16(acc[mt][nt], a[mt], b[nt]);
            }
        }
    }

    // epilogue: D frag (m16n8): d0 row gid col tig*2; d1 +1col; d2 row gid+8; d3 both
#pragma unroll
    for (int mt = 0; mt < 2; mt++) {
        int row = m0 + wm + mt * 16 + gid;
#pragma unroll
        for (int nt = 0; nt < 8; nt++) {
            int col = n0 + wn + nt * 8 + tig * 2;
            if (row < Nn)
                *(float2*)(g_h + (size_t)row * 256 + col) =
                    make_float2(acc[mt][nt][0], acc[mt][nt][1]);
            if (row + 8 < Nn)
                *(float2*)(g_h + (size_t)(row + 8) * 256 + col) =
                    make_float2(acc[mt][nt][2], acc[mt][nt][3]);
        }
    }
}

// ---------------- a_src / a_dst: warp per (node, head) ----------------
__global__ void att_kernel(const float* __restrict__ att_src,
                           const float* __restrict__ att_dst, int Nn) {
    int w    = (blockIdx.x * blockDim.x + threadIdx.x) >> 5;
    int lane = threadIdx.x & 31;
    if (w >= Nn * Hh) return;
    int n = w >> 2, hd = w & 3;
    const float* hrow = g_h + (size_t)n * HC + hd * Cc;
    float v1 = hrow[lane], v2 = hrow[lane + 32];
    float s = v1 * __ldg(att_src + hd * Cc + lane) + v2 * __ldg(att_src + hd * Cc + lane + 32);
    float d = v1 * __ldg(att_dst + hd * Cc + lane) + v2 * __ldg(att_dst + hd * Cc + lane + 32);
#pragma unroll
    for (int o = 16; o; o >>= 1) {
        s += __shfl_xor_sync(0xffffffffu, s, o);
        d += __shfl_xor_sync(0xffffffffu, d, o);
    }
    if (lane == 0) { g_asrc[n * Hh + hd] = s; g_adst[n * Hh + hd] = d; }
}

// ---------------- edge pass 1: count in-degrees ----------------
__global__ void edge_deg_kernel(const int* __restrict__ ei, int E, int ET, int Nn) {
    int e = blockIdx.x * blockDim.x + threadIdx.x;
    if (e >= ET) return;
    int d = (e < E) ? clampi(ei[(size_t)E + e], Nn) : (e - E);
    atomicAdd(&g_deg[d], 1);
}

// ---------------- offsets ----------------
__global__ void offsets_kernel(int Nn) {
    int n = blockIdx.x * blockDim.x + threadIdx.x;
    if (n >= Nn) return;
    g_off[n] = atomicAdd(&g_cursor, g_deg[n]);
}

// ---------------- edge pass 2: exp(leaky(logit)) -> CSR slots ----------------
__global__ void edge_fill_kernel(const int* __restrict__ ei, int E, int ET, int Nn) {
    int e = blockIdx.x * blockDim.x + threadIdx.x;
    if (e >= ET) return;
    int s, d;
    if (e < E) { s = clampi(ei[e], Nn); d = clampi(ei[(size_t)E + e], Nn); }
    else       { s = d = e - E; }
    float4 as = *(const float4*)(g_asrc + (size_t)s * Hh);
    float4 ad = *(const float4*)(g_adst + (size_t)d * Hh);
    float v[4];
    v[0] = as.x + ad.x; v[1] = as.y + ad.y; v[2] = as.z + ad.z; v[3] = as.w + ad.w;
#pragma unroll
    for (int h = 0; h < 4; h++) {
        float lv = (v[h] > 0.f) ? v[h] : NEG * v[h];
        v[h] = __expf(lv);
    }
    int slot = g_off[d] + atomicAdd(&g_cnt[d], 1);
    g_csr_src[slot] = s;
    *(float4*)(g_ee + (size_t)slot * Hh) = make_float4(v[0], v[1], v[2], v[3]);
}

// ---------------- aggregation: 64 threads/node ----------------
__global__ void agg_kernel(const float* __restrict__ bias_conv, int Nn) {
    int node = blockIdx.x * 4 + (threadIdx.x >> 6);
    int l    = threadIdx.x & 63;
    if (node >= Nn) return;
    int beg = g_off[node];
    int deg = g_deg[node];
    int hd  = l >> 4;

    float4 acc = make_float4(0.f, 0.f, 0.f, 0.f);
    float den = 0.f;
#pragma unroll 2
    for (int i = 0; i < deg; i++) {
        int slot = beg + i;
        int s    = g_csr_src[slot];
        float a  = g_ee[(size_t)slot * Hh + hd];
        float4 hv = *(const float4*)(g_h + (size_t)s * HC + l * 4);
        den += a;
        acc.x = fmaf(a, hv.x, acc.x);
        acc.y = fmaf(a, hv.y, acc.y);
        acc.z = fmaf(a, hv.z, acc.z);
        acc.w = fmaf(a, hv.w, acc.w);
    }
    float r = 1.f / den;
    float4 bv = *(const float4*)(bias_conv + l * 4);
    float4 o;
    o.x = fmaxf(fmaf(acc.x, r, bv.x), 0.f);
    o.y = fmaxf(fmaf(acc.y, r, bv.y), 0.f);
    o.z = fmaxf(fmaf(acc.z, r, bv.z), 0.f);
    o.w = fmaxf(fmaf(acc.w, r, bv.w), 0.f);
    *(float4*)(g_agg + (size_t)node * HC + l * 4) = o;
}

// ---------------- hid = relu(g_agg @ W1 + b1), f32x2 inner ----------------
__global__ void mlp1_kernel(const float* __restrict__ W1,
                            const float* __restrict__ b1, int M) {
    __shared__ float As[16][256];
    __shared__ float Bs[16][64];
    int t  = threadIdx.x;
    int tx = t & 15, ty = t >> 4;
    int m0 = blockIdx.x * 256;

    unsigned long long acc2[16][2];
#pragma unroll
    for (int i = 0; i < 16; i++) { acc2[i][0] = 0ull; acc2[i][1] = 0ull; }

    int lr = t >> 2;
    int lc = (t & 3) << 2;
    int wr = t >> 4;
    int wc = (t & 15) << 2;

    for (int kk = 0; kk < 256; kk += 16) {
#pragma unroll
        for (int p = 0; p < 4; p++) {
            int row = lr + p * 64;
            float4 v = make_float4(0.f, 0.f, 0.f, 0.f);
            if (m0 + row < M)
                v = *(const float4*)(g_agg + (size_t)(m0 + row) * 256 + kk + lc);
            As[lc + 0][row] = v.x;
            As[lc + 1][row] = v.y;
            As[lc + 2][row] = v.z;
            As[lc + 3][row] = v.w;
        }
        *(float4*)(&Bs[wr][wc]) = *(const float4*)(W1 + (size_t)(kk + wr) * 64 + wc);
        __syncthreads();
#pragma unroll
        for (int k = 0; k < 16; k++) {
            unsigned long long a2[16], b2[2];
#pragma unroll
            for (int i = 0; i < 16; i++) {
                float av = As[k][ty * 16 + i];
                a2[i] = pk2(av, av);
            }
#pragma unroll
            for (int j = 0; j < 2; j++) {
                float2 bv = *(const float2*)(&Bs[k][tx * 4 + j * 2]);
                b2[j] = pk2(bv.x, bv.y);
            }
#pragma unroll
            for (int i = 0; i < 16; i++) {
                acc2[i][0] = ffma2(a2[i], b2[0], acc2[i][0]);
                acc2[i][1] = ffma2(a2[i], b2[1], acc2[i][1]);
            }
        }
        __syncthreads();
    }
    float4 b1v = *(const float4*)(b1 + tx * 4);
#pragma unroll
    for (int i = 0; i < 16; i++) {
        int row = m0 + ty * 16 + i;
        if (row < M) {
            float2 p0 = upk2(acc2[i][0]);
            float2 p1 = upk2(acc2[i][1]);
            float4 v;
            v.x = fmaxf(p0.x + b1v.x, 0.f);
            v.y = fmaxf(p0.y + b1v.y, 0.f);
            v.z = fmaxf(p1.x + b1v.z, 0.f);
            v.w = fmaxf(p1.y + b1v.w, 0.f);
            *(float4*)(g_hid + (size_t)row * HIDD + tx * 4) = v;
        }
    }
}

// ---------------- out = hid @ W2 + b2 ----------------
__global__ void mlp2_kernel(const float* __restrict__ W2, const float* __restrict__ b2,
                            float* __restrict__ out, int M) {
    __shared__ float sW2[HIDD * OUTC];
    __shared__ float sb2[OUTC];
    __shared__ float sX[128 * 65];
    int t = threadIdx.x;
    for (int i = t; i < HIDD * OUTC; i += 128) sW2[i] = W2[i];
    if (t < OUTC) sb2[t] = b2[t];
    int base = blockIdx.x * 128;
    for (int i = t; i < 128 * HIDD; i += 128) {
        int r = i >> 6, c = i & 63;
        float v = (base + r < M) ? g_hid[(size_t)(base + r) * HIDD + c] : 0.f;
        sX[r * 65 + c] = v;
    }
    __syncthreads();
    int node = base + t;
    if (node >= M) return;
    float acc[OUTC];
#pragma unroll
    for (int j = 0; j < OUTC; j++) acc[j] = sb2[j];
#pragma unroll 4
    for (int k = 0; k < HIDD; k++) {
        float xv = sX[t * 65 + k];
#pragma unroll
        for (int j = 0; j < OUTC; j++) acc[j] = fmaf(xv, sW2[k * OUTC + j], acc[j]);
    }
#pragma unroll
    for (int j = 0; j < OUTC; j++) out[(size_t)node * OUTC + j] = acc[j];
}

// ---------------- launch ----------------
extern "C" void kernel_launch(void* const* d_in, const int* in_sizes, int n_in,
                              void* d_out, int out_size) {
    const float* x         = (const float*)d_in[0];
    const int*   ei        = (const int*)d_in[1];      // int32
    const float* W         = (const float*)d_in[2];
    const float* att_src   = (const float*)d_in[3];
    const float* att_dst   = (const float*)d_in[4];
    const float* bias_conv = (const float*)d_in[5];
    const float* W1        = (const float*)d_in[6];
    const float* b1        = (const float*)d_in[7];
    const float* W2        = (const float*)d_in[8];
    const float* b2        = (const float*)d_in[9];
    float*       out       = (float*)d_out;

    int Nn = in_sizes[0] / INC;
    int E  = in_sizes[1] / 2;
    int ET = E + Nn;

    gnn_init_kernel<<<(Nn + 255) / 256, 256>>>(Nn);
    convert_x_kernel<<<(Nn * 64 + 255) / 256, 256>>>(x, Nn);
    convert_w_kernel<<<(256 * 256 + 255) / 256, 256>>>(W);

    dim3 gt((Nn + 127) / 128, 2);
    gemm_mma_kernel<<<gt, 256>>>(Nn);

    att_kernel<<<(Nn * Hh * 32 + 255) / 256, 256>>>(att_src, att_dst, Nn);

    edge_deg_kernel<<<(ET + 255) / 256, 256>>>(ei, E, ET, Nn);
    offsets_kernel<<<(Nn + 255) / 256, 256>>>(Nn);
    edge_fill_kernel<<<(ET + 255) / 256, 256>>>(ei, E, ET, Nn);

    agg_kernel<<<(Nn + 3) / 4, 256>>>(bias_conv, Nn);

    mlp1_kernel<<<(Nn + 255) / 256, 256>>>(W1, b1, Nn);
    mlp2_kernel<<<(Nn + 127) / 128, 128>>>(W2, b2, out, Nn);
}

// round 7
// speedup vs baseline: 2.7357x; 1.0949x over previous
#include <cuda_runtime.h>
#include <cuda_bf16.h>
#include <cstdint>
#include <math.h>

#define Hh   4
#define Cc   64
#define HC   256
#define INC  256
#define HIDD 64
#define OUTC 40
#define NEG  0.2f

#define N_MAX  50048
#define E_MAX  800000
#define ET_MAX (E_MAX + N_MAX)

// ---------------- static scratch ----------------
__device__ float g_h[(size_t)N_MAX * HC];       // lin-transformed features [N,256]
__device__ float g_agg[(size_t)N_MAX * HC];     // relu(agg/den + bias) [N,256]
__device__ float g_hid[(size_t)N_MAX * HIDD];   // MLP hidden [N,64]
__device__ float g_asrc[N_MAX * Hh];
__device__ float g_adst[N_MAX * Hh];
__device__ int   g_deg[N_MAX];
__device__ int   g_cnt[N_MAX];
__device__ int   g_off[N_MAX];
__device__ int   g_cursor;
__device__ int   g_csr_src[ET_MAX];
__device__ float g_ee[(size_t)ET_MAX * Hh];

// bf16 split operands for tensor-core GEMM
__device__ __align__(16) __nv_bfloat16 g_xhi[(size_t)N_MAX * 256];
__device__ __align__(16) __nv_bfloat16 g_xlo[(size_t)N_MAX * 256];
__device__ __align__(16) __nv_bfloat16 g_bhi[256 * 256];   // B[n,k] = W[k,n]
__device__ __align__(16) __nv_bfloat16 g_blo[256 * 256];

__device__ __forceinline__ int clampi(int v, int n) {
    return (v < 0) ? 0 : ((v >= n) ? n - 1 : v);
}

// ---------------- packed fp32x2 helpers ----------------
__device__ __forceinline__ unsigned long long pk2(float lo, float hi) {
    unsigned long long r;
    asm("mov.b64 %0, {%1, %2};" : "=l"(r) : "f"(lo), "f"(hi));
    return r;
}
__device__ __forceinline__ float2 upk2(unsigned long long v) {
    float lo, hi;
    asm("mov.b64 {%0, %1}, %2;" : "=f"(lo), "=f"(hi) : "l"(v));
    return make_float2(lo, hi);
}
__device__ __forceinline__ unsigned long long ffma2(unsigned long long a,
                                                    unsigned long long b,
                                                    unsigned long long c) {
    unsigned long long d;
    asm("fma.rn.f32x2 %0, %1, %2, %3;" : "=l"(d) : "l"(a), "l"(b), "l"(c));
    return d;
}

// ---------------- warp-level bf16 MMA (m16n8k16) ----------------
__device__ __forceinline__ void mma_bf16(float* d, const uint32_t* a, const uint32_t* b) {
    asm volatile(
        "mma.sync.aligned.m16n8k16.row.col.f32.bf16.bf16.f32 "
        "{%0,%1,%2,%3}, {%4,%5,%6,%7}, {%8,%9}, {%0,%1,%2,%3};"
        : "+f"(d[0]), "+f"(d[1]), "+f"(d[2]), "+f"(d[3])
        : "r"(a[0]), "r"(a[1]), "r"(a[2]), "r"(a[3]), "r"(b[0]), "r"(b[1]));
}

// ---------------- cp.async helpers ----------------
__device__ __forceinline__ uint32_t smem_u32(const void* p) {
    uint32_t a;
    asm("{ .reg .u64 t; cvta.to.shared.u64 t, %1; cvt.u32.u64 %0, t; }" : "=r"(a) : "l"(p));
    return a;
}
__device__ __forceinline__ void cpa16(uint32_t dst, const void* src, bool pred) {
    int sz = pred ? 16 : 0;
    asm volatile("cp.async.cg.shared.global [%0], [%1], 16, %2;"
                 :: "r"(dst), "l"(src), "r"(sz));
}
#define CPA_COMMIT() asm volatile("cp.async.commit_group;" ::: "memory")
#define CPA_WAIT(n)  asm volatile("cp.async.wait_group %0;" :: "n"(n) : "memory")

// ---------------- init ----------------
__global__ void gnn_init_kernel(int Nn) {
    int i = blockIdx.x * blockDim.x + threadIdx.x;
    if (i < Nn) { g_deg[i] = 0; g_cnt[i] = 0; }
    if (i == 0) g_cursor = 0;
}

// ---------------- fp32 -> bf16 hi/lo split of x ----------------
__global__ void convert_x_kernel(const float* __restrict__ x, int Nn) {
    int i = blockIdx.x * blockDim.x + threadIdx.x;     // one float4
    int tot = Nn * 64;
    if (i >= tot) return;
    float4 v = ((const float4*)x)[i];
    float f[4] = {v.x, v.y, v.z, v.w};
    __nv_bfloat16 h[4], l[4];
#pragma unroll
    for (int q = 0; q < 4; q++) {
        h[q] = __float2bfloat16(f[q]);
        l[q] = __float2bfloat16(f[q] - __bfloat162float(h[q]));
    }
    __nv_bfloat162* ph = (__nv_bfloat162*)g_xhi;
    __nv_bfloat162* pl = (__nv_bfloat162*)g_xlo;
    ph[i * 2 + 0] = __halves2bfloat162(h[0], h[1]);
    ph[i * 2 + 1] = __halves2bfloat162(h[2], h[3]);
    pl[i * 2 + 0] = __halves2bfloat162(l[0], l[1]);
    pl[i * 2 + 1] = __halves2bfloat162(l[2], l[3]);
}

// ---------------- W[k,n] -> B[n,k] bf16 hi/lo ----------------
__global__ void convert_w_kernel(const float* __restrict__ W) {
    int idx = blockIdx.x * blockDim.x + threadIdx.x;   // 65536
    if (idx >= 256 * 256) return;
    int n = idx & 255, k = idx >> 8;
    float w = W[k * 256 + n];
    __nv_bfloat16 h = __float2bfloat16(w);
    __nv_bfloat16 l = __float2bfloat16(w - __bfloat162float(h));
    g_bhi[n * 256 + k] = h;
    g_blo[n * 256 + k] = l;
}

// ---------------- fused-phase, cp.async double-buffered tensor GEMM ----------------
// CTA: 128M x 128N; 8 warps 4x2; warp tile 32M x 64N.
// Per k-chunk (64): stage Ahi/Alo/Bhi/Blo once; per ks issue hi*hi + hi*lo + lo*hi.
#define APAD    72
#define TILE_EL (128 * APAD)          // elements per 128x64 tile
#define STAGE_EL (4 * TILE_EL)
#define GEMM_SMEM_BYTES (2 * STAGE_EL * 2)   // 2 stages * 4 tiles * 2B = 147456

__global__ void __launch_bounds__(256)
gemm_mma_kernel(int Nn) {
    extern __shared__ __nv_bfloat16 sm[];
    int tid  = threadIdx.x;
    int wid  = tid >> 5;
    int lane = tid & 31;
    int gid  = lane >> 2;
    int tig  = lane & 3;
    int wm   = (wid & 3) * 32;
    int wn   = (wid >> 2) * 64;
    int m0 = blockIdx.x * 128;
    int n0 = blockIdx.y * 128;

    float acc[2][8][4];
#pragma unroll
    for (int mt = 0; mt < 2; mt++)
#pragma unroll
        for (int nt = 0; nt < 8; nt++)
#pragma unroll
            for (int q = 0; q < 4; q++) acc[mt][nt][q] = 0.f;

    // stage loader: 4 iters x 4 tiles of cp.async per thread
    auto stage_load = [&](int st, int kk) {
        __nv_bfloat16* base = sm + st * STAGE_EL;
        uint32_t sAhi = smem_u32(base);
        uint32_t sAlo = sAhi + TILE_EL * 2;
        uint32_t sBhi = sAhi + 2 * TILE_EL * 2;
        uint32_t sBlo = sAhi + 3 * TILE_EL * 2;
#pragma unroll
        for (int j0 = 0; j0 < 1024; j0 += 256) {
            int j = j0 + tid;
            int r = j >> 3, u = (j & 7) * 8;
            uint32_t so = (uint32_t)(r * APAD + u) * 2;
            bool am = (m0 + r) < Nn;
            size_t ga = (size_t)(m0 + r) * 256 + kk + u;
            size_t gb = (size_t)(n0 + r) * 256 + kk + u;
            cpa16(sAhi + so, g_xhi + ga, am);
            cpa16(sAlo + so, g_xlo + ga, am);
            cpa16(sBhi + so, g_bhi + gb, true);
            cpa16(sBlo + so, g_blo + gb, true);
        }
        CPA_COMMIT();
    };

    stage_load(0, 0);

    for (int c = 0; c < 4; c++) {
        if (c < 3) stage_load((c + 1) & 1, (c + 1) * 64);
        if (c < 3) { CPA_WAIT(1); } else { CPA_WAIT(0); }
        __syncthreads();

        const __nv_bfloat16* base = sm + (c & 1) * STAGE_EL;
        const __nv_bfloat16* Ahi = base;
        const __nv_bfloat16* Alo = base + TILE_EL;
        const __nv_bfloat16* Bhi = base + 2 * TILE_EL;
        const __nv_bfloat16* Blo = base + 3 * TILE_EL;

#pragma unroll
        for (int ks = 0; ks < 64; ks += 16) {
            uint32_t ahi[2][4], alo[2][4];
#pragma unroll
            for (int mt = 0; mt < 2; mt++) {
                int row = wm + mt * 16 + gid;
                ahi[mt][0] = *(const uint32_t*)(Ahi + row * APAD + ks + tig * 2);
                ahi[mt][1] = *(const uint32_t*)(Ahi + (row + 8) * APAD + ks + tig * 2);
                ahi[mt][2] = *(const uint32_t*)(Ahi + row * APAD + ks + tig * 2 + 8);
                ahi[mt][3] = *(const uint32_t*)(Ahi + (row + 8) * APAD + ks + tig * 2 + 8);
                alo[mt][0] = *(const uint32_t*)(Alo + row * APAD + ks + tig * 2);
                alo[mt][1] = *(const uint32_t*)(Alo + (row + 8) * APAD + ks + tig * 2);
                alo[mt][2] = *(const uint32_t*)(Alo + row * APAD + ks + tig * 2 + 8);
                alo[mt][3] = *(const uint32_t*)(Alo + (row + 8) * APAD + ks + tig * 2 + 8);
            }
            uint32_t bhi[8][2], blo[8][2];
#pragma unroll
            for (int nt = 0; nt < 8; nt++) {
                int col = wn + nt * 8 + gid;
                bhi[nt][0] = *(const uint32_t*)(Bhi + col * APAD + ks + tig * 2);
                bhi[nt][1] = *(const uint32_t*)(Bhi + col * APAD + ks + tig * 2 + 8);
                blo[nt][0] = *(const uint32_t*)(Blo + col * APAD + ks + tig * 2);
                blo[nt][1] = *(const uint32_t*)(Blo + col * APAD + ks + tig * 2 + 8);
            }
#pragma unroll
            for (int mt = 0; mt < 2; mt++)
#pragma unroll
                for (int nt = 0; nt < 8; nt++) {
                    mma_bf16(acc[mt][nt], ahi[mt], bhi[nt]);
                    mma_bf16(acc[mt][nt], ahi[mt], blo[nt]);
                    mma_bf16(acc[mt][nt], alo[mt], bhi[nt]);
                }
        }
        __syncthreads();
    }

    // epilogue
#pragma unroll
    for (int mt = 0; mt < 2; mt++) {
        int row = m0 + wm + mt * 16 + gid;
#pragma unroll
        for (int nt = 0; nt < 8; nt++) {
            int col = n0 + wn + nt * 8 + tig * 2;
            if (row < Nn)
                *(float2*)(g_h + (size_t)row * 256 + col) =
                    make_float2(acc[mt][nt][0], acc[mt][nt][1]);
            if (row + 8 < Nn)
                *(float2*)(g_h + (size_t)(row + 8) * 256 + col) =
                    make_float2(acc[mt][nt][2], acc[mt][nt][3]);
        }
    }
}

// ---------------- a_src / a_dst: warp per (node, head) ----------------
__global__ void att_kernel(const float* __restrict__ att_src,
                           const float* __restrict__ att_dst, int Nn) {
    int w    = (blockIdx.x * blockDim.x + threadIdx.x) >> 5;
    int lane = threadIdx.x & 31;
    if (w >= Nn * Hh) return;
    int n = w >> 2, hd = w & 3;
    const float* hrow = g_h + (size_t)n * HC + hd * Cc;
    float v1 = hrow[lane], v2 = hrow[lane + 32];
    float s = v1 * __ldg(att_src + hd * Cc + lane) + v2 * __ldg(att_src + hd * Cc + lane + 32);
    float d = v1 * __ldg(att_dst + hd * Cc + lane) + v2 * __ldg(att_dst + hd * Cc + lane + 32);
#pragma unroll
    for (int o = 16; o; o >>= 1) {
        s += __shfl_xor_sync(0xffffffffu, s, o);
        d += __shfl_xor_sync(0xffffffffu, d, o);
    }
    if (lane == 0) { g_asrc[n * Hh + hd] = s; g_adst[n * Hh + hd] = d; }
}

// ---------------- edge pass 1: count in-degrees ----------------
__global__ void edge_deg_kernel(const int* __restrict__ ei, int E, int ET, int Nn) {
    int e = blockIdx.x * blockDim.x + threadIdx.x;
    if (e >= ET) return;
    int d = (e < E) ? clampi(ei[(size_t)E + e], Nn) : (e - E);
    atomicAdd(&g_deg[d], 1);
}

// ---------------- offsets ----------------
__global__ void offsets_kernel(int Nn) {
    int n = blockIdx.x * blockDim.x + threadIdx.x;
    if (n >= Nn) return;
    g_off[n] = atomicAdd(&g_cursor, g_deg[n]);
}

// ---------------- edge pass 2: exp(leaky(logit)) -> CSR slots ----------------
__global__ void edge_fill_kernel(const int* __restrict__ ei, int E, int ET, int Nn) {
    int e = blockIdx.x * blockDim.x + threadIdx.x;
    if (e >= ET) return;
    int s, d;
    if (e < E) { s = clampi(ei[e], Nn); d = clampi(ei[(size_t)E + e], Nn); }
    else       { s = d = e - E; }
    float4 as = *(const float4*)(g_asrc + (size_t)s * Hh);
    float4 ad = *(const float4*)(g_adst + (size_t)d * Hh);
    float v[4];
    v[0] = as.x + ad.x; v[1] = as.y + ad.y; v[2] = as.z + ad.z; v[3] = as.w + ad.w;
#pragma unroll
    for (int h = 0; h < 4; h++) {
        float lv = (v[h] > 0.f) ? v[h] : NEG * v[h];
        v[h] = __expf(lv);
    }
    int slot = g_off[d] + atomicAdd(&g_cnt[d], 1);
    g_csr_src[slot] = s;
    *(float4*)(g_ee + (size_t)slot * Hh) = make_float4(v[0], v[1], v[2], v[3]);
}

// ---------------- aggregation: 64 threads/node ----------------
__global__ void agg_kernel(const float* __restrict__ bias_conv, int Nn) {
    int node = blockIdx.x * 4 + (threadIdx.x >> 6);
    int l    = threadIdx.x & 63;
    if (node >= Nn) return;
    int beg = g_off[node];
    int deg = g_deg[node];
    int hd  = l >> 4;

    float4 acc = make_float4(0.f, 0.f, 0.f, 0.f);
    float den = 0.f;
#pragma unroll 2
    for (int i = 0; i < deg; i++) {
        int slot = beg + i;
        int s    = g_csr_src[slot];
        float a  = g_ee[(size_t)slot * Hh + hd];
        float4 hv = *(const float4*)(g_h + (size_t)s * HC + l * 4);
        den += a;
        acc.x = fmaf(a, hv.x, acc.x);
        acc.y = fmaf(a, hv.y, acc.y);
        acc.z = fmaf(a, hv.z, acc.z);
        acc.w = fmaf(a, hv.w, acc.w);
    }
    float r = 1.f / den;
    float4 bv = *(const float4*)(bias_conv + l * 4);
    float4 o;
    o.x = fmaxf(fmaf(acc.x, r, bv.x), 0.f);
    o.y = fmaxf(fmaf(acc.y, r, bv.y), 0.f);
    o.z = fmaxf(fmaf(acc.z, r, bv.z), 0.f);
    o.w = fmaxf(fmaf(acc.w, r, bv.w), 0.f);
    *(float4*)(g_agg + (size_t)node * HC + l * 4) = o;
}

// ---------------- hid = relu(g_agg @ W1 + b1), f32x2 inner ----------------
__global__ void mlp1_kernel(const float* __restrict__ W1,
                            const float* __restrict__ b1, int M) {
    __shared__ float As[16][256];
    __shared__ float Bs[16][64];
    int t  = threadIdx.x;
    int tx = t & 15, ty = t >> 4;
    int m0 = blockIdx.x * 256;

    unsigned long long acc2[16][2];
#pragma unroll
    for (int i = 0; i < 16; i++) { acc2[i][0] = 0ull; acc2[i][1] = 0ull; }

    int lr = t >> 2;
    int lc = (t & 3) << 2;
    int wr = t >> 4;
    int wc = (t & 15) << 2;

    for (int kk = 0; kk < 256; kk += 16) {
#pragma unroll
        for (int p = 0; p < 4; p++) {
            int row = lr + p * 64;
            float4 v = make_float4(0.f, 0.f, 0.f, 0.f);
            if (m0 + row < M)
                v = *(const float4*)(g_agg + (size_t)(m0 + row) * 256 + kk + lc);
            As[lc + 0][row] = v.x;
            As[lc + 1][row] = v.y;
            As[lc + 2][row] = v.z;
            As[lc + 3][row] = v.w;
        }
        *(float4*)(&Bs[wr][wc]) = *(const float4*)(W1 + (size_t)(kk + wr) * 64 + wc);
        __syncthreads();
#pragma unroll
        for (int k = 0; k < 16; k++) {
            unsigned long long a2[16], b2[2];
#pragma unroll
            for (int i = 0; i < 16; i++) {
                float av = As[k][ty * 16 + i];
                a2[i] = pk2(av, av);
            }
#pragma unroll
            for (int j = 0; j < 2; j++) {
                float2 bv = *(const float2*)(&Bs[k][tx * 4 + j * 2]);
                b2[j] = pk2(bv.x, bv.y);
            }
#pragma unroll
            for (int i = 0; i < 16; i++) {
                acc2[i][0] = ffma2(a2[i], b2[0], acc2[i][0]);
                acc2[i][1] = ffma2(a2[i], b2[1], acc2[i][1]);
            }
        }
        __syncthreads();
    }
    float4 b1v = *(const float4*)(b1 + tx * 4);
#pragma unroll
    for (int i = 0; i < 16; i++) {
        int row = m0 + ty * 16 + i;
        if (row < M) {
            float2 p0 = upk2(acc2[i][0]);
            float2 p1 = upk2(acc2[i][1]);
            float4 v;
            v.x = fmaxf(p0.x + b1v.x, 0.f);
            v.y = fmaxf(p0.y + b1v.y, 0.f);
            v.z = fmaxf(p1.x + b1v.z, 0.f);
            v.w = fmaxf(p1.y + b1v.w, 0.f);
            *(float4*)(g_hid + (size_t)row * HIDD + tx * 4) = v;
        }
    }
}

// ---------------- out = hid @ W2 + b2 ----------------
__global__ void mlp2_kernel(const float* __restrict__ W2, const float* __restrict__ b2,
                            float* __restrict__ out, int M) {
    __shared__ float sW2[HIDD * OUTC];
    __shared__ float sb2[OUTC];
    __shared__ float sX[128 * 65];
    int t = threadIdx.x;
    for (int i = t; i < HIDD * OUTC; i += 128) sW2[i] = W2[i];
    if (t < OUTC) sb2[t] = b2[t];
    int base = blockIdx.x * 128;
    for (int i = t; i < 128 * HIDD; i += 128) {
        int r = i >> 6, c = i & 63;
        float v = (base + r < M) ? g_hid[(size_t)(base + r) * HIDD + c] : 0.f;
        sX[r * 65 + c] = v;
    }
    __syncthreads();
    int node = base + t;
    if (node >= M) return;
    float acc[OUTC];
#pragma unroll
    for (int j = 0; j < OUTC; j++) acc[j] = sb2[j];
#pragma unroll 4
    for (int k = 0; k < HIDD; k++) {
        float xv = sX[t * 65 + k];
#pragma unroll
        for (int j = 0; j < OUTC; j++) acc[j] = fmaf(xv, sW2[k * OUTC + j], acc[j]);
    }
#pragma unroll
    for (int j = 0; j < OUTC; j++) out[(size_t)node * OUTC + j] = acc[j];
}

// ---------------- launch ----------------
extern "C" void kernel_launch(void* const* d_in, const int* in_sizes, int n_in,
                              void* d_out, int out_size) {
    const float* x         = (const float*)d_in[0];
    const int*   ei        = (const int*)d_in[1];      // int32
    const float* W         = (const float*)d_in[2];
    const float* att_src   = (const float*)d_in[3];
    const float* att_dst   = (const float*)d_in[4];
    const float* bias_conv = (const float*)d_in[5];
    const float* W1        = (const float*)d_in[6];
    const float* b1        = (const float*)d_in[7];
    const float* W2        = (const float*)d_in[8];
    const float* b2        = (const float*)d_in[9];
    float*       out       = (float*)d_out;

    int Nn = in_sizes[0] / INC;
    int E  = in_sizes[1] / 2;
    int ET = E + Nn;

    cudaFuncSetAttribute(gemm_mma_kernel,
                         cudaFuncAttributeMaxDynamicSharedMemorySize, GEMM_SMEM_BYTES);

    gnn_init_kernel<<<(Nn + 255) / 256, 256>>>(Nn);
    convert_x_kernel<<<(Nn * 64 + 255) / 256, 256>>>(x, Nn);
    convert_w_kernel<<<(256 * 256 + 255) / 256, 256>>>(W);

    dim3 gt((Nn + 127) / 128, 2);
    gemm_mma_kernel<<<gt, 256, GEMM_SMEM_BYTES>>>(Nn);

    att_kernel<<<(Nn * Hh * 32 + 255) / 256, 256>>>(att_src, att_dst, Nn);

    edge_deg_kernel<<<(ET + 255) / 256, 256>>>(ei, E, ET, Nn);
    offsets_kernel<<<(Nn + 255) / 256, 256>>>(Nn);
    edge_fill_kernel<<<(ET + 255) / 256, 256>>>(ei, E, ET, Nn);

    agg_kernel<<<(Nn + 3) / 4, 256>>>(bias_conv, Nn);

    mlp1_kernel<<<(Nn + 255) / 256, 256>>>(W1, b1, Nn);
    mlp2_kernel<<<(Nn + 127) / 128, 128>>>(W2, b2, out, Nn);
}

// round 8
// speedup vs baseline: 2.7475x; 1.0043x over previous
#include <cuda_runtime.h>
#include <cuda_bf16.h>
#include <cstdint>
#include <math.h>

#define Hh   4
#define Cc   64
#define HC   256
#define INC  256
#define HIDD 64
#define OUTC 40
#define NEG  0.2f

#define N_MAX  50048
#define E_MAX  800000
#define ET_MAX (E_MAX + N_MAX)

// ---------------- static scratch ----------------
__device__ float g_h[(size_t)N_MAX * HC];
__device__ float g_agg[(size_t)N_MAX * HC];
__device__ float g_hid[(size_t)N_MAX * HIDD];
__device__ float g_asrc[N_MAX * Hh];
__device__ float g_adst[N_MAX * Hh];
__device__ int   g_deg[N_MAX];
__device__ int   g_cnt[N_MAX];
__device__ int   g_off[N_MAX];
__device__ int   g_cursor;
__device__ int   g_csr_src[ET_MAX];
__device__ float g_ee[(size_t)ET_MAX * Hh];

__device__ __align__(16) __nv_bfloat16 g_xhi[(size_t)N_MAX * 256];
__device__ __align__(16) __nv_bfloat16 g_xlo[(size_t)N_MAX * 256];
__device__ __align__(16) __nv_bfloat16 g_bhi[256 * 256];   // B[n,k] = W[k,n]
__device__ __align__(16) __nv_bfloat16 g_blo[256 * 256];

__device__ __forceinline__ int clampi(int v, int n) {
    return (v < 0) ? 0 : ((v >= n) ? n - 1 : v);
}

// ---------------- packed fp32x2 helpers ----------------
__device__ __forceinline__ unsigned long long pk2(float lo, float hi) {
    unsigned long long r;
    asm("mov.b64 %0, {%1, %2};" : "=l"(r) : "f"(lo), "f"(hi));
    return r;
}
__device__ __forceinline__ float2 upk2(unsigned long long v) {
    float lo, hi;
    asm("mov.b64 {%0, %1}, %2;" : "=f"(lo), "=f"(hi) : "l"(v));
    return make_float2(lo, hi);
}
__device__ __forceinline__ unsigned long long ffma2(unsigned long long a,
                                                    unsigned long long b,
                                                    unsigned long long c) {
    unsigned long long d;
    asm("fma.rn.f32x2 %0, %1, %2, %3;" : "=l"(d) : "l"(a), "l"(b), "l"(c));
    return d;
}

// ---------------- warp-level bf16 MMA + ldmatrix ----------------
__device__ __forceinline__ void mma_bf16(float* d, const uint32_t* a, const uint32_t* b) {
    asm volatile(
        "mma.sync.aligned.m16n8k16.row.col.f32.bf16.bf16.f32 "
        "{%0,%1,%2,%3}, {%4,%5,%6,%7}, {%8,%9}, {%0,%1,%2,%3};"
        : "+f"(d[0]), "+f"(d[1]), "+f"(d[2]), "+f"(d[3])
        : "r"(a[0]), "r"(a[1]), "r"(a[2]), "r"(a[3]), "r"(b[0]), "r"(b[1]));
}
__device__ __forceinline__ void ldsm_x4(uint32_t* r, uint32_t addr) {
    asm volatile("ldmatrix.sync.aligned.m8n8.x4.shared.b16 {%0,%1,%2,%3}, [%4];"
                 : "=r"(r[0]), "=r"(r[1]), "=r"(r[2]), "=r"(r[3]) : "r"(addr));
}

// ---------------- cp.async helpers ----------------
__device__ __forceinline__ uint32_t smem_u32(const void* p) {
    uint32_t a;
    asm("{ .reg .u64 t; cvta.to.shared.u64 t, %1; cvt.u32.u64 %0, t; }" : "=r"(a) : "l"(p));
    return a;
}
__device__ __forceinline__ void cpa16(uint32_t dst, const void* src, bool pred) {
    int sz = pred ? 16 : 0;
    asm volatile("cp.async.cg.shared.global [%0], [%1], 16, %2;"
                 :: "r"(dst), "l"(src), "r"(sz));
}
#define CPA_COMMIT() asm volatile("cp.async.commit_group;" ::: "memory")
#define CPA_WAIT(n)  asm volatile("cp.async.wait_group %0;" :: "n"(n) : "memory")

// ---------------- init ----------------
__global__ void gnn_init_kernel(int Nn) {
    int i = blockIdx.x * blockDim.x + threadIdx.x;
    if (i < Nn) { g_deg[i] = 0; g_cnt[i] = 0; }
    if (i == 0) g_cursor = 0;
}

// ---------------- fp32 -> bf16 hi/lo split of x ----------------
__global__ void convert_x_kernel(const float* __restrict__ x, int Nn) {
    int i = blockIdx.x * blockDim.x + threadIdx.x;
    int tot = Nn * 64;
    if (i >= tot) return;
    float4 v = ((const float4*)x)[i];
    float f[4] = {v.x, v.y, v.z, v.w};
    __nv_bfloat16 h[4], l[4];
#pragma unroll
    for (int q = 0; q < 4; q++) {
        h[q] = __float2bfloat16(f[q]);
        l[q] = __float2bfloat16(f[q] - __bfloat162float(h[q]));
    }
    __nv_bfloat162* ph = (__nv_bfloat162*)g_xhi;
    __nv_bfloat162* pl = (__nv_bfloat162*)g_xlo;
    ph[i * 2 + 0] = __halves2bfloat162(h[0], h[1]);
    ph[i * 2 + 1] = __halves2bfloat162(h[2], h[3]);
    pl[i * 2 + 0] = __halves2bfloat162(l[0], l[1]);
    pl[i * 2 + 1] = __halves2bfloat162(l[2], l[3]);
}

// ---------------- W[k,n] -> B[n,k] bf16 hi/lo ----------------
__global__ void convert_w_kernel(const float* __restrict__ W) {
    int idx = blockIdx.x * blockDim.x + threadIdx.x;
    if (idx >= 256 * 256) return;
    int n = idx & 255, k = idx >> 8;
    float w = W[k * 256 + n];
    __nv_bfloat16 h = __float2bfloat16(w);
    __nv_bfloat16 l = __float2bfloat16(w - __bfloat162float(h));
    g_bhi[n * 256 + k] = h;
    g_blo[n * 256 + k] = l;
}

// ---------------- fused-phase, cp.async pipelined, ldmatrix tensor GEMM ----------------
#define APAD    72
#define TILE_EL (128 * APAD)
#define STAGE_EL (4 * TILE_EL)
#define GEMM_SMEM_BYTES (2 * STAGE_EL * 2)   // 147456

__global__ void __launch_bounds__(256)
gemm_mma_kernel(int Nn) {
    extern __shared__ __nv_bfloat16 sm[];
    int tid  = threadIdx.x;
    int wid  = tid >> 5;
    int lane = tid & 31;
    int gid  = lane >> 2;
    int tig  = lane & 3;
    int wm   = (wid & 3) * 32;
    int wn   = (wid >> 2) * 64;
    int m0 = blockIdx.x * 128;
    int n0 = blockIdx.y * 128;

    float acc[2][8][4];
#pragma unroll
    for (int mt = 0; mt < 2; mt++)
#pragma unroll
        for (int nt = 0; nt < 8; nt++)
#pragma unroll
            for (int q = 0; q < 4; q++) acc[mt][nt][q] = 0.f;

    // per-lane ldmatrix address offsets (in bytes, within a tile)
    // A x4: row = wm + mt*16 + ((l>>3)&1)*8 + (l&7); koff = (l>>4)*8
    uint32_t aoff = (uint32_t)((wm + ((lane >> 3) & 1) * 8 + (lane & 7)) * APAD
                               + (lane >> 4) * 8) * 2;
    // B x4 (nt pair p): nrow = wn + p*16 + (l>>4)*8 + (l&7); koff = ((l>>3)&1)*8
    uint32_t boff = (uint32_t)((wn + (lane >> 4) * 8 + (lane & 7)) * APAD
                               + ((lane >> 3) & 1) * 8) * 2;

    auto stage_load = [&](int st, int kk) {
        __nv_bfloat16* base = sm + st * STAGE_EL;
        uint32_t sAhi = smem_u32(base);
        uint32_t sAlo = sAhi + TILE_EL * 2;
        uint32_t sBhi = sAhi + 2 * TILE_EL * 2;
        uint32_t sBlo = sAhi + 3 * TILE_EL * 2;
#pragma unroll
        for (int j0 = 0; j0 < 1024; j0 += 256) {
            int j = j0 + tid;
            int r = j >> 3, u = (j & 7) * 8;
            uint32_t so = (uint32_t)(r * APAD + u) * 2;
            bool am = (m0 + r) < Nn;
            size_t ga = (size_t)(m0 + r) * 256 + kk + u;
            size_t gb = (size_t)(n0 + r) * 256 + kk + u;
            cpa16(sAhi + so, g_xhi + ga, am);
            cpa16(sAlo + so, g_xlo + ga, am);
            cpa16(sBhi + so, g_bhi + gb, true);
            cpa16(sBlo + so, g_blo + gb, true);
        }
        CPA_COMMIT();
    };

    stage_load(0, 0);

    for (int c = 0; c < 4; c++) {
        if (c < 3) stage_load((c + 1) & 1, (c + 1) * 64);
        if (c < 3) { CPA_WAIT(1); } else { CPA_WAIT(0); }
        __syncthreads();

        uint32_t base = smem_u32(sm + (c & 1) * STAGE_EL);
        uint32_t aHi = base + aoff;
        uint32_t aLo = aHi + TILE_EL * 2;
        uint32_t bHi = base + 2 * TILE_EL * 2 + boff;
        uint32_t bLo = bHi + TILE_EL * 2;

#pragma unroll
        for (int ks = 0; ks < 64; ks += 16) {
            uint32_t ahi[2][4], alo[2][4], bhi[4][4], blo[4][4];
#pragma unroll
            for (int mt = 0; mt < 2; mt++) {
                uint32_t d = (uint32_t)(mt * 16 * APAD + ks) * 2;
                ldsm_x4(ahi[mt], aHi + d);
                ldsm_x4(alo[mt], aLo + d);
            }
#pragma unroll
            for (int p = 0; p < 4; p++) {
                uint32_t d = (uint32_t)(p * 16 * APAD + ks) * 2;
                ldsm_x4(bhi[p], bHi + d);
                ldsm_x4(blo[p], bLo + d);
            }
#pragma unroll
            for (int mt = 0; mt < 2; mt++)
#pragma unroll
                for (int nt = 0; nt < 8; nt++) {
                    const uint32_t* bh = &bhi[nt >> 1][(nt & 1) * 2];
                    const uint32_t* bl = &blo[nt >> 1][(nt & 1) * 2];
                    mma_bf16(acc[mt][nt], ahi[mt], bh);
                    mma_bf16(acc[mt][nt], ahi[mt], bl);
                    mma_bf16(acc[mt][nt], alo[mt], bh);
                }
        }
        __syncthreads();
    }

    // epilogue
#pragma unroll
    for (int mt = 0; mt < 2; mt++) {
        int row = m0 + wm + mt * 16 + gid;
#pragma unroll
        for (int nt = 0; nt < 8; nt++) {
            int col = n0 + wn + nt * 8 + tig * 2;
            if (row < Nn)
                *(float2*)(g_h + (size_t)row * 256 + col) =
                    make_float2(acc[mt][nt][0], acc[mt][nt][1]);
            if (row + 8 < Nn)
                *(float2*)(g_h + (size_t)(row + 8) * 256 + col) =
                    make_float2(acc[mt][nt][2], acc[mt][nt][3]);
        }
    }
}

// ---------------- a_src / a_dst: warp per (node, head) ----------------
__global__ void att_kernel(const float* __restrict__ att_src,
                           const float* __restrict__ att_dst, int Nn) {
    int w    = (blockIdx.x * blockDim.x + threadIdx.x) >> 5;
    int lane = threadIdx.x & 31;
    if (w >= Nn * Hh) return;
    int n = w >> 2, hd = w & 3;
    const float* hrow = g_h + (size_t)n * HC + hd * Cc;
    float v1 = hrow[lane], v2 = hrow[lane + 32];
    float s = v1 * __ldg(att_src + hd * Cc + lane) + v2 * __ldg(att_src + hd * Cc + lane + 32);
    float d = v1 * __ldg(att_dst + hd * Cc + lane) + v2 * __ldg(att_dst + hd * Cc + lane + 32);
#pragma unroll
    for (int o = 16; o; o >>= 1) {
        s += __shfl_xor_sync(0xffffffffu, s, o);
        d += __shfl_xor_sync(0xffffffffu, d, o);
    }
    if (lane == 0) { g_asrc[n * Hh + hd] = s; g_adst[n * Hh + hd] = d; }
}

// ---------------- edge pass 1: count in-degrees ----------------
__global__ void edge_deg_kernel(const int* __restrict__ ei, int E, int ET, int Nn) {
    int e = blockIdx.x * blockDim.x + threadIdx.x;
    if (e >= ET) return;
    int d = (e < E) ? clampi(ei[(size_t)E + e], Nn) : (e - E);
    atomicAdd(&g_deg[d], 1);
}

// ---------------- offsets ----------------
__global__ void offsets_kernel(int Nn) {
    int n = blockIdx.x * blockDim.x + threadIdx.x;
    if (n >= Nn) return;
    g_off[n] = atomicAdd(&g_cursor, g_deg[n]);
}

// ---------------- edge pass 2: exp(leaky(logit)) -> CSR slots ----------------
__global__ void edge_fill_kernel(const int* __restrict__ ei, int E, int ET, int Nn) {
    int e = blockIdx.x * blockDim.x + threadIdx.x;
    if (e >= ET) return;
    int s, d;
    if (e < E) { s = clampi(ei[e], Nn); d = clampi(ei[(size_t)E + e], Nn); }
    else       { s = d = e - E; }
    float4 as = *(const float4*)(g_asrc + (size_t)s * Hh);
    float4 ad = *(const float4*)(g_adst + (size_t)d * Hh);
    float v[4];
    v[0] = as.x + ad.x; v[1] = as.y + ad.y; v[2] = as.z + ad.z; v[3] = as.w + ad.w;
#pragma unroll
    for (int h = 0; h < 4; h++) {
        float lv = (v[h] > 0.f) ? v[h] : NEG * v[h];
        v[h] = __expf(lv);
    }
    int slot = g_off[d] + atomicAdd(&g_cnt[d], 1);
    g_csr_src[slot] = s;
    *(float4*)(g_ee + (size_t)slot * Hh) = make_float4(v[0], v[1], v[2], v[3]);
}

// ---------------- aggregation: 64 threads/node ----------------
__global__ void agg_kernel(const float* __restrict__ bias_conv, int Nn) {
    int node = blockIdx.x * 4 + (threadIdx.x >> 6);
    int l    = threadIdx.x & 63;
    if (node >= Nn) return;
    int beg = g_off[node];
    int deg = g_deg[node];
    int hd  = l >> 4;

    float4 acc = make_float4(0.f, 0.f, 0.f, 0.f);
    float den = 0.f;
#pragma unroll 2
    for (int i = 0; i < deg; i++) {
        int slot = beg + i;
        int s    = g_csr_src[slot];
        float a  = g_ee[(size_t)slot * Hh + hd];
        float4 hv = *(const float4*)(g_h + (size_t)s * HC + l * 4);
        den += a;
        acc.x = fmaf(a, hv.x, acc.x);
        acc.y = fmaf(a, hv.y, acc.y);
        acc.z = fmaf(a, hv.z, acc.z);
        acc.w = fmaf(a, hv.w, acc.w);
    }
    float r = 1.f / den;
    float4 bv = *(const float4*)(bias_conv + l * 4);
    float4 o;
    o.x = fmaxf(fmaf(acc.x, r, bv.x), 0.f);
    o.y = fmaxf(fmaf(acc.y, r, bv.y), 0.f);
    o.z = fmaxf(fmaf(acc.z, r, bv.z), 0.f);
    o.w = fmaxf(fmaf(acc.w, r, bv.w), 0.f);
    *(float4*)(g_agg + (size_t)node * HC + l * 4) = o;
}

// ---------------- hid = relu(g_agg @ W1 + b1), f32x2 inner ----------------
__global__ void mlp1_kernel(const float* __restrict__ W1,
                            const float* __restrict__ b1, int M) {
    __shared__ float As[16][256];
    __shared__ float Bs[16][64];
    int t  = threadIdx.x;
    int tx = t & 15, ty = t >> 4;
    int m0 = blockIdx.x * 256;

    unsigned long long acc2[16][2];
#pragma unroll
    for (int i = 0; i < 16; i++) { acc2[i][0] = 0ull; acc2[i][1] = 0ull; }

    int lr = t >> 2;
    int lc = (t & 3) << 2;
    int wr = t >> 4;
    int wc = (t & 15) << 2;

    for (int kk = 0; kk < 256; kk += 16) {
#pragma unroll
        for (int p = 0; p < 4; p++) {
            int row = lr + p * 64;
            float4 v = make_float4(0.f, 0.f, 0.f, 0.f);
            if (m0 + row < M)
                v = *(const float4*)(g_agg + (size_t)(m0 + row) * 256 + kk + lc);
            As[lc + 0][row] = v.x;
            As[lc + 1][row] = v.y;
            As[lc + 2][row] = v.z;
            As[lc + 3][row] = v.w;
        }
        *(float4*)(&Bs[wr][wc]) = *(const float4*)(W1 + (size_t)(kk + wr) * 64 + wc);
        __syncthreads();
#pragma unroll
        for (int k = 0; k < 16; k++) {
            unsigned long long a2[16], b2[2];
#pragma unroll
            for (int i = 0; i < 16; i++) {
                float av = As[k][ty * 16 + i];
                a2[i] = pk2(av, av);
            }
#pragma unroll
            for (int j = 0; j < 2; j++) {
                float2 bv = *(const float2*)(&Bs[k][tx * 4 + j * 2]);
                b2[j] = pk2(bv.x, bv.y);
            }
#pragma unroll
            for (int i = 0; i < 16; i++) {
                acc2[i][0] = ffma2(a2[i], b2[0], acc2[i][0]);
                acc2[i][1] = ffma2(a2[i], b2[1], acc2[i][1]);
            }
        }
        __syncthreads();
    }
    float4 b1v = *(const float4*)(b1 + tx * 4);
#pragma unroll
    for (int i = 0; i < 16; i++) {
        int row = m0 + ty * 16 + i;
        if (row < M) {
            float2 p0 = upk2(acc2[i][0]);
            float2 p1 = upk2(acc2[i][1]);
            float4 v;
            v.x = fmaxf(p0.x + b1v.x, 0.f);
            v.y = fmaxf(p0.y + b1v.y, 0.f);
            v.z = fmaxf(p1.x + b1v.z, 0.f);
            v.w = fmaxf(p1.y + b1v.w, 0.f);
            *(float4*)(g_hid + (size_t)row * HIDD + tx * 4) = v;
        }
    }
}

// ---------------- out = hid @ W2 + b2 ----------------
__global__ void mlp2_kernel(const float* __restrict__ W2, const float* __restrict__ b2,
                            float* __restrict__ out, int M) {
    __shared__ float sW2[HIDD * OUTC];
    __shared__ float sb2[OUTC];
    __shared__ float sX[128 * 65];
    int t = threadIdx.x;
    for (int i = t; i < HIDD * OUTC; i += 128) sW2[i] = W2[i];
    if (t < OUTC) sb2[t] = b2[t];
    int base = blockIdx.x * 128;
    for (int i = t; i < 128 * HIDD; i += 128) {
        int r = i >> 6, c = i & 63;
        float v = (base + r < M) ? g_hid[(size_t)(base + r) * HIDD + c] : 0.f;
        sX[r * 65 + c] = v;
    }
    __syncthreads();
    int node = base + t;
    if (node >= M) return;
    float acc[OUTC];
#pragma unroll
    for (int j = 0; j < OUTC; j++) acc[j] = sb2[j];
#pragma unroll 4
    for (int k = 0; k < HIDD; k++) {
        float xv = sX[t * 65 + k];
#pragma unroll
        for (int j = 0; j < OUTC; j++) acc[j] = fmaf(xv, sW2[k * OUTC + j], acc[j]);
    }
#pragma unroll
    for (int j = 0; j < OUTC; j++) out[(size_t)node * OUTC + j] = acc[j];
}

// ---------------- launch ----------------
extern "C" void kernel_launch(void* const* d_in, const int* in_sizes, int n_in,
                              void* d_out, int out_size) {
    const float* x         = (const float*)d_in[0];
    const int*   ei        = (const int*)d_in[1];      // int32
    const float* W         = (const float*)d_in[2];
    const float* att_src   = (const float*)d_in[3];
    const float* att_dst   = (const float*)d_in[4];
    const float* bias_conv = (const float*)d_in[5];
    const float* W1        = (const float*)d_in[6];
    const float* b1        = (const float*)d_in[7];
    const float* W2        = (const float*)d_in[8];
    const float* b2        = (const float*)d_in[9];
    float*       out       = (float*)d_out;

    int Nn = in_sizes[0] / INC;
    int E  = in_sizes[1] / 2;
    int ET = E + Nn;

    cudaFuncSetAttribute(gemm_mma_kernel,
                         cudaFuncAttributeMaxDynamicSharedMemorySize, GEMM_SMEM_BYTES);

    gnn_init_kernel<<<(Nn + 255) / 256, 256>>>(Nn);
    convert_x_kernel<<<(Nn * 64 + 255) / 256, 256>>>(x, Nn);
    convert_w_kernel<<<(256 * 256 + 255) / 256, 256>>>(W);

    dim3 gt((Nn + 127) / 128, 2);
    gemm_mma_kernel<<<gt, 256, GEMM_SMEM_BYTES>>>(Nn);

    att_kernel<<<(Nn * Hh * 32 + 255) / 256, 256>>>(att_src, att_dst, Nn);

    edge_deg_kernel<<<(ET + 255) / 256, 256>>>(ei, E, ET, Nn);
    offsets_kernel<<<(Nn + 255) / 256, 256>>>(Nn);
    edge_fill_kernel<<<(ET + 255) / 256, 256>>>(ei, E, ET, Nn);

    agg_kernel<<<(Nn + 3) / 4, 256>>>(bias_conv, Nn);

    mlp1_kernel<<<(Nn + 255) / 256, 256>>>(W1, b1, Nn);
    mlp2_kernel<<<(Nn + 127) / 128, 128>>>(W2, b2, out, Nn);
}

// round 9
// speedup vs baseline: 2.7680x; 1.0075x over previous
#include <cuda_runtime.h>
#include <cuda_bf16.h>
#include <cstdint>
#include <math.h>

#define Hh   4
#define Cc   64
#define HC   256
#define INC  256
#define HIDD 64
#define OUTC 40
#define NEG  0.2f

#define N_MAX  50048
#define E_MAX  800000
#define ET_MAX (E_MAX + N_MAX)

// ---------------- static scratch ----------------
__device__ float g_h[(size_t)N_MAX * HC];
__device__ float g_agg[(size_t)N_MAX * HC];
__device__ float g_hid[(size_t)N_MAX * HIDD];
__device__ float g_asrc[N_MAX * Hh];
__device__ float g_adst[N_MAX * Hh];
__device__ int   g_deg[N_MAX];
__device__ int   g_cnt[N_MAX];
__device__ int   g_off[N_MAX];
__device__ int   g_cursor;
__device__ int   g_csr_src[ET_MAX];
__device__ float g_ee[(size_t)ET_MAX * Hh];

__device__ __align__(16) __nv_bfloat16 g_xhi[(size_t)N_MAX * 256];
__device__ __align__(16) __nv_bfloat16 g_xlo[(size_t)N_MAX * 256];
__device__ __align__(16) __nv_bfloat16 g_bhi[256 * 256];   // B[n,k] = W[k,n]
__device__ __align__(16) __nv_bfloat16 g_blo[256 * 256];

__device__ __forceinline__ int clampi(int v, int n) {
    return (v < 0) ? 0 : ((v >= n) ? n - 1 : v);
}

// ---------------- packed fp32x2 helpers ----------------
__device__ __forceinline__ unsigned long long pk2(float lo, float hi) {
    unsigned long long r;
    asm("mov.b64 %0, {%1, %2};" : "=l"(r) : "f"(lo), "f"(hi));
    return r;
}
__device__ __forceinline__ float2 upk2(unsigned long long v) {
    float lo, hi;
    asm("mov.b64 {%0, %1}, %2;" : "=f"(lo), "=f"(hi) : "l"(v));
    return make_float2(lo, hi);
}
__device__ __forceinline__ unsigned long long ffma2(unsigned long long a,
                                                    unsigned long long b,
                                                    unsigned long long c) {
    unsigned long long d;
    asm("fma.rn.f32x2 %0, %1, %2, %3;" : "=l"(d) : "l"(a), "l"(b), "l"(c));
    return d;
}

// ---------------- warp-level bf16 MMA + ldmatrix ----------------
__device__ __forceinline__ void mma_bf16(float* d, const uint32_t* a, const uint32_t* b) {
    asm volatile(
        "mma.sync.aligned.m16n8k16.row.col.f32.bf16.bf16.f32 "
        "{%0,%1,%2,%3}, {%4,%5,%6,%7}, {%8,%9}, {%0,%1,%2,%3};"
        : "+f"(d[0]), "+f"(d[1]), "+f"(d[2]), "+f"(d[3])
        : "r"(a[0]), "r"(a[1]), "r"(a[2]), "r"(a[3]), "r"(b[0]), "r"(b[1]));
}
__device__ __forceinline__ void ldsm_x4(uint32_t* r, uint32_t addr) {
    asm volatile("ldmatrix.sync.aligned.m8n8.x4.shared.b16 {%0,%1,%2,%3}, [%4];"
                 : "=r"(r[0]), "=r"(r[1]), "=r"(r[2]), "=r"(r[3]) : "r"(addr));
}

// ---------------- cp.async helpers ----------------
__device__ __forceinline__ uint32_t smem_u32(const void* p) {
    uint32_t a;
    asm("{ .reg .u64 t; cvta.to.shared.u64 t, %1; cvt.u32.u64 %0, t; }" : "=r"(a) : "l"(p));
    return a;
}
__device__ __forceinline__ void cpa16(uint32_t dst, const void* src, bool pred) {
    int sz = pred ? 16 : 0;
    asm volatile("cp.async.cg.shared.global [%0], [%1], 16, %2;"
                 :: "r"(dst), "l"(src), "r"(sz));
}
#define CPA_COMMIT() asm volatile("cp.async.commit_group;" ::: "memory")
#define CPA_WAIT(n)  asm volatile("cp.async.wait_group %0;" :: "n"(n) : "memory")

// ---------------- init ----------------
__global__ void gnn_init_kernel(int Nn) {
    int i = blockIdx.x * blockDim.x + threadIdx.x;
    if (i < Nn) { g_deg[i] = 0; g_cnt[i] = 0; }
    if (i == 0) g_cursor = 0;
}

// ---------------- fused: fp32->bf16 split of x  +  edge in-degree count ----------------
__global__ void convx_deg_kernel(const float* __restrict__ x,
                                 const int* __restrict__ ei,
                                 int Nn, int E, int ET) {
    int i = blockIdx.x * blockDim.x + threadIdx.x;
    int tot = Nn * 64;
    if (i < tot) {
        float4 v = ((const float4*)x)[i];
        float f[4] = {v.x, v.y, v.z, v.w};
        __nv_bfloat16 h[4], l[4];
#pragma unroll
        for (int q = 0; q < 4; q++) {
            h[q] = __float2bfloat16(f[q]);
            l[q] = __float2bfloat16(f[q] - __bfloat162float(h[q]));
        }
        __nv_bfloat162* ph = (__nv_bfloat162*)g_xhi;
        __nv_bfloat162* pl = (__nv_bfloat162*)g_xlo;
        ph[i * 2 + 0] = __halves2bfloat162(h[0], h[1]);
        ph[i * 2 + 1] = __halves2bfloat162(h[2], h[3]);
        pl[i * 2 + 0] = __halves2bfloat162(l[0], l[1]);
        pl[i * 2 + 1] = __halves2bfloat162(l[2], l[3]);
    }
    if (i < ET) {
        int d = (i < E) ? clampi(ei[(size_t)E + i], Nn) : (i - E);
        atomicAdd(&g_deg[d], 1);
    }
}

// ---------------- fused: W[k,n] -> B[n,k] bf16 hi/lo  +  CSR offsets ----------------
__global__ void convw_off_kernel(const float* __restrict__ W, int Nn) {
    int idx = blockIdx.x * blockDim.x + threadIdx.x;
    if (idx < 256 * 256) {
        int n = idx & 255, k = idx >> 8;
        float w = W[k * 256 + n];
        __nv_bfloat16 h = __float2bfloat16(w);
        __nv_bfloat16 l = __float2bfloat16(w - __bfloat162float(h));
        g_bhi[n * 256 + k] = h;
        g_blo[n * 256 + k] = l;
    }
    if (idx < Nn)
        g_off[idx] = atomicAdd(&g_cursor, g_deg[idx]);
}

// ---------------- tensor GEMM: 512 threads, 16 warps, warp tile 32x32 ----------------
#define APAD    72
#define TILE_EL (128 * APAD)
#define STAGE_EL (4 * TILE_EL)
#define GEMM_SMEM_BYTES (2 * STAGE_EL * 2)   // 147456

__global__ void __launch_bounds__(512, 1)
gemm_mma_kernel(int Nn) {
    extern __shared__ __nv_bfloat16 sm[];
    int tid  = threadIdx.x;
    int wid  = tid >> 5;
    int lane = tid & 31;
    int gid  = lane >> 2;
    int tig  = lane & 3;
    int wm   = (wid & 3) * 32;
    int wn   = (wid >> 2) * 32;
    int m0 = blockIdx.x * 128;
    int n0 = blockIdx.y * 128;

    float acc[2][4][4];
#pragma unroll
    for (int mt = 0; mt < 2; mt++)
#pragma unroll
        for (int nt = 0; nt < 4; nt++)
#pragma unroll
            for (int q = 0; q < 4; q++) acc[mt][nt][q] = 0.f;

    // ldmatrix per-lane offsets (bytes within a tile)
    uint32_t aoff = (uint32_t)((wm + ((lane >> 3) & 1) * 8 + (lane & 7)) * APAD
                               + (lane >> 4) * 8) * 2;
    uint32_t boff = (uint32_t)((wn + (lane >> 4) * 8 + (lane & 7)) * APAD
                               + ((lane >> 3) & 1) * 8) * 2;

    auto stage_load = [&](int st, int kk) {
        __nv_bfloat16* base = sm + st * STAGE_EL;
        uint32_t sAhi = smem_u32(base);
        uint32_t sAlo = sAhi + TILE_EL * 2;
        uint32_t sBhi = sAhi + 2 * TILE_EL * 2;
        uint32_t sBlo = sAhi + 3 * TILE_EL * 2;
#pragma unroll
        for (int j0 = 0; j0 < 1024; j0 += 512) {
            int j = j0 + tid;
            int r = j >> 3, u = (j & 7) * 8;
            uint32_t so = (uint32_t)(r * APAD + u) * 2;
            bool am = (m0 + r) < Nn;
            size_t ga = (size_t)(m0 + r) * 256 + kk + u;
            size_t gb = (size_t)(n0 + r) * 256 + kk + u;
            cpa16(sAhi + so, g_xhi + ga, am);
            cpa16(sAlo + so, g_xlo + ga, am);
            cpa16(sBhi + so, g_bhi + gb, true);
            cpa16(sBlo + so, g_blo + gb, true);
        }
        CPA_COMMIT();
    };

    stage_load(0, 0);

    for (int c = 0; c < 4; c++) {
        if (c < 3) stage_load((c + 1) & 1, (c + 1) * 64);
        if (c < 3) { CPA_WAIT(1); } else { CPA_WAIT(0); }
        __syncthreads();

        uint32_t base = smem_u32(sm + (c & 1) * STAGE_EL);
        uint32_t aHi = base + aoff;
        uint32_t aLo = aHi + TILE_EL * 2;
        uint32_t bHi = base + 2 * TILE_EL * 2 + boff;
        uint32_t bLo = bHi + TILE_EL * 2;

#pragma unroll
        for (int ks = 0; ks < 64; ks += 16) {
            uint32_t ahi[2][4], alo[2][4], bhi[2][4], blo[2][4];
#pragma unroll
            for (int mt = 0; mt < 2; mt++) {
                uint32_t d = (uint32_t)(mt * 16 * APAD + ks) * 2;
                ldsm_x4(ahi[mt], aHi + d);
                ldsm_x4(alo[mt], aLo + d);
            }
#pragma unroll
            for (int p = 0; p < 2; p++) {
                uint32_t d = (uint32_t)(p * 16 * APAD + ks) * 2;
                ldsm_x4(bhi[p], bHi + d);
                ldsm_x4(blo[p], bLo + d);
            }
            // phase-ordered: 8 independent MMAs per phase
#pragma unroll
            for (int mt = 0; mt < 2; mt++)
#pragma unroll
                for (int nt = 0; nt < 4; nt++)
                    mma_bf16(acc[mt][nt], ahi[mt], &bhi[nt >> 1][(nt & 1) * 2]);
#pragma unroll
            for (int mt = 0; mt < 2; mt++)
#pragma unroll
                for (int nt = 0; nt < 4; nt++)
                    mma_bf16(acc[mt][nt], ahi[mt], &blo[nt >> 1][(nt & 1) * 2]);
#pragma unroll
            for (int mt = 0; mt < 2; mt++)
#pragma unroll
                for (int nt = 0; nt < 4; nt++)
                    mma_bf16(acc[mt][nt], alo[mt], &bhi[nt >> 1][(nt & 1) * 2]);
        }
        __syncthreads();
    }

    // epilogue
#pragma unroll
    for (int mt = 0; mt < 2; mt++) {
        int row = m0 + wm + mt * 16 + gid;
#pragma unroll
        for (int nt = 0; nt < 4; nt++) {
            int col = n0 + wn + nt * 8 + tig * 2;
            if (row < Nn)
                *(float2*)(g_h + (size_t)row * 256 + col) =
                    make_float2(acc[mt][nt][0], acc[mt][nt][1]);
            if (row + 8 < Nn)
                *(float2*)(g_h + (size_t)(row + 8) * 256 + col) =
                    make_float2(acc[mt][nt][2], acc[mt][nt][3]);
        }
    }
}

// ---------------- a_src / a_dst: warp per (node, head) ----------------
__global__ void att_kernel(const float* __restrict__ att_src,
                           const float* __restrict__ att_dst, int Nn) {
    int w    = (blockIdx.x * blockDim.x + threadIdx.x) >> 5;
    int lane = threadIdx.x & 31;
    if (w >= Nn * Hh) return;
    int n = w >> 2, hd = w & 3;
    const float* hrow = g_h + (size_t)n * HC + hd * Cc;
    float v1 = hrow[lane], v2 = hrow[lane + 32];
    float s = v1 * __ldg(att_src + hd * Cc + lane) + v2 * __ldg(att_src + hd * Cc + lane + 32);
    float d = v1 * __ldg(att_dst + hd * Cc + lane) + v2 * __ldg(att_dst + hd * Cc + lane + 32);
#pragma unroll
    for (int o = 16; o; o >>= 1) {
        s += __shfl_xor_sync(0xffffffffu, s, o);
        d += __shfl_xor_sync(0xffffffffu, d, o);
    }
    if (lane == 0) { g_asrc[n * Hh + hd] = s; g_adst[n * Hh + hd] = d; }
}

// ---------------- edge pass 2: exp(leaky(logit)) -> CSR slots ----------------
__global__ void edge_fill_kernel(const int* __restrict__ ei, int E, int ET, int Nn) {
    int e = blockIdx.x * blockDim.x + threadIdx.x;
    if (e >= ET) return;
    int s, d;
    if (e < E) { s = clampi(ei[e], Nn); d = clampi(ei[(size_t)E + e], Nn); }
    else       { s = d = e - E; }
    float4 as = *(const float4*)(g_asrc + (size_t)s * Hh);
    float4 ad = *(const float4*)(g_adst + (size_t)d * Hh);
    float v[4];
    v[0] = as.x + ad.x; v[1] = as.y + ad.y; v[2] = as.z + ad.z; v[3] = as.w + ad.w;
#pragma unroll
    for (int h = 0; h < 4; h++) {
        float lv = (v[h] > 0.f) ? v[h] : NEG * v[h];
        v[h] = __expf(lv);
    }
    int slot = g_off[d] + atomicAdd(&g_cnt[d], 1);
    g_csr_src[slot] = s;
    *(float4*)(g_ee + (size_t)slot * Hh) = make_float4(v[0], v[1], v[2], v[3]);
}

// ---------------- aggregation: 64 threads/node ----------------
__global__ void agg_kernel(const float* __restrict__ bias_conv, int Nn) {
    int node = blockIdx.x * 4 + (threadIdx.x >> 6);
    int l    = threadIdx.x & 63;
    if (node >= Nn) return;
    int beg = g_off[node];
    int deg = g_deg[node];
    int hd  = l >> 4;

    float4 acc = make_float4(0.f, 0.f, 0.f, 0.f);
    float den = 0.f;
#pragma unroll 2
    for (int i = 0; i < deg; i++) {
        int slot = beg + i;
        int s    = g_csr_src[slot];
        float a  = g_ee[(size_t)slot * Hh + hd];
        float4 hv = *(const float4*)(g_h + (size_t)s * HC + l * 4);
        den += a;
        acc.x = fmaf(a, hv.x, acc.x);
        acc.y = fmaf(a, hv.y, acc.y);
        acc.z = fmaf(a, hv.z, acc.z);
        acc.w = fmaf(a, hv.w, acc.w);
    }
    float r = 1.f / den;
    float4 bv = *(const float4*)(bias_conv + l * 4);
    float4 o;
    o.x = fmaxf(fmaf(acc.x, r, bv.x), 0.f);
    o.y = fmaxf(fmaf(acc.y, r, bv.y), 0.f);
    o.z = fmaxf(fmaf(acc.z, r, bv.z), 0.f);
    o.w = fmaxf(fmaf(acc.w, r, bv.w), 0.f);
    *(float4*)(g_agg + (size_t)node * HC + l * 4) = o;
}

// ---------------- hid = relu(g_agg @ W1 + b1), f32x2 inner ----------------
__global__ void mlp1_kernel(const float* __restrict__ W1,
                            const float* __restrict__ b1, int M) {
    __shared__ float As[16][256];
    __shared__ float Bs[16][64];
    int t  = threadIdx.x;
    int tx = t & 15, ty = t >> 4;
    int m0 = blockIdx.x * 256;

    unsigned long long acc2[16][2];
#pragma unroll
    for (int i = 0; i < 16; i++) { acc2[i][0] = 0ull; acc2[i][1] = 0ull; }

    int lr = t >> 2;
    int lc = (t & 3) << 2;
    int wr = t >> 4;
    int wc = (t & 15) << 2;

    for (int kk = 0; kk < 256; kk += 16) {
#pragma unroll
        for (int p = 0; p < 4; p++) {
            int row = lr + p * 64;
            float4 v = make_float4(0.f, 0.f, 0.f, 0.f);
            if (m0 + row < M)
                v = *(const float4*)(g_agg + (size_t)(m0 + row) * 256 + kk + lc);
            As[lc + 0][row] = v.x;
            As[lc + 1][row] = v.y;
            As[lc + 2][row] = v.z;
            As[lc + 3][row] = v.w;
        }
        *(float4*)(&Bs[wr][wc]) = *(const float4*)(W1 + (size_t)(kk + wr) * 64 + wc);
        __syncthreads();
#pragma unroll
        for (int k = 0; k < 16; k++) {
            unsigned long long a2[16], b2[2];
#pragma unroll
            for (int i = 0; i < 16; i++) {
                float av = As[k][ty * 16 + i];
                a2[i] = pk2(av, av);
            }
#pragma unroll
            for (int j = 0; j < 2; j++) {
                float2 bv = *(const float2*)(&Bs[k][tx * 4 + j * 2]);
                b2[j] = pk2(bv.x, bv.y);
            }
#pragma unroll
            for (int i = 0; i < 16; i++) {
                acc2[i][0] = ffma2(a2[i], b2[0], acc2[i][0]);
                acc2[i][1] = ffma2(a2[i], b2[1], acc2[i][1]);
            }
        }
        __syncthreads();
    }
    float4 b1v = *(const float4*)(b1 + tx * 4);
#pragma unroll
    for (int i = 0; i < 16; i++) {
        int row = m0 + ty * 16 + i;
        if (row < M) {
            float2 p0 = upk2(acc2[i][0]);
            float2 p1 = upk2(acc2[i][1]);
            float4 v;
            v.x = fmaxf(p0.x + b1v.x, 0.f);
            v.y = fmaxf(p0.y + b1v.y, 0.f);
            v.z = fmaxf(p1.x + b1v.z, 0.f);
            v.w = fmaxf(p1.y + b1v.w, 0.f);
            *(float4*)(g_hid + (size_t)row * HIDD + tx * 4) = v;
        }
    }
}

// ---------------- out = hid @ W2 + b2 ----------------
__global__ void mlp2_kernel(const float* __restrict__ W2, const float* __restrict__ b2,
                            float* __restrict__ out, int M) {
    __shared__ float sW2[HIDD * OUTC];
    __shared__ float sb2[OUTC];
    __shared__ float sX[128 * 65];
    int t = threadIdx.x;
    for (int i = t; i < HIDD * OUTC; i += 128) sW2[i] = W2[i];
    if (t < OUTC) sb2[t] = b2[t];
    int base = blockIdx.x * 128;
    for (int i = t; i < 128 * HIDD; i += 128) {
        int r = i >> 6, c = i & 63;
        float v = (base + r < M) ? g_hid[(size_t)(base + r) * HIDD + c] : 0.f;
        sX[r * 65 + c] = v;
    }
    __syncthreads();
    int node = base + t;
    if (node >= M) return;
    float acc[OUTC];
#pragma unroll
    for (int j = 0; j < OUTC; j++) acc[j] = sb2[j];
#pragma unroll 4
    for (int k = 0; k < HIDD; k++) {
        float xv = sX[t * 65 + k];
#pragma unroll
        for (int j = 0; j < OUTC; j++) acc[j] = fmaf(xv, sW2[k * OUTC + j], acc[j]);
    }
#pragma unroll
    for (int j = 0; j < OUTC; j++) out[(size_t)node * OUTC + j] = acc[j];
}

// ---------------- launch ----------------
extern "C" void kernel_launch(void* const* d_in, const int* in_sizes, int n_in,
                              void* d_out, int out_size) {
    const float* x         = (const float*)d_in[0];
    const int*   ei        = (const int*)d_in[1];      // int32
    const float* W         = (const float*)d_in[2];
    const float* att_src   = (const float*)d_in[3];
    const float* att_dst   = (const float*)d_in[4];
    const float* bias_conv = (const float*)d_in[5];
    const float* W1        = (const float*)d_in[6];
    const float* b1        = (const float*)d_in[7];
    const float* W2        = (const float*)d_in[8];
    const float* b2        = (const float*)d_in[9];
    float*       out       = (float*)d_out;

    int Nn = in_sizes[0] / INC;
    int E  = in_sizes[1] / 2;
    int ET = E + Nn;

    cudaFuncSetAttribute(gemm_mma_kernel,
                         cudaFuncAttributeMaxDynamicSharedMemorySize, GEMM_SMEM_BYTES);

    gnn_init_kernel<<<(Nn + 255) / 256, 256>>>(Nn);

    int t1 = Nn * 64; if (ET > t1) t1 = ET;
    convx_deg_kernel<<<(t1 + 255) / 256, 256>>>(x, ei, Nn, E, ET);
    convw_off_kernel<<<(256 * 256 + 255) / 256, 256>>>(W, Nn);

    dim3 gt((Nn + 127) / 128, 2);
    gemm_mma_kernel<<<gt, 512, GEMM_SMEM_BYTES>>>(Nn);

    att_kernel<<<(Nn * Hh * 32 + 255) / 256, 256>>>(att_src, att_dst, Nn);

    edge_fill_kernel<<<(ET + 255) / 256, 256>>>(ei, E, ET, Nn);

    agg_kernel<<<(Nn + 3) / 4, 256>>>(bias_conv, Nn);

    mlp1_kernel<<<(Nn + 255) / 256, 256>>>(W1, b1, Nn);
    mlp2_kernel<<<(Nn + 127) / 128, 128>>>(W2, b2, out, Nn);
}

// round 10
// speedup vs baseline: 3.0610x; 1.1058x over previous
#include <cuda_runtime.h>
#include <cuda_bf16.h>
#include <cuda_fp16.h>
#include <cstdint>
#include <math.h>

#define Hh   4
#define Cc   64
#define HC   256
#define INC  256
#define HIDD 64
#define OUTC 40
#define NEG  0.2f

#define N_MAX  50048
#define E_MAX  800000
#define ET_MAX (E_MAX + N_MAX)

// ---------------- static scratch ----------------
__device__ __align__(16) __half g_hh[(size_t)N_MAX * HC];   // h in fp16
__device__ float g_agg[(size_t)N_MAX * HC];
__device__ float g_hid[(size_t)N_MAX * HIDD];
__device__ float g_asrc[N_MAX * Hh];
__device__ float g_adst[N_MAX * Hh];
__device__ int   g_deg[N_MAX];
__device__ int   g_cnt[N_MAX];
__device__ int   g_off[N_MAX];
__device__ int   g_cursor;
__device__ int   g_csr_src[ET_MAX];
__device__ float g_ee[(size_t)ET_MAX * Hh];

__device__ __align__(16) __nv_bfloat16 g_xhi[(size_t)N_MAX * 256];
__device__ __align__(16) __nv_bfloat16 g_xlo[(size_t)N_MAX * 256];
__device__ __align__(16) __nv_bfloat16 g_bhi[256 * 256];   // B[n,k] = W[k,n]
__device__ __align__(16) __nv_bfloat16 g_blo[256 * 256];

__device__ __forceinline__ int clampi(int v, int n) {
    return (v < 0) ? 0 : ((v >= n) ? n - 1 : v);
}

// ---------------- packed fp32x2 helpers ----------------
__device__ __forceinline__ unsigned long long pk2(float lo, float hi) {
    unsigned long long r;
    asm("mov.b64 %0, {%1, %2};" : "=l"(r) : "f"(lo), "f"(hi));
    return r;
}
__device__ __forceinline__ float2 upk2(unsigned long long v) {
    float lo, hi;
    asm("mov.b64 {%0, %1}, %2;" : "=f"(lo), "=f"(hi) : "l"(v));
    return make_float2(lo, hi);
}
__device__ __forceinline__ unsigned long long ffma2(unsigned long long a,
                                                    unsigned long long b,
                                                    unsigned long long c) {
    unsigned long long d;
    asm("fma.rn.f32x2 %0, %1, %2, %3;" : "=l"(d) : "l"(a), "l"(b), "l"(c));
    return d;
}

// ---------------- warp-level bf16 MMA + ldmatrix ----------------
__device__ __forceinline__ void mma_bf16(float* d, const uint32_t* a, const uint32_t* b) {
    asm volatile(
        "mma.sync.aligned.m16n8k16.row.col.f32.bf16.bf16.f32 "
        "{%0,%1,%2,%3}, {%4,%5,%6,%7}, {%8,%9}, {%0,%1,%2,%3};"
        : "+f"(d[0]), "+f"(d[1]), "+f"(d[2]), "+f"(d[3])
        : "r"(a[0]), "r"(a[1]), "r"(a[2]), "r"(a[3]), "r"(b[0]), "r"(b[1]));
}
__device__ __forceinline__ void ldsm_x4(uint32_t* r, uint32_t addr) {
    asm volatile("ldmatrix.sync.aligned.m8n8.x4.shared.b16 {%0,%1,%2,%3}, [%4];"
                 : "=r"(r[0]), "=r"(r[1]), "=r"(r[2]), "=r"(r[3]) : "r"(addr));
}

// ---------------- cp.async helpers ----------------
__device__ __forceinline__ uint32_t smem_u32(const void* p) {
    uint32_t a;
    asm("{ .reg .u64 t; cvta.to.shared.u64 t, %1; cvt.u32.u64 %0, t; }" : "=r"(a) : "l"(p));
    return a;
}
__device__ __forceinline__ void cpa16(uint32_t dst, const void* src, bool pred) {
    int sz = pred ? 16 : 0;
    asm volatile("cp.async.cg.shared.global [%0], [%1], 16, %2;"
                 :: "r"(dst), "l"(src), "r"(sz));
}
#define CPA_COMMIT() asm volatile("cp.async.commit_group;" ::: "memory")
#define CPA_WAIT(n)  asm volatile("cp.async.wait_group %0;" :: "n"(n) : "memory")

// ---------------- init ----------------
__global__ void gnn_init_kernel(int Nn) {
    int i = blockIdx.x * blockDim.x + threadIdx.x;
    if (i < Nn) { g_deg[i] = 0; g_cnt[i] = 0; }
    if (i == 0) g_cursor = 0;
}

// ---------------- fused: fp32->bf16 split of x  +  edge in-degree count ----------------
__global__ void convx_deg_kernel(const float* __restrict__ x,
                                 const int* __restrict__ ei,
                                 int Nn, int E, int ET) {
    int i = blockIdx.x * blockDim.x + threadIdx.x;
    int tot = Nn * 64;
    if (i < tot) {
        float4 v = ((const float4*)x)[i];
        float f[4] = {v.x, v.y, v.z, v.w};
        __nv_bfloat16 h[4], l[4];
#pragma unroll
        for (int q = 0; q < 4; q++) {
            h[q] = __float2bfloat16(f[q]);
            l[q] = __float2bfloat16(f[q] - __bfloat162float(h[q]));
        }
        __nv_bfloat162* ph = (__nv_bfloat162*)g_xhi;
        __nv_bfloat162* pl = (__nv_bfloat162*)g_xlo;
        ph[i * 2 + 0] = __halves2bfloat162(h[0], h[1]);
        ph[i * 2 + 1] = __halves2bfloat162(h[2], h[3]);
        pl[i * 2 + 0] = __halves2bfloat162(l[0], l[1]);
        pl[i * 2 + 1] = __halves2bfloat162(l[2], l[3]);
    }
    if (i < ET) {
        int d = (i < E) ? clampi(ei[(size_t)E + i], Nn) : (i - E);
        atomicAdd(&g_deg[d], 1);
    }
}

// ---------------- fused: W[k,n] -> B[n,k] bf16 hi/lo  +  CSR offsets ----------------
__global__ void convw_off_kernel(const float* __restrict__ W, int Nn) {
    int idx = blockIdx.x * blockDim.x + threadIdx.x;
    if (idx < 256 * 256) {
        int n = idx & 255, k = idx >> 8;
        float w = W[k * 256 + n];
        __nv_bfloat16 h = __float2bfloat16(w);
        __nv_bfloat16 l = __float2bfloat16(w - __bfloat162float(h));
        g_bhi[n * 256 + k] = h;
        g_blo[n * 256 + k] = l;
    }
    if (idx < Nn)
        g_off[idx] = atomicAdd(&g_cursor, g_deg[idx]);
}

// ---------------- tensor GEMM + fused attention epilogue ----------------
// 512 thr, 16 warps, warp tile 32x32. Epilogue: h -> fp16 g_hh, and
// a_src/a_dst reduced from acc registers via shfl + smem (CTA owns 2 heads).
#define APAD    72
#define TILE_EL (128 * APAD)
#define STAGE_EL (4 * TILE_EL)
#define GEMM_SMEM_BYTES (2 * STAGE_EL * 2)   // 147456

__global__ void __launch_bounds__(512, 1)
gemm_mma_kernel(const float* __restrict__ att_src,
                const float* __restrict__ att_dst, int Nn) {
    extern __shared__ __nv_bfloat16 sm[];
    int tid  = threadIdx.x;
    int wid  = tid >> 5;
    int lane = tid & 31;
    int gid  = lane >> 2;
    int tig  = lane & 3;
    int wm   = (wid & 3) * 32;
    int wn   = (wid >> 2) * 32;
    int m0 = blockIdx.x * 128;
    int n0 = blockIdx.y * 128;

    float acc[2][4][4];
#pragma unroll
    for (int mt = 0; mt < 2; mt++)
#pragma unroll
        for (int nt = 0; nt < 4; nt++)
#pragma unroll
            for (int q = 0; q < 4; q++) acc[mt][nt][q] = 0.f;

    uint32_t aoff = (uint32_t)((wm + ((lane >> 3) & 1) * 8 + (lane & 7)) * APAD
                               + (lane >> 4) * 8) * 2;
    uint32_t boff = (uint32_t)((wn + (lane >> 4) * 8 + (lane & 7)) * APAD
                               + ((lane >> 3) & 1) * 8) * 2;

    auto stage_load = [&](int st, int kk) {
        __nv_bfloat16* base = sm + st * STAGE_EL;
        uint32_t sAhi = smem_u32(base);
        uint32_t sAlo = sAhi + TILE_EL * 2;
        uint32_t sBhi = sAhi + 2 * TILE_EL * 2;
        uint32_t sBlo = sAhi + 3 * TILE_EL * 2;
#pragma unroll
        for (int j0 = 0; j0 < 1024; j0 += 512) {
            int j = j0 + tid;
            int r = j >> 3, u = (j & 7) * 8;
            uint32_t so = (uint32_t)(r * APAD + u) * 2;
            bool am = (m0 + r) < Nn;
            size_t ga = (size_t)(m0 + r) * 256 + kk + u;
            size_t gb = (size_t)(n0 + r) * 256 + kk + u;
            cpa16(sAhi + so, g_xhi + ga, am);
            cpa16(sAlo + so, g_xlo + ga, am);
            cpa16(sBhi + so, g_bhi + gb, true);
            cpa16(sBlo + so, g_blo + gb, true);
        }
        CPA_COMMIT();
    };

    stage_load(0, 0);

    for (int c = 0; c < 4; c++) {
        if (c < 3) stage_load((c + 1) & 1, (c + 1) * 64);
        if (c < 3) { CPA_WAIT(1); } else { CPA_WAIT(0); }
        __syncthreads();

        uint32_t base = smem_u32(sm + (c & 1) * STAGE_EL);
        uint32_t aHi = base + aoff;
        uint32_t aLo = aHi + TILE_EL * 2;
        uint32_t bHi = base + 2 * TILE_EL * 2 + boff;
        uint32_t bLo = bHi + TILE_EL * 2;

#pragma unroll
        for (int ks = 0; ks < 64; ks += 16) {
            uint32_t ahi[2][4], alo[2][4], bhi[2][4], blo[2][4];
#pragma unroll
            for (int mt = 0; mt < 2; mt++) {
                uint32_t d = (uint32_t)(mt * 16 * APAD + ks) * 2;
                ldsm_x4(ahi[mt], aHi + d);
                ldsm_x4(alo[mt], aLo + d);
            }
#pragma unroll
            for (int p = 0; p < 2; p++) {
                uint32_t d = (uint32_t)(p * 16 * APAD + ks) * 2;
                ldsm_x4(bhi[p], bHi + d);
                ldsm_x4(blo[p], bLo + d);
            }
#pragma unroll
            for (int mt = 0; mt < 2; mt++)
#pragma unroll
                for (int nt = 0; nt < 4; nt++)
                    mma_bf16(acc[mt][nt], ahi[mt], &bhi[nt >> 1][(nt & 1) * 2]);
#pragma unroll
            for (int mt = 0; mt < 2; mt++)
#pragma unroll
                for (int nt = 0; nt < 4; nt++)
                    mma_bf16(acc[mt][nt], ahi[mt], &blo[nt >> 1][(nt & 1) * 2]);
#pragma unroll
            for (int mt = 0; mt < 2; mt++)
#pragma unroll
                for (int nt = 0; nt < 4; nt++)
                    mma_bf16(acc[mt][nt], alo[mt], &bhi[nt >> 1][(nt & 1) * 2]);
        }
        __syncthreads();
    }

    // ---- epilogue 1: store h as fp16 ----
#pragma unroll
    for (int mt = 0; mt < 2; mt++) {
        int row = m0 + wm + mt * 16 + gid;
#pragma unroll
        for (int nt = 0; nt < 4; nt++) {
            int col = n0 + wn + nt * 8 + tig * 2;
            if (row < Nn)
                *(__half2*)(g_hh + (size_t)row * 256 + col) =
                    __floats2half2_rn(acc[mt][nt][0], acc[mt][nt][1]);
            if (row + 8 < Nn)
                *(__half2*)(g_hh + (size_t)(row + 8) * 256 + col) =
                    __floats2half2_rn(acc[mt][nt][2], acc[mt][nt][3]);
        }
    }

    // ---- epilogue 2: fused attention logits (a_src/a_dst) ----
    float* sA = (float*)sm;          // [128][2]
    float* sD = sA + 256;            // [128][2]
    if (tid < 256) { sA[tid] = 0.f; sD[tid] = 0.f; }
    __syncthreads();

    int lh = wn >> 6;                // local head 0/1 (warp-uniform)
    const float* ats = att_src + (blockIdx.y * 2 + lh) * 64;
    const float* atd = att_dst + (blockIdx.y * 2 + lh) * 64;

#pragma unroll
    for (int mt = 0; mt < 2; mt++) {
        float s0 = 0.f, d0 = 0.f, s1 = 0.f, d1 = 0.f;
#pragma unroll
        for (int nt = 0; nt < 4; nt++)
#pragma unroll
            for (int q = 0; q < 2; q++) {
                int cc = (wn & 63) + nt * 8 + tig * 2 + q;
                float ws = __ldg(ats + cc);
                float wd = __ldg(atd + cc);
                s0 = fmaf(acc[mt][nt][q], ws, s0);
                d0 = fmaf(acc[mt][nt][q], wd, d0);
                s1 = fmaf(acc[mt][nt][q + 2], ws, s1);
                d1 = fmaf(acc[mt][nt][q + 2], wd, d1);
            }
#pragma unroll
        for (int off = 1; off <= 2; off <<= 1) {
            s0 += __shfl_xor_sync(0xffffffffu, s0, off);
            d0 += __shfl_xor_sync(0xffffffffu, d0, off);
            s1 += __shfl_xor_sync(0xffffffffu, s1, off);
            d1 += __shfl_xor_sync(0xffffffffu, d1, off);
        }
        if (tig == 0) {
            int r0 = wm + mt * 16 + gid;
            atomicAdd(&sA[r0 * 2 + lh], s0);
            atomicAdd(&sD[r0 * 2 + lh], d0);
            atomicAdd(&sA[(r0 + 8) * 2 + lh], s1);
            atomicAdd(&sD[(r0 + 8) * 2 + lh], d1);
        }
    }
    __syncthreads();
    if (tid < 256) {
        int r = tid >> 1, h2 = tid & 1;
        int grow = m0 + r;
        if (grow < Nn) {
            int gh = blockIdx.y * 2 + h2;
            g_asrc[grow * 4 + gh] = sA[r * 2 + h2];
            g_adst[grow * 4 + gh] = sD[r * 2 + h2];
        }
    }
}

// ---------------- edge pass 2: exp(leaky(logit)) -> CSR slots ----------------
__global__ void edge_fill_kernel(const int* __restrict__ ei, int E, int ET, int Nn) {
    int e = blockIdx.x * blockDim.x + threadIdx.x;
    if (e >= ET) return;
    int s, d;
    if (e < E) { s = clampi(ei[e], Nn); d = clampi(ei[(size_t)E + e], Nn); }
    else       { s = d = e - E; }
    float4 as = *(const float4*)(g_asrc + (size_t)s * Hh);
    float4 ad = *(const float4*)(g_adst + (size_t)d * Hh);
    float v[4];
    v[0] = as.x + ad.x; v[1] = as.y + ad.y; v[2] = as.z + ad.z; v[3] = as.w + ad.w;
#pragma unroll
    for (int h = 0; h < 4; h++) {
        float lv = (v[h] > 0.f) ? v[h] : NEG * v[h];
        v[h] = __expf(lv);
    }
    int slot = g_off[d] + atomicAdd(&g_cnt[d], 1);
    g_csr_src[slot] = s;
    *(float4*)(g_ee + (size_t)slot * Hh) = make_float4(v[0], v[1], v[2], v[3]);
}

// ---------------- aggregation: 32 threads/node, fp16 gather ----------------
__global__ void agg_kernel(const float* __restrict__ bias_conv, int Nn) {
    int node = blockIdx.x * 8 + (threadIdx.x >> 5);
    int l    = threadIdx.x & 31;      // 8-col group index
    if (node >= Nn) return;
    int beg = g_off[node];
    int deg = g_deg[node];
    int hd  = l >> 3;

    float acc[8];
#pragma unroll
    for (int q = 0; q < 8; q++) acc[q] = 0.f;
    float den = 0.f;
#pragma unroll 2
    for (int i = 0; i < deg; i++) {
        int slot = beg + i;
        int s    = g_csr_src[slot];
        float a  = g_ee[(size_t)slot * Hh + hd];
        uint4 hv = *(const uint4*)(g_hh + (size_t)s * 256 + l * 8);
        __half2 p0 = *(__half2*)&hv.x, p1 = *(__half2*)&hv.y;
        __half2 p2 = *(__half2*)&hv.z, p3 = *(__half2*)&hv.w;
        float2 f0 = __half22float2(p0), f1 = __half22float2(p1);
        float2 f2 = __half22float2(p2), f3 = __half22float2(p3);
        den += a;
        acc[0] = fmaf(a, f0.x, acc[0]); acc[1] = fmaf(a, f0.y, acc[1]);
        acc[2] = fmaf(a, f1.x, acc[2]); acc[3] = fmaf(a, f1.y, acc[3]);
        acc[4] = fmaf(a, f2.x, acc[4]); acc[5] = fmaf(a, f2.y, acc[5]);
        acc[6] = fmaf(a, f3.x, acc[6]); acc[7] = fmaf(a, f3.y, acc[7]);
    }
    float r = 1.f / den;
    float4 b0 = *(const float4*)(bias_conv + l * 8);
    float4 b1 = *(const float4*)(bias_conv + l * 8 + 4);
    float4 o0, o1;
    o0.x = fmaxf(fmaf(acc[0], r, b0.x), 0.f);
    o0.y = fmaxf(fmaf(acc[1], r, b0.y), 0.f);
    o0.z = fmaxf(fmaf(acc[2], r, b0.z), 0.f);
    o0.w = fmaxf(fmaf(acc[3], r, b0.w), 0.f);
    o1.x = fmaxf(fmaf(acc[4], r, b1.x), 0.f);
    o1.y = fmaxf(fmaf(acc[5], r, b1.y), 0.f);
    o1.z = fmaxf(fmaf(acc[6], r, b1.z), 0.f);
    o1.w = fmaxf(fmaf(acc[7], r, b1.w), 0.f);
    *(float4*)(g_agg + (size_t)node * HC + l * 8)     = o0;
    *(float4*)(g_agg + (size_t)node * HC + l * 8 + 4) = o1;
}

// ---------------- hid = relu(g_agg @ W1 + b1), f32x2 inner ----------------
__global__ void mlp1_kernel(const float* __restrict__ W1,
                            const float* __restrict__ b1, int M) {
    __shared__ float As[16][256];
    __shared__ float Bs[16][64];
    int t  = threadIdx.x;
    int tx = t & 15, ty = t >> 4;
    int m0 = blockIdx.x * 256;

    unsigned long long acc2[16][2];
#pragma unroll
    for (int i = 0; i < 16; i++) { acc2[i][0] = 0ull; acc2[i][1] = 0ull; }

    int lr = t >> 2;
    int lc = (t & 3) << 2;
    int wr = t >> 4;
    int wc = (t & 15) << 2;

    for (int kk = 0; kk < 256; kk += 16) {
#pragma unroll
        for (int p = 0; p < 4; p++) {
            int row = lr + p * 64;
            float4 v = make_float4(0.f, 0.f, 0.f, 0.f);
            if (m0 + row < M)
                v = *(const float4*)(g_agg + (size_t)(m0 + row) * 256 + kk + lc);
            As[lc + 0][row] = v.x;
            As[lc + 1][row] = v.y;
            As[lc + 2][row] = v.z;
            As[lc + 3][row] = v.w;
        }
        *(float4*)(&Bs[wr][wc]) = *(const float4*)(W1 + (size_t)(kk + wr) * 64 + wc);
        __syncthreads();
#pragma unroll
        for (int k = 0; k < 16; k++) {
            unsigned long long a2[16], b2[2];
#pragma unroll
            for (int i = 0; i < 16; i++) {
                float av = As[k][ty * 16 + i];
                a2[i] = pk2(av, av);
            }
#pragma unroll
            for (int j = 0; j < 2; j++) {
                float2 bv = *(const float2*)(&Bs[k][tx * 4 + j * 2]);
                b2[j] = pk2(bv.x, bv.y);
            }
#pragma unroll
            for (int i = 0; i < 16; i++) {
                acc2[i][0] = ffma2(a2[i], b2[0], acc2[i][0]);
                acc2[i][1] = ffma2(a2[i], b2[1], acc2[i][1]);
            }
        }
        __syncthreads();
    }
    float4 b1v = *(const float4*)(b1 + tx * 4);
#pragma unroll
    for (int i = 0; i < 16; i++) {
        int row = m0 + ty * 16 + i;
        if (row < M) {
            float2 p0 = upk2(acc2[i][0]);
            float2 p1 = upk2(acc2[i][1]);
            float4 v;
            v.x = fmaxf(p0.x + b1v.x, 0.f);
            v.y = fmaxf(p0.y + b1v.y, 0.f);
            v.z = fmaxf(p1.x + b1v.z, 0.f);
            v.w = fmaxf(p1.y + b1v.w, 0.f);
            *(float4*)(g_hid + (size_t)row * HIDD + tx * 4) = v;
        }
    }
}

// ---------------- out = hid @ W2 + b2 ----------------
__global__ void mlp2_kernel(const float* __restrict__ W2, const float* __restrict__ b2,
                            float* __restrict__ out, int M) {
    __shared__ float sW2[HIDD * OUTC];
    __shared__ float sb2[OUTC];
    __shared__ float sX[128 * 65];
    int t = threadIdx.x;
    for (int i = t; i < HIDD * OUTC; i += 128) sW2[i] = W2[i];
    if (t < OUTC) sb2[t] = b2[t];
    int base = blockIdx.x * 128;
    for (int i = t; i < 128 * HIDD; i += 128) {
        int r = i >> 6, c = i & 63;
        float v = (base + r < M) ? g_hid[(size_t)(base + r) * HIDD + c] : 0.f;
        sX[r * 65 + c] = v;
    }
    __syncthreads();
    int node = base + t;
    if (node >= M) return;
    float acc[OUTC];
#pragma unroll
    for (int j = 0; j < OUTC; j++) acc[j] = sb2[j];
#pragma unroll 4
    for (int k = 0; k < HIDD; k++) {
        float xv = sX[t * 65 + k];
#pragma unroll
        for (int j = 0; j < OUTC; j++) acc[j] = fmaf(xv, sW2[k * OUTC + j], acc[j]);
    }
#pragma unroll
    for (int j = 0; j < OUTC; j++) out[(size_t)node * OUTC + j] = acc[j];
}

// ---------------- launch ----------------
extern "C" void kernel_launch(void* const* d_in, const int* in_sizes, int n_in,
                              void* d_out, int out_size) {
    const float* x         = (const float*)d_in[0];
    const int*   ei        = (const int*)d_in[1];      // int32
    const float* W         = (const float*)d_in[2];
    const float* att_src   = (const float*)d_in[3];
    const float* att_dst   = (const float*)d_in[4];
    const float* bias_conv = (const float*)d_in[5];
    const float* W1        = (const float*)d_in[6];
    const float* b1        = (const float*)d_in[7];
    const float* W2        = (const float*)d_in[8];
    const float* b2        = (const float*)d_in[9];
    float*       out       = (float*)d_out;

    int Nn = in_sizes[0] / INC;
    int E  = in_sizes[1] / 2;
    int ET = E + Nn;

    cudaFuncSetAttribute(gemm_mma_kernel,
                         cudaFuncAttributeMaxDynamicSharedMemorySize, GEMM_SMEM_BYTES);

    gnn_init_kernel<<<(Nn + 255) / 256, 256>>>(Nn);

    int t1 = Nn * 64; if (ET > t1) t1 = ET;
    convx_deg_kernel<<<(t1 + 255) / 256, 256>>>(x, ei, Nn, E, ET);
    convw_off_kernel<<<(256 * 256 + 255) / 256, 256>>>(W, Nn);

    dim3 gt((Nn + 127) / 128, 2);
    gemm_mma_kernel<<<gt, 512, GEMM_SMEM_BYTES>>>(att_src, att_dst, Nn);

    edge_fill_kernel<<<(ET + 255) / 256, 256>>>(ei, E, ET, Nn);

    agg_kernel<<<(Nn + 7) / 8, 256>>>(bias_conv, Nn);

    mlp1_kernel<<<(Nn + 255) / 256, 256>>>(W1, b1, Nn);
    mlp2_kernel<<<(Nn + 127) / 128, 128>>>(W2, b2, out, Nn);
}

// round 11
// speedup vs baseline: 3.4041x; 1.1121x over previous
#include <cuda_runtime.h>
#include <cuda_fp16.h>
#include <cstdint>
#include <math.h>

#define Hh   4
#define Cc   64
#define HC   256
#define INC  256
#define HIDD 64
#define OUTC 40
#define NEG  0.2f

#define N_MAX  50048
#define E_MAX  800000
#define ET_MAX (E_MAX + N_MAX)

// ---------------- static scratch ----------------
__device__ __align__(16) __half g_hh[(size_t)N_MAX * HC];    // h in fp16
__device__ __align__(16) __half g_agg[(size_t)N_MAX * HC];   // relu(agg/den+bias), fp16
__device__ float g_asrc[N_MAX * Hh];
__device__ float g_adst[N_MAX * Hh];
__device__ int   g_deg[N_MAX];
__device__ int   g_cnt[N_MAX];
__device__ int   g_off[N_MAX];
__device__ int   g_cursor;
__device__ int   g_csr_src[ET_MAX];
__device__ float g_ee[(size_t)ET_MAX * Hh];

// fp16 split operands for tensor-core GEMM
__device__ __align__(16) __half g_xhi[(size_t)N_MAX * 256];
__device__ __align__(16) __half g_xlo[(size_t)N_MAX * 256];
__device__ __align__(16) __half g_bhi[256 * 256];   // B[n,k] = W[k,n]
__device__ __align__(16) __half g_blo[256 * 256];

__device__ __forceinline__ int clampi(int v, int n) {
    return (v < 0) ? 0 : ((v >= n) ? n - 1 : v);
}

// ---------------- packed fp32x2 helpers ----------------
__device__ __forceinline__ unsigned long long pk2(float lo, float hi) {
    unsigned long long r;
    asm("mov.b64 %0, {%1, %2};" : "=l"(r) : "f"(lo), "f"(hi));
    return r;
}
__device__ __forceinline__ float2 upk2(unsigned long long v) {
    float lo, hi;
    asm("mov.b64 {%0, %1}, %2;" : "=f"(lo), "=f"(hi) : "l"(v));
    return make_float2(lo, hi);
}
__device__ __forceinline__ unsigned long long ffma2(unsigned long long a,
                                                    unsigned long long b,
                                                    unsigned long long c) {
    unsigned long long d;
    asm("fma.rn.f32x2 %0, %1, %2, %3;" : "=l"(d) : "l"(a), "l"(b), "l"(c));
    return d;
}

// ---------------- warp-level fp16 MMA + ldmatrix ----------------
__device__ __forceinline__ void mma_f16(float* d, const uint32_t* a, const uint32_t* b) {
    asm volatile(
        "mma.sync.aligned.m16n8k16.row.col.f32.f16.f16.f32 "
        "{%0,%1,%2,%3}, {%4,%5,%6,%7}, {%8,%9}, {%0,%1,%2,%3};"
        : "+f"(d[0]), "+f"(d[1]), "+f"(d[2]), "+f"(d[3])
        : "r"(a[0]), "r"(a[1]), "r"(a[2]), "r"(a[3]), "r"(b[0]), "r"(b[1]));
}
__device__ __forceinline__ void ldsm_x4(uint32_t* r, uint32_t addr) {
    asm volatile("ldmatrix.sync.aligned.m8n8.x4.shared.b16 {%0,%1,%2,%3}, [%4];"
                 : "=r"(r[0]), "=r"(r[1]), "=r"(r[2]), "=r"(r[3]) : "r"(addr));
}

// ---------------- cp.async helpers ----------------
__device__ __forceinline__ uint32_t smem_u32(const void* p) {
    uint32_t a;
    asm("{ .reg .u64 t; cvta.to.shared.u64 t, %1; cvt.u32.u64 %0, t; }" : "=r"(a) : "l"(p));
    return a;
}
__device__ __forceinline__ void cpa16(uint32_t dst, const void* src, bool pred) {
    int sz = pred ? 16 : 0;
    asm volatile("cp.async.cg.shared.global [%0], [%1], 16, %2;"
                 :: "r"(dst), "l"(src), "r"(sz));
}
#define CPA_COMMIT() asm volatile("cp.async.commit_group;" ::: "memory")
#define CPA_WAIT(n)  asm volatile("cp.async.wait_group %0;" :: "n"(n) : "memory")

// ---------------- init ----------------
__global__ void gnn_init_kernel(int Nn) {
    int i = blockIdx.x * blockDim.x + threadIdx.x;
    if (i < Nn) { g_deg[i] = 0; g_cnt[i] = 0; }
    if (i == 0) g_cursor = 0;
}

// ---------------- fused: fp32->fp16 split of x  +  edge in-degree count ----------------
__global__ void convx_deg_kernel(const float* __restrict__ x,
                                 const int* __restrict__ ei,
                                 int Nn, int E, int ET) {
    int i = blockIdx.x * blockDim.x + threadIdx.x;
    int tot = Nn * 64;
    if (i < tot) {
        float4 v = ((const float4*)x)[i];
        float f[4] = {v.x, v.y, v.z, v.w};
        __half h[4], l[4];
#pragma unroll
        for (int q = 0; q < 4; q++) {
            h[q] = __float2half_rn(f[q]);
            l[q] = __float2half_rn(f[q] - __half2float(h[q]));
        }
        __half2* ph = (__half2*)g_xhi;
        __half2* pl = (__half2*)g_xlo;
        ph[i * 2 + 0] = __halves2half2(h[0], h[1]);
        ph[i * 2 + 1] = __halves2half2(h[2], h[3]);
        pl[i * 2 + 0] = __halves2half2(l[0], l[1]);
        pl[i * 2 + 1] = __halves2half2(l[2], l[3]);
    }
    if (i < ET) {
        int d = (i < E) ? clampi(ei[(size_t)E + i], Nn) : (i - E);
        atomicAdd(&g_deg[d], 1);
    }
}

// ---------------- fused: W[k,n] -> B[n,k] fp16 hi/lo  +  CSR offsets ----------------
__global__ void convw_off_kernel(const float* __restrict__ W, int Nn) {
    int idx = blockIdx.x * blockDim.x + threadIdx.x;
    if (idx < 256 * 256) {
        int n = idx & 255, k = idx >> 8;
        float w = W[k * 256 + n];
        __half h = __float2half_rn(w);
        __half l = __float2half_rn(w - __half2float(h));
        g_bhi[n * 256 + k] = h;
        g_blo[n * 256 + k] = l;
    }
    if (idx < Nn)
        g_off[idx] = atomicAdd(&g_cursor, g_deg[idx]);
}

// ---------------- tensor GEMM + fused attention epilogue ----------------
#define APAD    72
#define TILE_EL (128 * APAD)
#define STAGE_EL (4 * TILE_EL)
#define GEMM_SMEM_BYTES (2 * STAGE_EL * 2)   // 147456

__global__ void __launch_bounds__(512, 1)
gemm_mma_kernel(const float* __restrict__ att_src,
                const float* __restrict__ att_dst, int Nn) {
    extern __shared__ __half sm[];
    int tid  = threadIdx.x;
    int wid  = tid >> 5;
    int lane = tid & 31;
    int gid  = lane >> 2;
    int tig  = lane & 3;
    int wm   = (wid & 3) * 32;
    int wn   = (wid >> 2) * 32;
    int m0 = blockIdx.x * 128;
    int n0 = blockIdx.y * 128;

    float acc[2][4][4];
#pragma unroll
    for (int mt = 0; mt < 2; mt++)
#pragma unroll
        for (int nt = 0; nt < 4; nt++)
#pragma unroll
            for (int q = 0; q < 4; q++) acc[mt][nt][q] = 0.f;

    uint32_t aoff = (uint32_t)((wm + ((lane >> 3) & 1) * 8 + (lane & 7)) * APAD
                               + (lane >> 4) * 8) * 2;
    uint32_t boff = (uint32_t)((wn + (lane >> 4) * 8 + (lane & 7)) * APAD
                               + ((lane >> 3) & 1) * 8) * 2;

    auto stage_load = [&](int st, int kk) {
        __half* base = sm + st * STAGE_EL;
        uint32_t sAhi = smem_u32(base);
        uint32_t sAlo = sAhi + TILE_EL * 2;
        uint32_t sBhi = sAhi + 2 * TILE_EL * 2;
        uint32_t sBlo = sAhi + 3 * TILE_EL * 2;
#pragma unroll
        for (int j0 = 0; j0 < 1024; j0 += 512) {
            int j = j0 + tid;
            int r = j >> 3, u = (j & 7) * 8;
            uint32_t so = (uint32_t)(r * APAD + u) * 2;
            bool am = (m0 + r) < Nn;
            size_t ga = (size_t)(m0 + r) * 256 + kk + u;
            size_t gb = (size_t)(n0 + r) * 256 + kk + u;
            cpa16(sAhi + so, g_xhi + ga, am);
            cpa16(sAlo + so, g_xlo + ga, am);
            cpa16(sBhi + so, g_bhi + gb, true);
            cpa16(sBlo + so, g_blo + gb, true);
        }
        CPA_COMMIT();
    };

    stage_load(0, 0);

    for (int c = 0; c < 4; c++) {
        if (c < 3) stage_load((c + 1) & 1, (c + 1) * 64);
        if (c < 3) { CPA_WAIT(1); } else { CPA_WAIT(0); }
        __syncthreads();

        uint32_t base = smem_u32(sm + (c & 1) * STAGE_EL);
        uint32_t aHi = base + aoff;
        uint32_t aLo = aHi + TILE_EL * 2;
        uint32_t bHi = base + 2 * TILE_EL * 2 + boff;
        uint32_t bLo = bHi + TILE_EL * 2;

#pragma unroll
        for (int ks = 0; ks < 64; ks += 16) {
            uint32_t ahi[2][4], alo[2][4], bhi[2][4], blo[2][4];
#pragma unroll
            for (int mt = 0; mt < 2; mt++) {
                uint32_t d = (uint32_t)(mt * 16 * APAD + ks) * 2;
                ldsm_x4(ahi[mt], aHi + d);
                ldsm_x4(alo[mt], aLo + d);
            }
#pragma unroll
            for (int p = 0; p < 2; p++) {
                uint32_t d = (uint32_t)(p * 16 * APAD + ks) * 2;
                ldsm_x4(bhi[p], bHi + d);
                ldsm_x4(blo[p], bLo + d);
            }
#pragma unroll
            for (int mt = 0; mt < 2; mt++)
#pragma unroll
                for (int nt = 0; nt < 4; nt++)
                    mma_f16(acc[mt][nt], ahi[mt], &bhi[nt >> 1][(nt & 1) * 2]);
#pragma unroll
            for (int mt = 0; mt < 2; mt++)
#pragma unroll
                for (int nt = 0; nt < 4; nt++)
                    mma_f16(acc[mt][nt], ahi[mt], &blo[nt >> 1][(nt & 1) * 2]);
#pragma unroll
            for (int mt = 0; mt < 2; mt++)
#pragma unroll
                for (int nt = 0; nt < 4; nt++)
                    mma_f16(acc[mt][nt], alo[mt], &bhi[nt >> 1][(nt & 1) * 2]);
        }
        __syncthreads();
    }

    // ---- epilogue 1: store h as fp16 ----
#pragma unroll
    for (int mt = 0; mt < 2; mt++) {
        int row = m0 + wm + mt * 16 + gid;
#pragma unroll
        for (int nt = 0; nt < 4; nt++) {
            int col = n0 + wn + nt * 8 + tig * 2;
            if (row < Nn)
                *(__half2*)(g_hh + (size_t)row * 256 + col) =
                    __floats2half2_rn(acc[mt][nt][0], acc[mt][nt][1]);
            if (row + 8 < Nn)
                *(__half2*)(g_hh + (size_t)(row + 8) * 256 + col) =
                    __floats2half2_rn(acc[mt][nt][2], acc[mt][nt][3]);
        }
    }

    // ---- epilogue 2: fused attention logits ----
    float* sA = (float*)sm;          // [128][2]
    float* sD = sA + 256;            // [128][2]
    if (tid < 256) { sA[tid] = 0.f; sD[tid] = 0.f; }
    __syncthreads();

    int lh = wn >> 6;                // local head 0/1 (warp-uniform)
    const float* ats = att_src + (blockIdx.y * 2 + lh) * 64;
    const float* atd = att_dst + (blockIdx.y * 2 + lh) * 64;

#pragma unroll
    for (int mt = 0; mt < 2; mt++) {
        float s0 = 0.f, d0 = 0.f, s1 = 0.f, d1 = 0.f;
#pragma unroll
        for (int nt = 0; nt < 4; nt++)
#pragma unroll
            for (int q = 0; q < 2; q++) {
                int cc = (wn & 63) + nt * 8 + tig * 2 + q;
                float ws = __ldg(ats + cc);
                float wd = __ldg(atd + cc);
                s0 = fmaf(acc[mt][nt][q], ws, s0);
                d0 = fmaf(acc[mt][nt][q], wd, d0);
                s1 = fmaf(acc[mt][nt][q + 2], ws, s1);
                d1 = fmaf(acc[mt][nt][q + 2], wd, d1);
            }
#pragma unroll
        for (int off = 1; off <= 2; off <<= 1) {
            s0 += __shfl_xor_sync(0xffffffffu, s0, off);
            d0 += __shfl_xor_sync(0xffffffffu, d0, off);
            s1 += __shfl_xor_sync(0xffffffffu, s1, off);
            d1 += __shfl_xor_sync(0xffffffffu, d1, off);
        }
        if (tig == 0) {
            int r0 = wm + mt * 16 + gid;
            atomicAdd(&sA[r0 * 2 + lh], s0);
            atomicAdd(&sD[r0 * 2 + lh], d0);
            atomicAdd(&sA[(r0 + 8) * 2 + lh], s1);
            atomicAdd(&sD[(r0 + 8) * 2 + lh], d1);
        }
    }
    __syncthreads();
    if (tid < 256) {
        int r = tid >> 1, h2 = tid & 1;
        int grow = m0 + r;
        if (grow < Nn) {
            int gh = blockIdx.y * 2 + h2;
            g_asrc[grow * 4 + gh] = sA[r * 2 + h2];
            g_adst[grow * 4 + gh] = sD[r * 2 + h2];
        }
    }
}

// ---------------- edge pass 2: exp(leaky(logit)) -> CSR slots ----------------
__global__ void edge_fill_kernel(const int* __restrict__ ei, int E, int ET, int Nn) {
    int e = blockIdx.x * blockDim.x + threadIdx.x;
    if (e >= ET) return;
    int s, d;
    if (e < E) { s = clampi(ei[e], Nn); d = clampi(ei[(size_t)E + e], Nn); }
    else       { s = d = e - E; }
    float4 as = *(const float4*)(g_asrc + (size_t)s * Hh);
    float4 ad = *(const float4*)(g_adst + (size_t)d * Hh);
    float v[4];
    v[0] = as.x + ad.x; v[1] = as.y + ad.y; v[2] = as.z + ad.z; v[3] = as.w + ad.w;
#pragma unroll
    for (int h = 0; h < 4; h++) {
        float lv = (v[h] > 0.f) ? v[h] : NEG * v[h];
        v[h] = __expf(lv);
    }
    int slot = g_off[d] + atomicAdd(&g_cnt[d], 1);
    g_csr_src[slot] = s;
    *(float4*)(g_ee + (size_t)slot * Hh) = make_float4(v[0], v[1], v[2], v[3]);
}

// ---------------- aggregation: 32 threads/node, fp16 gather, fp16 agg out ----------------
__global__ void agg_kernel(const float* __restrict__ bias_conv, int Nn) {
    int node = blockIdx.x * 8 + (threadIdx.x >> 5);
    int l    = threadIdx.x & 31;
    if (node >= Nn) return;
    int beg = g_off[node];
    int deg = g_deg[node];
    int hd  = l >> 3;

    float acc[8];
#pragma unroll
    for (int q = 0; q < 8; q++) acc[q] = 0.f;
    float den = 0.f;
#pragma unroll 2
    for (int i = 0; i < deg; i++) {
        int slot = beg + i;
        int s    = g_csr_src[slot];
        float a  = g_ee[(size_t)slot * Hh + hd];
        uint4 hv = *(const uint4*)(g_hh + (size_t)s * 256 + l * 8);
        __half2 p0 = *(__half2*)&hv.x, p1 = *(__half2*)&hv.y;
        __half2 p2 = *(__half2*)&hv.z, p3 = *(__half2*)&hv.w;
        float2 f0 = __half22float2(p0), f1 = __half22float2(p1);
        float2 f2 = __half22float2(p2), f3 = __half22float2(p3);
        den += a;
        acc[0] = fmaf(a, f0.x, acc[0]); acc[1] = fmaf(a, f0.y, acc[1]);
        acc[2] = fmaf(a, f1.x, acc[2]); acc[3] = fmaf(a, f1.y, acc[3]);
        acc[4] = fmaf(a, f2.x, acc[4]); acc[5] = fmaf(a, f2.y, acc[5]);
        acc[6] = fmaf(a, f3.x, acc[6]); acc[7] = fmaf(a, f3.y, acc[7]);
    }
    float r = 1.f / den;
    float4 b0 = *(const float4*)(bias_conv + l * 8);
    float4 b1 = *(const float4*)(bias_conv + l * 8 + 4);
    float o[8];
    o[0] = fmaxf(fmaf(acc[0], r, b0.x), 0.f);
    o[1] = fmaxf(fmaf(acc[1], r, b0.y), 0.f);
    o[2] = fmaxf(fmaf(acc[2], r, b0.z), 0.f);
    o[3] = fmaxf(fmaf(acc[3], r, b0.w), 0.f);
    o[4] = fmaxf(fmaf(acc[4], r, b1.x), 0.f);
    o[5] = fmaxf(fmaf(acc[5], r, b1.y), 0.f);
    o[6] = fmaxf(fmaf(acc[6], r, b1.z), 0.f);
    o[7] = fmaxf(fmaf(acc[7], r, b1.w), 0.f);
    uint4 ov;
    ((__half2*)&ov)[0] = __floats2half2_rn(o[0], o[1]);
    ((__half2*)&ov)[1] = __floats2half2_rn(o[2], o[3]);
    ((__half2*)&ov)[2] = __floats2half2_rn(o[4], o[5]);
    ((__half2*)&ov)[3] = __floats2half2_rn(o[6], o[7]);
    *(uint4*)(g_agg + (size_t)node * HC + l * 8) = ov;
}

// ---------------- fused MLP: out = relu(g_agg @ W1 + b1) @ W2 + b2 ----------------
// 256 rows/CTA. hid tile kept in smem fp16; per-thread row GEMM for mlp2.
#define MLP_SMEM_BYTES ((16 * 256 + 16 * 64 + 2560 + 40) * 4 + 256 * 66 * 2)  // 64672

__global__ void __launch_bounds__(256)
mlp_kernel(const float* __restrict__ W1, const float* __restrict__ b1,
           const float* __restrict__ W2, const float* __restrict__ b2,
           float* __restrict__ out, int M) {
    extern __shared__ char smc[];
    float*  As   = (float*)smc;                 // [16][256]
    float*  Bs   = As + 16 * 256;               // [16][64]
    float*  sW2  = Bs + 16 * 64;                // [64][40]
    float*  sb2  = sW2 + 2560;                  // [40]
    __half* sHid = (__half*)(sb2 + 40);         // [256][66]

    int t  = threadIdx.x;
    int tx = t & 15, ty = t >> 4;
    int m0 = blockIdx.x * 256;

    for (int i = t; i < 2560; i += 256) sW2[i] = W2[i];
    if (t < 40) sb2[t] = b2[t];

    unsigned long long acc2[16][2];
#pragma unroll
    for (int i = 0; i < 16; i++) { acc2[i][0] = 0ull; acc2[i][1] = 0ull; }

    int lr = t >> 2;
    int lc = (t & 3) << 2;
    int wr = t >> 4;
    int wc = (t & 15) << 2;

    for (int kk = 0; kk < 256; kk += 16) {
#pragma unroll
        for (int p = 0; p < 4; p++) {
            int row = lr + p * 64;
            uint2 hv = make_uint2(0u, 0u);
            if (m0 + row < M)
                hv = *(const uint2*)(g_agg + (size_t)(m0 + row) * 256 + kk + lc);
            float2 f01 = __half22float2(*(__half2*)&hv.x);
            float2 f23 = __half22float2(*(__half2*)&hv.y);
            As[(lc + 0) * 256 + row] = f01.x;
            As[(lc + 1) * 256 + row] = f01.y;
            As[(lc + 2) * 256 + row] = f23.x;
            As[(lc + 3) * 256 + row] = f23.y;
        }
        *(float4*)(&Bs[wr * 64 + wc]) = *(const float4*)(W1 + (size_t)(kk + wr) * 64 + wc);
        __syncthreads();
#pragma unroll
        for (int k = 0; k < 16; k++) {
            unsigned long long a2[16], b2v[2];
#pragma unroll
            for (int i = 0; i < 16; i++) {
                float av = As[k * 256 + ty * 16 + i];
                a2[i] = pk2(av, av);
            }
#pragma unroll
            for (int j = 0; j < 2; j++) {
                float2 bv = *(const float2*)(&Bs[k * 64 + tx * 4 + j * 2]);
                b2v[j] = pk2(bv.x, bv.y);
            }
#pragma unroll
            for (int i = 0; i < 16; i++) {
                acc2[i][0] = ffma2(a2[i], b2v[0], acc2[i][0]);
                acc2[i][1] = ffma2(a2[i], b2v[1], acc2[i][1]);
            }
        }
        __syncthreads();
    }
    float4 b1v = *(const float4*)(b1 + tx * 4);
#pragma unroll
    for (int i = 0; i < 16; i++) {
        int rl = ty * 16 + i;
        float2 p0 = upk2(acc2[i][0]);
        float2 p1 = upk2(acc2[i][1]);
        float hx = fmaxf(p0.x + b1v.x, 0.f);
        float hy = fmaxf(p0.y + b1v.y, 0.f);
        float hz = fmaxf(p1.x + b1v.z, 0.f);
        float hw = fmaxf(p1.y + b1v.w, 0.f);
        *(__half2*)(sHid + rl * 66 + tx * 4)     = __floats2half2_rn(hx, hy);
        *(__half2*)(sHid + rl * 66 + tx * 4 + 2) = __floats2half2_rn(hz, hw);
    }
    __syncthreads();

    // mlp2: each thread one row
    int node = m0 + t;
    if (node >= M) return;
    float acc[OUTC];
#pragma unroll
    for (int j = 0; j < OUTC; j++) acc[j] = sb2[j];
#pragma unroll 4
    for (int k = 0; k < HIDD; k++) {
        float xv = __half2float(sHid[t * 66 + k]);
        const float4* wrow = (const float4*)(sW2 + k * OUTC);
#pragma unroll
        for (int j4 = 0; j4 < OUTC / 4; j4++) {
            float4 w = wrow[j4];
            acc[j4 * 4 + 0] = fmaf(xv, w.x, acc[j4 * 4 + 0]);
            acc[j4 * 4 + 1] = fmaf(xv, w.y, acc[j4 * 4 + 1]);
            acc[j4 * 4 + 2] = fmaf(xv, w.z, acc[j4 * 4 + 2]);
            acc[j4 * 4 + 3] = fmaf(xv, w.w, acc[j4 * 4 + 3]);
        }
    }
    float4* orow = (float4*)(out + (size_t)node * OUTC);
#pragma unroll
    for (int j4 = 0; j4 < OUTC / 4; j4++)
        orow[j4] = make_float4(acc[j4 * 4 + 0], acc[j4 * 4 + 1],
                               acc[j4 * 4 + 2], acc[j4 * 4 + 3]);
}

// ---------------- launch ----------------
extern "C" void kernel_launch(void* const* d_in, const int* in_sizes, int n_in,
                              void* d_out, int out_size) {
    const float* x         = (const float*)d_in[0];
    const int*   ei        = (const int*)d_in[1];      // int32
    const float* W         = (const float*)d_in[2];
    const float* att_src   = (const float*)d_in[3];
    const float* att_dst   = (const float*)d_in[4];
    const float* bias_conv = (const float*)d_in[5];
    const float* W1        = (const float*)d_in[6];
    const float* b1        = (const float*)d_in[7];
    const float* W2        = (const float*)d_in[8];
    const float* b2        = (const float*)d_in[9];
    float*       out       = (float*)d_out;

    int Nn = in_sizes[0] / INC;
    int E  = in_sizes[1] / 2;
    int ET = E + Nn;

    cudaFuncSetAttribute(gemm_mma_kernel,
                         cudaFuncAttributeMaxDynamicSharedMemorySize, GEMM_SMEM_BYTES);
    cudaFuncSetAttribute(mlp_kernel,
                         cudaFuncAttributeMaxDynamicSharedMemorySize, MLP_SMEM_BYTES);

    gnn_init_kernel<<<(Nn + 255) / 256, 256>>>(Nn);

    int t1 = Nn * 64; if (ET > t1) t1 = ET;
    convx_deg_kernel<<<(t1 + 255) / 256, 256>>>(x, ei, Nn, E, ET);
    convw_off_kernel<<<(256 * 256 + 255) / 256, 256>>>(W, Nn);

    dim3 gt((Nn + 127) / 128, 2);
    gemm_mma_kernel<<<gt, 512, GEMM_SMEM_BYTES>>>(att_src, att_dst, Nn);

    edge_fill_kernel<<<(ET + 255) / 256, 256>>>(ei, E, ET, Nn);

    agg_kernel<<<(Nn + 7) / 8, 256>>>(bias_conv, Nn);

    mlp_kernel<<<(Nn + 255) / 256, 256, MLP_SMEM_BYTES>>>(W1, b1, W2, b2, out, Nn);
}

// round 12
// speedup vs baseline: 3.8229x; 1.1230x over previous
#include <cuda_runtime.h>
#include <cuda_fp16.h>
#include <cstdint>
#include <math.h>

#define Hh   4
#define Cc   64
#define HC   256
#define INC  256
#define HIDD 64
#define OUTC 40
#define NEG  0.2f

#define N_MAX  50048
#define E_MAX  800000
#define ET_MAX (E_MAX + N_MAX)

// ---------------- static scratch ----------------
__device__ __align__(16) __half g_hh[(size_t)N_MAX * HC];    // h in fp16
__device__ __align__(16) __half g_agg[(size_t)N_MAX * HC];   // relu(agg/den+bias), fp16
__device__ float g_asrc[N_MAX * Hh];
__device__ float g_adst[N_MAX * Hh];
__device__ int   g_deg[N_MAX];
__device__ int   g_cnt[N_MAX];
__device__ int   g_off[N_MAX];
__device__ int   g_cursor;
__device__ int   g_csr_src[ET_MAX];
__device__ float g_ee[(size_t)ET_MAX * Hh];

// fp16 operands for tensor-core GEMM (x in fp16; W split hi/lo)
__device__ __align__(16) __half g_xhi[(size_t)N_MAX * 256];
__device__ __align__(16) __half g_bhi[256 * 256];   // B[n,k] = W[k,n]
__device__ __align__(16) __half g_blo[256 * 256];

__device__ __forceinline__ int clampi(int v, int n) {
    return (v < 0) ? 0 : ((v >= n) ? n - 1 : v);
}

// ---------------- packed fp32x2 helpers ----------------
__device__ __forceinline__ unsigned long long pk2(float lo, float hi) {
    unsigned long long r;
    asm("mov.b64 %0, {%1, %2};" : "=l"(r) : "f"(lo), "f"(hi));
    return r;
}
__device__ __forceinline__ float2 upk2(unsigned long long v) {
    float lo, hi;
    asm("mov.b64 {%0, %1}, %2;" : "=f"(lo), "=f"(hi) : "l"(v));
    return make_float2(lo, hi);
}
__device__ __forceinline__ unsigned long long ffma2(unsigned long long a,
                                                    unsigned long long b,
                                                    unsigned long long c) {
    unsigned long long d;
    asm("fma.rn.f32x2 %0, %1, %2, %3;" : "=l"(d) : "l"(a), "l"(b), "l"(c));
    return d;
}

// ---------------- warp-level fp16 MMA + ldmatrix ----------------
__device__ __forceinline__ void mma_f16(float* d, const uint32_t* a, const uint32_t* b) {
    asm volatile(
        "mma.sync.aligned.m16n8k16.row.col.f32.f16.f16.f32 "
        "{%0,%1,%2,%3}, {%4,%5,%6,%7}, {%8,%9}, {%0,%1,%2,%3};"
        : "+f"(d[0]), "+f"(d[1]), "+f"(d[2]), "+f"(d[3])
        : "r"(a[0]), "r"(a[1]), "r"(a[2]), "r"(a[3]), "r"(b[0]), "r"(b[1]));
}
__device__ __forceinline__ void ldsm_x4(uint32_t* r, uint32_t addr) {
    asm volatile("ldmatrix.sync.aligned.m8n8.x4.shared.b16 {%0,%1,%2,%3}, [%4];"
                 : "=r"(r[0]), "=r"(r[1]), "=r"(r[2]), "=r"(r[3]) : "r"(addr));
}

// ---------------- cp.async helpers ----------------
__device__ __forceinline__ uint32_t smem_u32(const void* p) {
    uint32_t a;
    asm("{ .reg .u64 t; cvta.to.shared.u64 t, %1; cvt.u32.u64 %0, t; }" : "=r"(a) : "l"(p));
    return a;
}
__device__ __forceinline__ void cpa16(uint32_t dst, const void* src, bool pred) {
    int sz = pred ? 16 : 0;
    asm volatile("cp.async.cg.shared.global [%0], [%1], 16, %2;"
                 :: "r"(dst), "l"(src), "r"(sz));
}
#define CPA_COMMIT() asm volatile("cp.async.commit_group;" ::: "memory")
#define CPA_WAIT(n)  asm volatile("cp.async.wait_group %0;" :: "n"(n) : "memory")

// ---------------- init ----------------
__global__ void gnn_init_kernel(int Nn) {
    int i = blockIdx.x * blockDim.x + threadIdx.x;
    if (i < Nn) { g_deg[i] = 0; g_cnt[i] = 0; }
    if (i == 0) g_cursor = 0;
}

// ---------------- fused: fp32->fp16 x  +  edge in-degree count ----------------
__global__ void convx_deg_kernel(const float* __restrict__ x,
                                 const int* __restrict__ ei,
                                 int Nn, int E, int ET) {
    int i = blockIdx.x * blockDim.x + threadIdx.x;
    int tot = Nn * 64;
    if (i < tot) {
        float4 v = ((const float4*)x)[i];
        __half2* ph = (__half2*)g_xhi;
        ph[i * 2 + 0] = __floats2half2_rn(v.x, v.y);
        ph[i * 2 + 1] = __floats2half2_rn(v.z, v.w);
    }
    if (i < ET) {
        int d = (i < E) ? clampi(ei[(size_t)E + i], Nn) : (i - E);
        atomicAdd(&g_deg[d], 1);
    }
}

// ---------------- fused: W[k,n] -> B[n,k] fp16 hi/lo  +  CSR offsets ----------------
__global__ void convw_off_kernel(const float* __restrict__ W, int Nn) {
    int idx = blockIdx.x * blockDim.x + threadIdx.x;
    if (idx < 256 * 256) {
        int n = idx & 255, k = idx >> 8;
        float w = W[k * 256 + n];
        __half h = __float2half_rn(w);
        __half l = __float2half_rn(w - __half2float(h));
        g_bhi[n * 256 + k] = h;
        g_blo[n * 256 + k] = l;
    }
    if (idx < Nn)
        g_off[idx] = atomicAdd(&g_cursor, g_deg[idx]);
}

// ---------------- tensor GEMM (2-term: x_hi*W_hi + x_hi*W_lo) + fused attention ----------------
#define APAD    72
#define TILE_EL (128 * APAD)
#define STAGE_EL (3 * TILE_EL)
#define GEMM_SMEM_BYTES (2 * STAGE_EL * 2)   // 110592

__global__ void __launch_bounds__(512, 1)
gemm_mma_kernel(const float* __restrict__ att_src,
                const float* __restrict__ att_dst, int Nn) {
    extern __shared__ __half sm[];
    int tid  = threadIdx.x;
    int wid  = tid >> 5;
    int lane = tid & 31;
    int gid  = lane >> 2;
    int tig  = lane & 3;
    int wm   = (wid & 3) * 32;
    int wn   = (wid >> 2) * 32;
    int m0 = blockIdx.x * 128;
    int n0 = blockIdx.y * 128;

    float acc[2][4][4];
#pragma unroll
    for (int mt = 0; mt < 2; mt++)
#pragma unroll
        for (int nt = 0; nt < 4; nt++)
#pragma unroll
            for (int q = 0; q < 4; q++) acc[mt][nt][q] = 0.f;

    uint32_t aoff = (uint32_t)((wm + ((lane >> 3) & 1) * 8 + (lane & 7)) * APAD
                               + (lane >> 4) * 8) * 2;
    uint32_t boff = (uint32_t)((wn + (lane >> 4) * 8 + (lane & 7)) * APAD
                               + ((lane >> 3) & 1) * 8) * 2;

    auto stage_load = [&](int st, int kk) {
        __half* base = sm + st * STAGE_EL;
        uint32_t sA   = smem_u32(base);
        uint32_t sBhi = sA + TILE_EL * 2;
        uint32_t sBlo = sA + 2 * TILE_EL * 2;
#pragma unroll
        for (int j0 = 0; j0 < 1024; j0 += 512) {
            int j = j0 + tid;
            int r = j >> 3, u = (j & 7) * 8;
            uint32_t so = (uint32_t)(r * APAD + u) * 2;
            bool am = (m0 + r) < Nn;
            size_t ga = (size_t)(m0 + r) * 256 + kk + u;
            size_t gb = (size_t)(n0 + r) * 256 + kk + u;
            cpa16(sA + so,   g_xhi + ga, am);
            cpa16(sBhi + so, g_bhi + gb, true);
            cpa16(sBlo + so, g_blo + gb, true);
        }
        CPA_COMMIT();
    };

    stage_load(0, 0);

    for (int c = 0; c < 4; c++) {
        if (c < 3) stage_load((c + 1) & 1, (c + 1) * 64);
        if (c < 3) { CPA_WAIT(1); } else { CPA_WAIT(0); }
        __syncthreads();

        uint32_t base = smem_u32(sm + (c & 1) * STAGE_EL);
        uint32_t aHi = base + aoff;
        uint32_t bHi = base + TILE_EL * 2 + boff;
        uint32_t bLo = base + 2 * TILE_EL * 2 + boff;

#pragma unroll
        for (int ks = 0; ks < 64; ks += 16) {
            uint32_t ahi[2][4], bhi[2][4], blo[2][4];
#pragma unroll
            for (int mt = 0; mt < 2; mt++) {
                uint32_t d = (uint32_t)(mt * 16 * APAD + ks) * 2;
                ldsm_x4(ahi[mt], aHi + d);
            }
#pragma unroll
            for (int p = 0; p < 2; p++) {
                uint32_t d = (uint32_t)(p * 16 * APAD + ks) * 2;
                ldsm_x4(bhi[p], bHi + d);
                ldsm_x4(blo[p], bLo + d);
            }
#pragma unroll
            for (int mt = 0; mt < 2; mt++)
#pragma unroll
                for (int nt = 0; nt < 4; nt++)
                    mma_f16(acc[mt][nt], ahi[mt], &bhi[nt >> 1][(nt & 1) * 2]);
#pragma unroll
            for (int mt = 0; mt < 2; mt++)
#pragma unroll
                for (int nt = 0; nt < 4; nt++)
                    mma_f16(acc[mt][nt], ahi[mt], &blo[nt >> 1][(nt & 1) * 2]);
        }
        __syncthreads();
    }

    // ---- epilogue 1: store h as fp16 ----
#pragma unroll
    for (int mt = 0; mt < 2; mt++) {
        int row = m0 + wm + mt * 16 + gid;
#pragma unroll
        for (int nt = 0; nt < 4; nt++) {
            int col = n0 + wn + nt * 8 + tig * 2;
            if (row < Nn)
                *(__half2*)(g_hh + (size_t)row * 256 + col) =
                    __floats2half2_rn(acc[mt][nt][0], acc[mt][nt][1]);
            if (row + 8 < Nn)
                *(__half2*)(g_hh + (size_t)(row + 8) * 256 + col) =
                    __floats2half2_rn(acc[mt][nt][2], acc[mt][nt][3]);
        }
    }

    // ---- epilogue 2: fused attention logits ----
    float* sA = (float*)sm;          // [128][2]
    float* sD = sA + 256;            // [128][2]
    if (tid < 256) { sA[tid] = 0.f; sD[tid] = 0.f; }
    __syncthreads();

    int lh = wn >> 6;                // local head 0/1 (warp-uniform)
    const float* ats = att_src + (blockIdx.y * 2 + lh) * 64;
    const float* atd = att_dst + (blockIdx.y * 2 + lh) * 64;

#pragma unroll
    for (int mt = 0; mt < 2; mt++) {
        float s0 = 0.f, d0 = 0.f, s1 = 0.f, d1 = 0.f;
#pragma unroll
        for (int nt = 0; nt < 4; nt++)
#pragma unroll
            for (int q = 0; q < 2; q++) {
                int cc = (wn & 63) + nt * 8 + tig * 2 + q;
                float ws = __ldg(ats + cc);
                float wd = __ldg(atd + cc);
                s0 = fmaf(acc[mt][nt][q], ws, s0);
                d0 = fmaf(acc[mt][nt][q], wd, d0);
                s1 = fmaf(acc[mt][nt][q + 2], ws, s1);
                d1 = fmaf(acc[mt][nt][q + 2], wd, d1);
            }
#pragma unroll
        for (int off = 1; off <= 2; off <<= 1) {
            s0 += __shfl_xor_sync(0xffffffffu, s0, off);
            d0 += __shfl_xor_sync(0xffffffffu, d0, off);
            s1 += __shfl_xor_sync(0xffffffffu, s1, off);
            d1 += __shfl_xor_sync(0xffffffffu, d1, off);
        }
        if (tig == 0) {
            int r0 = wm + mt * 16 + gid;
            atomicAdd(&sA[r0 * 2 + lh], s0);
            atomicAdd(&sD[r0 * 2 + lh], d0);
            atomicAdd(&sA[(r0 + 8) * 2 + lh], s1);
            atomicAdd(&sD[(r0 + 8) * 2 + lh], d1);
        }
    }
    __syncthreads();
    if (tid < 256) {
        int r = tid >> 1, h2 = tid & 1;
        int grow = m0 + r;
        if (grow < Nn) {
            int gh = blockIdx.y * 2 + h2;
            g_asrc[grow * 4 + gh] = sA[r * 2 + h2];
            g_adst[grow * 4 + gh] = sD[r * 2 + h2];
        }
    }
}

// ---------------- edge pass 2: exp(leaky(logit)) -> CSR slots ----------------
__global__ void edge_fill_kernel(const int* __restrict__ ei, int E, int ET, int Nn) {
    int e = blockIdx.x * blockDim.x + threadIdx.x;
    if (e >= ET) return;
    int s, d;
    if (e < E) { s = clampi(ei[e], Nn); d = clampi(ei[(size_t)E + e], Nn); }
    else       { s = d = e - E; }
    float4 as = *(const float4*)(g_asrc + (size_t)s * Hh);
    float4 ad = *(const float4*)(g_adst + (size_t)d * Hh);
    float v[4];
    v[0] = as.x + ad.x; v[1] = as.y + ad.y; v[2] = as.z + ad.z; v[3] = as.w + ad.w;
#pragma unroll
    for (int h = 0; h < 4; h++) {
        float lv = (v[h] > 0.f) ? v[h] : NEG * v[h];
        v[h] = __expf(lv);
    }
    int slot = g_off[d] + atomicAdd(&g_cnt[d], 1);
    g_csr_src[slot] = s;
    *(float4*)(g_ee + (size_t)slot * Hh) = make_float4(v[0], v[1], v[2], v[3]);
}

// ---------------- aggregation: 32 threads/node, fp16 gather, fp16 agg out ----------------
__global__ void agg_kernel(const float* __restrict__ bias_conv, int Nn) {
    int node = blockIdx.x * 8 + (threadIdx.x >> 5);
    int l    = threadIdx.x & 31;
    if (node >= Nn) return;
    int beg = g_off[node];
    int deg = g_deg[node];
    int hd  = l >> 3;

    float acc[8];
#pragma unroll
    for (int q = 0; q < 8; q++) acc[q] = 0.f;
    float den = 0.f;
#pragma unroll 2
    for (int i = 0; i < deg; i++) {
        int slot = beg + i;
        int s    = g_csr_src[slot];
        float a  = g_ee[(size_t)slot * Hh + hd];
        uint4 hv = *(const uint4*)(g_hh + (size_t)s * 256 + l * 8);
        __half2 p0 = *(__half2*)&hv.x, p1 = *(__half2*)&hv.y;
        __half2 p2 = *(__half2*)&hv.z, p3 = *(__half2*)&hv.w;
        float2 f0 = __half22float2(p0), f1 = __half22float2(p1);
        float2 f2 = __half22float2(p2), f3 = __half22float2(p3);
        den += a;
        acc[0] = fmaf(a, f0.x, acc[0]); acc[1] = fmaf(a, f0.y, acc[1]);
        acc[2] = fmaf(a, f1.x, acc[2]); acc[3] = fmaf(a, f1.y, acc[3]);
        acc[4] = fmaf(a, f2.x, acc[4]); acc[5] = fmaf(a, f2.y, acc[5]);
        acc[6] = fmaf(a, f3.x, acc[6]); acc[7] = fmaf(a, f3.y, acc[7]);
    }
    float r = 1.f / den;
    float4 b0 = *(const float4*)(bias_conv + l * 8);
    float4 b1 = *(const float4*)(bias_conv + l * 8 + 4);
    float o[8];
    o[0] = fmaxf(fmaf(acc[0], r, b0.x), 0.f);
    o[1] = fmaxf(fmaf(acc[1], r, b0.y), 0.f);
    o[2] = fmaxf(fmaf(acc[2], r, b0.z), 0.f);
    o[3] = fmaxf(fmaf(acc[3], r, b0.w), 0.f);
    o[4] = fmaxf(fmaf(acc[4], r, b1.x), 0.f);
    o[5] = fmaxf(fmaf(acc[5], r, b1.y), 0.f);
    o[6] = fmaxf(fmaf(acc[6], r, b1.z), 0.f);
    o[7] = fmaxf(fmaf(acc[7], r, b1.w), 0.f);
    uint4 ov;
    ((__half2*)&ov)[0] = __floats2half2_rn(o[0], o[1]);
    ((__half2*)&ov)[1] = __floats2half2_rn(o[2], o[3]);
    ((__half2*)&ov)[2] = __floats2half2_rn(o[4], o[5]);
    ((__half2*)&ov)[3] = __floats2half2_rn(o[6], o[7]);
    *(uint4*)(g_agg + (size_t)node * HC + l * 8) = ov;
}

// ---------------- fused MLP: out = relu(g_agg @ W1 + b1) @ W2 + b2 ----------------
#define MLP_SMEM_BYTES ((16 * 256 + 16 * 64 + 2560 + 40) * 4 + 256 * 66 * 2)  // 64672

__global__ void __launch_bounds__(256)
mlp_kernel(const float* __restrict__ W1, const float* __restrict__ b1,
           const float* __restrict__ W2, const float* __restrict__ b2,
           float* __restrict__ out, int M) {
    extern __shared__ char smc[];
    float*  As   = (float*)smc;                 // [16][256]
    float*  Bs   = As + 16 * 256;               // [16][64]
    float*  sW2  = Bs + 16 * 64;                // [64][40]
    float*  sb2  = sW2 + 2560;                  // [40]
    __half* sHid = (__half*)(sb2 + 40);         // [256][66]

    int t  = threadIdx.x;
    int tx = t & 15, ty = t >> 4;
    int m0 = blockIdx.x * 256;

    for (int i = t; i < 2560; i += 256) sW2[i] = W2[i];
    if (t < 40) sb2[t] = b2[t];

    unsigned long long acc2[16][2];
#pragma unroll
    for (int i = 0; i < 16; i++) { acc2[i][0] = 0ull; acc2[i][1] = 0ull; }

    int lr = t >> 2;
    int lc = (t & 3) << 2;
    int wr = t >> 4;
    int wc = (t & 15) << 2;

    for (int kk = 0; kk < 256; kk += 16) {
#pragma unroll
        for (int p = 0; p < 4; p++) {
            int row = lr + p * 64;
            uint2 hv = make_uint2(0u, 0u);
            if (m0 + row < M)
                hv = *(const uint2*)(g_agg + (size_t)(m0 + row) * 256 + kk + lc);
            float2 f01 = __half22float2(*(__half2*)&hv.x);
            float2 f23 = __half22float2(*(__half2*)&hv.y);
            As[(lc + 0) * 256 + row] = f01.x;
            As[(lc + 1) * 256 + row] = f01.y;
            As[(lc + 2) * 256 + row] = f23.x;
            As[(lc + 3) * 256 + row] = f23.y;
        }
        *(float4*)(&Bs[wr * 64 + wc]) = *(const float4*)(W1 + (size_t)(kk + wr) * 64 + wc);
        __syncthreads();
#pragma unroll
        for (int k = 0; k < 16; k++) {
            unsigned long long a2[16], b2v[2];
#pragma unroll
            for (int i = 0; i < 16; i++) {
                float av = As[k * 256 + ty * 16 + i];
                a2[i] = pk2(av, av);
            }
#pragma unroll
            for (int j = 0; j < 2; j++) {
                float2 bv = *(const float2*)(&Bs[k * 64 + tx * 4 + j * 2]);
                b2v[j] = pk2(bv.x, bv.y);
            }
#pragma unroll
            for (int i = 0; i < 16; i++) {
                acc2[i][0] = ffma2(a2[i], b2v[0], acc2[i][0]);
                acc2[i][1] = ffma2(a2[i], b2v[1], acc2[i][1]);
            }
        }
        __syncthreads();
    }
    float4 b1v = *(const float4*)(b1 + tx * 4);
#pragma unroll
    for (int i = 0; i < 16; i++) {
        int rl = ty * 16 + i;
        float2 p0 = upk2(acc2[i][0]);
        float2 p1 = upk2(acc2[i][1]);
        float hx = fmaxf(p0.x + b1v.x, 0.f);
        float hy = fmaxf(p0.y + b1v.y, 0.f);
        float hz = fmaxf(p1.x + b1v.z, 0.f);
        float hw = fmaxf(p1.y + b1v.w, 0.f);
        *(__half2*)(sHid + rl * 66 + tx * 4)     = __floats2half2_rn(hx, hy);
        *(__half2*)(sHid + rl * 66 + tx * 4 + 2) = __floats2half2_rn(hz, hw);
    }
    __syncthreads();

    // mlp2: each thread one row
    int node = m0 + t;
    if (node >= M) return;
    float acc[OUTC];
#pragma unroll
    for (int j = 0; j < OUTC; j++) acc[j] = sb2[j];
#pragma unroll 4
    for (int k = 0; k < HIDD; k++) {
        float xv = __half2float(sHid[t * 66 + k]);
        const float4* wrow = (const float4*)(sW2 + k * OUTC);
#pragma unroll
        for (int j4 = 0; j4 < OUTC / 4; j4++) {
            float4 w = wrow[j4];
            acc[j4 * 4 + 0] = fmaf(xv, w.x, acc[j4 * 4 + 0]);
            acc[j4 * 4 + 1] = fmaf(xv, w.y, acc[j4 * 4 + 1]);
            acc[j4 * 4 + 2] = fmaf(xv, w.z, acc[j4 * 4 + 2]);
            acc[j4 * 4 + 3] = fmaf(xv, w.w, acc[j4 * 4 + 3]);
        }
    }
    float4* orow = (float4*)(out + (size_t)node * OUTC);
#pragma unroll
    for (int j4 = 0; j4 < OUTC / 4; j4++)
        orow[j4] = make_float4(acc[j4 * 4 + 0], acc[j4 * 4 + 1],
                               acc[j4 * 4 + 2], acc[j4 * 4 + 3]);
}

// ---------------- launch ----------------
extern "C" void kernel_launch(void* const* d_in, const int* in_sizes, int n_in,
                              void* d_out, int out_size) {
    const float* x         = (const float*)d_in[0];
    const int*   ei        = (const int*)d_in[1];      // int32
    const float* W         = (const float*)d_in[2];
    const float* att_src   = (const float*)d_in[3];
    const float* att_dst   = (const float*)d_in[4];
    const float* bias_conv = (const float*)d_in[5];
    const float* W1        = (const float*)d_in[6];
    const float* b1        = (const float*)d_in[7];
    const float* W2        = (const float*)d_in[8];
    const float* b2        = (const float*)d_in[9];
    float*       out       = (float*)d_out;

    int Nn = in_sizes[0] / INC;
    int E  = in_sizes[1] / 2;
    int ET = E + Nn;

    cudaFuncSetAttribute(gemm_mma_kernel,
                         cudaFuncAttributeMaxDynamicSharedMemorySize, GEMM_SMEM_BYTES);
    cudaFuncSetAttribute(mlp_kernel,
                         cudaFuncAttributeMaxDynamicSharedMemorySize, MLP_SMEM_BYTES);

    gnn_init_kernel<<<(Nn + 255) / 256, 256>>>(Nn);

    int t1 = Nn * 64; if (ET > t1) t1 = ET;
    convx_deg_kernel<<<(t1 + 255) / 256, 256>>>(x, ei, Nn, E, ET);
    convw_off_kernel<<<(256 * 256 + 255) / 256, 256>>>(W, Nn);

    dim3 gt((Nn + 127) / 128, 2);
    gemm_mma_kernel<<<gt, 512, GEMM_SMEM_BYTES>>>(att_src, att_dst, Nn);

    edge_fill_kernel<<<(ET + 255) / 256, 256>>>(ei, E, ET, Nn);

    agg_kernel<<<(Nn + 7) / 8, 256>>>(bias_conv, Nn);

    mlp_kernel<<<(Nn + 255) / 256, 256, MLP_SMEM_BYTES>>>(W1, b1, W2, b2, out, Nn);
}

// round 13
// speedup vs baseline: 4.0946x; 1.0711x over previous
#include <cuda_runtime.h>
#include <cuda_fp16.h>
#include <cstdint>
#include <math.h>

#define Hh   4
#define Cc   64
#define HC   256
#define INC  256
#define HIDD 64
#define OUTC 40
#define NEG  0.2f

#define N_MAX  50048
#define E_MAX  800000
#define ET_MAX (E_MAX + N_MAX)

// ---------------- static scratch ----------------
__device__ __align__(16) __half g_hh[(size_t)N_MAX * HC];    // h in fp16
__device__ __align__(16) __half g_agg[(size_t)N_MAX * HC];   // relu(agg/den+bias), fp16
__device__ float g_asrc[N_MAX * Hh];
__device__ float g_adst[N_MAX * Hh];
__device__ int   g_deg[N_MAX];
__device__ int   g_cnt[N_MAX];
__device__ int   g_off[N_MAX];
__device__ int   g_cursor;
__device__ int   g_csr_src[ET_MAX];
__device__ float g_ee[(size_t)ET_MAX * Hh];

// fp16 operands for tensor-core GEMM
__device__ __align__(16) __half g_xhi[(size_t)N_MAX * 256];
__device__ __align__(16) __half g_bhi[256 * 256];   // B[n,k] = W[k,n]

__device__ __forceinline__ int clampi(int v, int n) {
    return (v < 0) ? 0 : ((v >= n) ? n - 1 : v);
}

// ---------------- packed fp32x2 helpers ----------------
__device__ __forceinline__ unsigned long long pk2(float lo, float hi) {
    unsigned long long r;
    asm("mov.b64 %0, {%1, %2};" : "=l"(r) : "f"(lo), "f"(hi));
    return r;
}
__device__ __forceinline__ float2 upk2(unsigned long long v) {
    float lo, hi;
    asm("mov.b64 {%0, %1}, %2;" : "=f"(lo), "=f"(hi) : "l"(v));
    return make_float2(lo, hi);
}
__device__ __forceinline__ unsigned long long ffma2(unsigned long long a,
                                                    unsigned long long b,
                                                    unsigned long long c) {
    unsigned long long d;
    asm("fma.rn.f32x2 %0, %1, %2, %3;" : "=l"(d) : "l"(a), "l"(b), "l"(c));
    return d;
}

// ---------------- warp-level fp16 MMA + ldmatrix ----------------
__device__ __forceinline__ void mma_f16(float* d, const uint32_t* a, const uint32_t* b) {
    asm volatile(
        "mma.sync.aligned.m16n8k16.row.col.f32.f16.f16.f32 "
        "{%0,%1,%2,%3}, {%4,%5,%6,%7}, {%8,%9}, {%0,%1,%2,%3};"
        : "+f"(d[0]), "+f"(d[1]), "+f"(d[2]), "+f"(d[3])
        : "r"(a[0]), "r"(a[1]), "r"(a[2]), "r"(a[3]), "r"(b[0]), "r"(b[1]));
}
__device__ __forceinline__ void ldsm_x4(uint32_t* r, uint32_t addr) {
    asm volatile("ldmatrix.sync.aligned.m8n8.x4.shared.b16 {%0,%1,%2,%3}, [%4];"
                 : "=r"(r[0]), "=r"(r[1]), "=r"(r[2]), "=r"(r[3]) : "r"(addr));
}

// ---------------- cp.async helpers ----------------
__device__ __forceinline__ uint32_t smem_u32(const void* p) {
    uint32_t a;
    asm("{ .reg .u64 t; cvta.to.shared.u64 t, %1; cvt.u32.u64 %0, t; }" : "=r"(a) : "l"(p));
    return a;
}
__device__ __forceinline__ void cpa16(uint32_t dst, const void* src, bool pred) {
    int sz = pred ? 16 : 0;
    asm volatile("cp.async.cg.shared.global [%0], [%1], 16, %2;"
                 :: "r"(dst), "l"(src), "r"(sz));
}
#define CPA_COMMIT() asm volatile("cp.async.commit_group;" ::: "memory")
#define CPA_WAIT(n)  asm volatile("cp.async.wait_group %0;" :: "n"(n) : "memory")

// ---------------- init ----------------
__global__ void gnn_init_kernel(int Nn) {
    int i = blockIdx.x * blockDim.x + threadIdx.x;
    if (i < Nn) { g_deg[i] = 0; g_cnt[i] = 0; }
    if (i == 0) g_cursor = 0;
}

// ---------------- fused: fp32->fp16 x  +  edge in-degree count ----------------
__global__ void convx_deg_kernel(const float* __restrict__ x,
                                 const int* __restrict__ ei,
                                 int Nn, int E, int ET) {
    int i = blockIdx.x * blockDim.x + threadIdx.x;
    int tot = Nn * 64;
    if (i < tot) {
        float4 v = ((const float4*)x)[i];
        __half2* ph = (__half2*)g_xhi;
        ph[i * 2 + 0] = __floats2half2_rn(v.x, v.y);
        ph[i * 2 + 1] = __floats2half2_rn(v.z, v.w);
    }
    if (i < ET) {
        int d = (i < E) ? clampi(ei[(size_t)E + i], Nn) : (i - E);
        atomicAdd(&g_deg[d], 1);
    }
}

// ---------------- fused: W[k,n] -> B[n,k] fp16  +  CSR offsets ----------------
__global__ void convw_off_kernel(const float* __restrict__ W, int Nn) {
    int idx = blockIdx.x * blockDim.x + threadIdx.x;
    if (idx < 256 * 256) {
        int n = idx & 255, k = idx >> 8;
        g_bhi[n * 256 + k] = __float2half_rn(W[k * 256 + n]);
    }
    if (idx < Nn)
        g_off[idx] = atomicAdd(&g_cursor, g_deg[idx]);
}

// ---------------- tensor GEMM (1-term fp16) + fused attention epilogue ----------------
#define APAD    72
#define TILE_EL (128 * APAD)
#define STAGE_EL (2 * TILE_EL)
#define GEMM_SMEM_BYTES (2 * STAGE_EL * 2)   // 73728

__global__ void __launch_bounds__(512, 1)
gemm_mma_kernel(const float* __restrict__ att_src,
                const float* __restrict__ att_dst, int Nn) {
    extern __shared__ __half sm[];
    int tid  = threadIdx.x;
    int wid  = tid >> 5;
    int lane = tid & 31;
    int gid  = lane >> 2;
    int tig  = lane & 3;
    int wm   = (wid & 3) * 32;
    int wn   = (wid >> 2) * 32;
    int m0 = blockIdx.x * 128;
    int n0 = blockIdx.y * 128;

    float acc[2][4][4];
#pragma unroll
    for (int mt = 0; mt < 2; mt++)
#pragma unroll
        for (int nt = 0; nt < 4; nt++)
#pragma unroll
            for (int q = 0; q < 4; q++) acc[mt][nt][q] = 0.f;

    uint32_t aoff = (uint32_t)((wm + ((lane >> 3) & 1) * 8 + (lane & 7)) * APAD
                               + (lane >> 4) * 8) * 2;
    uint32_t boff = (uint32_t)((wn + (lane >> 4) * 8 + (lane & 7)) * APAD
                               + ((lane >> 3) & 1) * 8) * 2;

    auto stage_load = [&](int st, int kk) {
        __half* base = sm + st * STAGE_EL;
        uint32_t sA = smem_u32(base);
        uint32_t sB = sA + TILE_EL * 2;
#pragma unroll
        for (int j0 = 0; j0 < 1024; j0 += 512) {
            int j = j0 + tid;
            int r = j >> 3, u = (j & 7) * 8;
            uint32_t so = (uint32_t)(r * APAD + u) * 2;
            bool am = (m0 + r) < Nn;
            size_t ga = (size_t)(m0 + r) * 256 + kk + u;
            size_t gb = (size_t)(n0 + r) * 256 + kk + u;
            cpa16(sA + so, g_xhi + ga, am);
            cpa16(sB + so, g_bhi + gb, true);
        }
        CPA_COMMIT();
    };

    stage_load(0, 0);

    for (int c = 0; c < 4; c++) {
        if (c < 3) stage_load((c + 1) & 1, (c + 1) * 64);
        if (c < 3) { CPA_WAIT(1); } else { CPA_WAIT(0); }
        __syncthreads();

        uint32_t base = smem_u32(sm + (c & 1) * STAGE_EL);
        uint32_t aHi = base + aoff;
        uint32_t bHi = base + TILE_EL * 2 + boff;

#pragma unroll
        for (int ks = 0; ks < 64; ks += 16) {
            uint32_t ahi[2][4], bhi[2][4];
#pragma unroll
            for (int mt = 0; mt < 2; mt++) {
                uint32_t d = (uint32_t)(mt * 16 * APAD + ks) * 2;
                ldsm_x4(ahi[mt], aHi + d);
            }
#pragma unroll
            for (int p = 0; p < 2; p++) {
                uint32_t d = (uint32_t)(p * 16 * APAD + ks) * 2;
                ldsm_x4(bhi[p], bHi + d);
            }
#pragma unroll
            for (int mt = 0; mt < 2; mt++)
#pragma unroll
                for (int nt = 0; nt < 4; nt++)
                    mma_f16(acc[mt][nt], ahi[mt], &bhi[nt >> 1][(nt & 1) * 2]);
        }
        __syncthreads();
    }

    // ---- epilogue 1: store h as fp16 ----
#pragma unroll
    for (int mt = 0; mt < 2; mt++) {
        int row = m0 + wm + mt * 16 + gid;
#pragma unroll
        for (int nt = 0; nt < 4; nt++) {
            int col = n0 + wn + nt * 8 + tig * 2;
            if (row < Nn)
                *(__half2*)(g_hh + (size_t)row * 256 + col) =
                    __floats2half2_rn(acc[mt][nt][0], acc[mt][nt][1]);
            if (row + 8 < Nn)
                *(__half2*)(g_hh + (size_t)(row + 8) * 256 + col) =
                    __floats2half2_rn(acc[mt][nt][2], acc[mt][nt][3]);
        }
    }

    // ---- epilogue 2: fused attention logits ----
    float* sA = (float*)sm;          // [128][2]
    float* sD = sA + 256;            // [128][2]
    if (tid < 256) { sA[tid] = 0.f; sD[tid] = 0.f; }
    __syncthreads();

    int lh = wn >> 6;                // local head 0/1 (warp-uniform)
    const float* ats = att_src + (blockIdx.y * 2 + lh) * 64;
    const float* atd = att_dst + (blockIdx.y * 2 + lh) * 64;

#pragma unroll
    for (int mt = 0; mt < 2; mt++) {
        float s0 = 0.f, d0 = 0.f, s1 = 0.f, d1 = 0.f;
#pragma unroll
        for (int nt = 0; nt < 4; nt++)
#pragma unroll
            for (int q = 0; q < 2; q++) {
                int cc = (wn & 63) + nt * 8 + tig * 2 + q;
                float ws = __ldg(ats + cc);
                float wd = __ldg(atd + cc);
                s0 = fmaf(acc[mt][nt][q], ws, s0);
                d0 = fmaf(acc[mt][nt][q], wd, d0);
                s1 = fmaf(acc[mt][nt][q + 2], ws, s1);
                d1 = fmaf(acc[mt][nt][q + 2], wd, d1);
            }
#pragma unroll
        for (int off = 1; off <= 2; off <<= 1) {
            s0 += __shfl_xor_sync(0xffffffffu, s0, off);
            d0 += __shfl_xor_sync(0xffffffffu, d0, off);
            s1 += __shfl_xor_sync(0xffffffffu, s1, off);
            d1 += __shfl_xor_sync(0xffffffffu, d1, off);
        }
        if (tig == 0) {
            int r0 = wm + mt * 16 + gid;
            atomicAdd(&sA[r0 * 2 + lh], s0);
            atomicAdd(&sD[r0 * 2 + lh], d0);
            atomicAdd(&sA[(r0 + 8) * 2 + lh], s1);
            atomicAdd(&sD[(r0 + 8) * 2 + lh], d1);
        }
    }
    __syncthreads();
    if (tid < 256) {
        int r = tid >> 1, h2 = tid & 1;
        int grow = m0 + r;
        if (grow < Nn) {
            int gh = blockIdx.y * 2 + h2;
            g_asrc[grow * 4 + gh] = sA[r * 2 + h2];
            g_adst[grow * 4 + gh] = sD[r * 2 + h2];
        }
    }
}

// ---------------- edge pass 2: exp(leaky(logit)) -> CSR slots ----------------
__global__ void edge_fill_kernel(const int* __restrict__ ei, int E, int ET, int Nn) {
    int e = blockIdx.x * blockDim.x + threadIdx.x;
    if (e >= ET) return;
    int s, d;
    if (e < E) { s = clampi(ei[e], Nn); d = clampi(ei[(size_t)E + e], Nn); }
    else       { s = d = e - E; }
    float4 as = *(const float4*)(g_asrc + (size_t)s * Hh);
    float4 ad = *(const float4*)(g_adst + (size_t)d * Hh);
    float v[4];
    v[0] = as.x + ad.x; v[1] = as.y + ad.y; v[2] = as.z + ad.z; v[3] = as.w + ad.w;
#pragma unroll
    for (int h = 0; h < 4; h++) {
        float lv = (v[h] > 0.f) ? v[h] : NEG * v[h];
        v[h] = __expf(lv);
    }
    int slot = g_off[d] + atomicAdd(&g_cnt[d], 1);
    g_csr_src[slot] = s;
    *(float4*)(g_ee + (size_t)slot * Hh) = make_float4(v[0], v[1], v[2], v[3]);
}

// ---------------- aggregation: 32 threads/node, fp16 gather, fp16 agg out ----------------
__global__ void agg_kernel(const float* __restrict__ bias_conv, int Nn) {
    int node = blockIdx.x * 8 + (threadIdx.x >> 5);
    int l    = threadIdx.x & 31;
    if (node >= Nn) return;
    int beg = g_off[node];
    int deg = g_deg[node];
    int hd  = l >> 3;

    float acc[8];
#pragma unroll
    for (int q = 0; q < 8; q++) acc[q] = 0.f;
    float den = 0.f;
#pragma unroll 2
    for (int i = 0; i < deg; i++) {
        int slot = beg + i;
        int s    = g_csr_src[slot];
        float a  = g_ee[(size_t)slot * Hh + hd];
        uint4 hv = *(const uint4*)(g_hh + (size_t)s * 256 + l * 8);
        __half2 p0 = *(__half2*)&hv.x, p1 = *(__half2*)&hv.y;
        __half2 p2 = *(__half2*)&hv.z, p3 = *(__half2*)&hv.w;
        float2 f0 = __half22float2(p0), f1 = __half22float2(p1);
        float2 f2 = __half22float2(p2), f3 = __half22float2(p3);
        den += a;
        acc[0] = fmaf(a, f0.x, acc[0]); acc[1] = fmaf(a, f0.y, acc[1]);
        acc[2] = fmaf(a, f1.x, acc[2]); acc[3] = fmaf(a, f1.y, acc[3]);
        acc[4] = fmaf(a, f2.x, acc[4]); acc[5] = fmaf(a, f2.y, acc[5]);
        acc[6] = fmaf(a, f3.x, acc[6]); acc[7] = fmaf(a, f3.y, acc[7]);
    }
    float r = 1.f / den;
    float4 b0 = *(const float4*)(bias_conv + l * 8);
    float4 b1 = *(const float4*)(bias_conv + l * 8 + 4);
    float o[8];
    o[0] = fmaxf(fmaf(acc[0], r, b0.x), 0.f);
    o[1] = fmaxf(fmaf(acc[1], r, b0.y), 0.f);
    o[2] = fmaxf(fmaf(acc[2], r, b0.z), 0.f);
    o[3] = fmaxf(fmaf(acc[3], r, b0.w), 0.f);
    o[4] = fmaxf(fmaf(acc[4], r, b1.x), 0.f);
    o[5] = fmaxf(fmaf(acc[5], r, b1.y), 0.f);
    o[6] = fmaxf(fmaf(acc[6], r, b1.z), 0.f);
    o[7] = fmaxf(fmaf(acc[7], r, b1.w), 0.f);
    uint4 ov;
    ((__half2*)&ov)[0] = __floats2half2_rn(o[0], o[1]);
    ((__half2*)&ov)[1] = __floats2half2_rn(o[2], o[3]);
    ((__half2*)&ov)[2] = __floats2half2_rn(o[4], o[5]);
    ((__half2*)&ov)[3] = __floats2half2_rn(o[6], o[7]);
    *(uint4*)(g_agg + (size_t)node * HC + l * 8) = ov;
}

// ---------------- fused MLP: out = relu(g_agg @ W1 + b1) @ W2 + b2 ----------------
#define MLP_SMEM_BYTES ((16 * 256 + 16 * 64 + 2560 + 40) * 4 + 256 * 66 * 2)  // 64672

__global__ void __launch_bounds__(256)
mlp_kernel(const float* __restrict__ W1, const float* __restrict__ b1,
           const float* __restrict__ W2, const float* __restrict__ b2,
           float* __restrict__ out, int M) {
    extern __shared__ char smc[];
    float*  As   = (float*)smc;                 // [16][256]
    float*  Bs   = As + 16 * 256;               // [16][64]
    float*  sW2  = Bs + 16 * 64;                // [64][40]
    float*  sb2  = sW2 + 2560;                  // [40]
    __half* sHid = (__half*)(sb2 + 40);         // [256][66]

    int t  = threadIdx.x;
    int tx = t & 15, ty = t >> 4;
    int m0 = blockIdx.x * 256;

    for (int i = t; i < 2560; i += 256) sW2[i] = W2[i];
    if (t < 40) sb2[t] = b2[t];

    unsigned long long acc2[16][2];
#pragma unroll
    for (int i = 0; i < 16; i++) { acc2[i][0] = 0ull; acc2[i][1] = 0ull; }

    int lr = t >> 2;
    int lc = (t & 3) << 2;
    int wr = t >> 4;
    int wc = (t & 15) << 2;

    for (int kk = 0; kk < 256; kk += 16) {
#pragma unroll
        for (int p = 0; p < 4; p++) {
            int row = lr + p * 64;
            uint2 hv = make_uint2(0u, 0u);
            if (m0 + row < M)
                hv = *(const uint2*)(g_agg + (size_t)(m0 + row) * 256 + kk + lc);
            float2 f01 = __half22float2(*(__half2*)&hv.x);
            float2 f23 = __half22float2(*(__half2*)&hv.y);
            As[(lc + 0) * 256 + row] = f01.x;
            As[(lc + 1) * 256 + row] = f01.y;
            As[(lc + 2) * 256 + row] = f23.x;
            As[(lc + 3) * 256 + row] = f23.y;
        }
        *(float4*)(&Bs[wr * 64 + wc]) = *(const float4*)(W1 + (size_t)(kk + wr) * 64 + wc);
        __syncthreads();
#pragma unroll
        for (int k = 0; k < 16; k++) {
            unsigned long long a2[16], b2v[2];
#pragma unroll
            for (int i = 0; i < 16; i++) {
                float av = As[k * 256 + ty * 16 + i];
                a2[i] = pk2(av, av);
            }
#pragma unroll
            for (int j = 0; j < 2; j++) {
                float2 bv = *(const float2*)(&Bs[k * 64 + tx * 4 + j * 2]);
                b2v[j] = pk2(bv.x, bv.y);
            }
#pragma unroll
            for (int i = 0; i < 16; i++) {
                acc2[i][0] = ffma2(a2[i], b2v[0], acc2[i][0]);
                acc2[i][1] = ffma2(a2[i], b2v[1], acc2[i][1]);
            }
        }
        __syncthreads();
    }
    float4 b1v = *(const float4*)(b1 + tx * 4);
#pragma unroll
    for (int i = 0; i < 16; i++) {
        int rl = ty * 16 + i;
        float2 p0 = upk2(acc2[i][0]);
        float2 p1 = upk2(acc2[i][1]);
        float hx = fmaxf(p0.x + b1v.x, 0.f);
        float hy = fmaxf(p0.y + b1v.y, 0.f);
        float hz = fmaxf(p1.x + b1v.z, 0.f);
        float hw = fmaxf(p1.y + b1v.w, 0.f);
        *(__half2*)(sHid + rl * 66 + tx * 4)     = __floats2half2_rn(hx, hy);
        *(__half2*)(sHid + rl * 66 + tx * 4 + 2) = __floats2half2_rn(hz, hw);
    }
    __syncthreads();

    // mlp2: each thread one row
    int node = m0 + t;
    if (node >= M) return;
    float acc[OUTC];
#pragma unroll
    for (int j = 0; j < OUTC; j++) acc[j] = sb2[j];
#pragma unroll 4
    for (int k = 0; k < HIDD; k++) {
        float xv = __half2float(sHid[t * 66 + k]);
        const float4* wrow = (const float4*)(sW2 + k * OUTC);
#pragma unroll
        for (int j4 = 0; j4 < OUTC / 4; j4++) {
            float4 w = wrow[j4];
            acc[j4 * 4 + 0] = fmaf(xv, w.x, acc[j4 * 4 + 0]);
            acc[j4 * 4 + 1] = fmaf(xv, w.y, acc[j4 * 4 + 1]);
            acc[j4 * 4 + 2] = fmaf(xv, w.z, acc[j4 * 4 + 2]);
            acc[j4 * 4 + 3] = fmaf(xv, w.w, acc[j4 * 4 + 3]);
        }
    }
    float4* orow = (float4*)(out + (size_t)node * OUTC);
#pragma unroll
    for (int j4 = 0; j4 < OUTC / 4; j4++)
        orow[j4] = make_float4(acc[j4 * 4 + 0], acc[j4 * 4 + 1],
                               acc[j4 * 4 + 2], acc[j4 * 4 + 3]);
}

// ---------------- launch ----------------
extern "C" void kernel_launch(void* const* d_in, const int* in_sizes, int n_in,
                              void* d_out, int out_size) {
    const float* x         = (const float*)d_in[0];
    const int*   ei        = (const int*)d_in[1];      // int32
    const float* W         = (const float*)d_in[2];
    const float* att_src   = (const float*)d_in[3];
    const float* att_dst   = (const float*)d_in[4];
    const float* bias_conv = (const float*)d_in[5];
    const float* W1        = (const float*)d_in[6];
    const float* b1        = (const float*)d_in[7];
    const float* W2        = (const float*)d_in[8];
    const float* b2        = (const float*)d_in[9];
    float*       out       = (float*)d_out;

    int Nn = in_sizes[0] / INC;
    int E  = in_sizes[1] / 2;
    int ET = E + Nn;

    cudaFuncSetAttribute(gemm_mma_kernel,
                         cudaFuncAttributeMaxDynamicSharedMemorySize, GEMM_SMEM_BYTES);
    cudaFuncSetAttribute(mlp_kernel,
                         cudaFuncAttributeMaxDynamicSharedMemorySize, MLP_SMEM_BYTES);

    gnn_init_kernel<<<(Nn + 255) / 256, 256>>>(Nn);

    int t1 = Nn * 64; if (ET > t1) t1 = ET;
    convx_deg_kernel<<<(t1 + 255) / 256, 256>>>(x, ei, Nn, E, ET);
    convw_off_kernel<<<(256 * 256 + 255) / 256, 256>>>(W, Nn);

    dim3 gt((Nn + 127) / 128, 2);
    gemm_mma_kernel<<<gt, 512, GEMM_SMEM_BYTES>>>(att_src, att_dst, Nn);

    edge_fill_kernel<<<(ET + 255) / 256, 256>>>(ei, E, ET, Nn);

    agg_kernel<<<(Nn + 7) / 8, 256>>>(bias_conv, Nn);

    mlp_kernel<<<(Nn + 255) / 256, 256, MLP_SMEM_BYTES>>>(W1, b1, W2, b2, out, Nn);
}

// round 14
// speedup vs baseline: 5.3229x; 1.3000x over previous
#include <cuda_runtime.h>
#include <cuda_fp16.h>
#include <cstdint>
#include <math.h>

#define Hh   4
#define Cc   64
#define HC   256
#define INC  256
#define HIDD 64
#define OUTC 40
#define NEG  0.2f

#define N_MAX  50048
#define E_MAX  800000
#define ET_MAX (E_MAX + N_MAX)

// ---------------- static scratch ----------------
__device__ __align__(16) __half g_hh[(size_t)N_MAX * HC];    // h in fp16
__device__ __align__(16) __half g_agg[(size_t)N_MAX * HC];   // relu(agg/den+bias), fp16
__device__ float g_asrc[N_MAX * Hh];
__device__ float g_adst[N_MAX * Hh];
__device__ int   g_deg[N_MAX];
__device__ int   g_cnt[N_MAX];
__device__ int   g_off[N_MAX];
__device__ int   g_cursor;
__device__ int   g_csr_src[ET_MAX];
__device__ __align__(16) __half g_eeh[(size_t)ET_MAX * Hh];  // exp(logit), fp16

// fp16 operands for tensor-core GEMMs
__device__ __align__(16) __half g_xhi[(size_t)N_MAX * 256];
__device__ __align__(16) __half g_bhi[256 * 256];            // B[n,k] = W[k,n]
__device__ __align__(16) __half g_w1hi[64 * 256];            // W1[k,n] -> [n,k] hi
__device__ __align__(16) __half g_w1lo[64 * 256];            // lo

__device__ __forceinline__ int clampi(int v, int n) {
    return (v < 0) ? 0 : ((v >= n) ? n - 1 : v);
}

// ---------------- packed fp32x2 helpers ----------------
__device__ __forceinline__ unsigned long long pk2(float lo, float hi) {
    unsigned long long r;
    asm("mov.b64 %0, {%1, %2};" : "=l"(r) : "f"(lo), "f"(hi));
    return r;
}
__device__ __forceinline__ float2 upk2(unsigned long long v) {
    float lo, hi;
    asm("mov.b64 {%0, %1}, %2;" : "=f"(lo), "=f"(hi) : "l"(v));
    return make_float2(lo, hi);
}
__device__ __forceinline__ unsigned long long ffma2(unsigned long long a,
                                                    unsigned long long b,
                                                    unsigned long long c) {
    unsigned long long d;
    asm("fma.rn.f32x2 %0, %1, %2, %3;" : "=l"(d) : "l"(a), "l"(b), "l"(c));
    return d;
}

// ---------------- warp-level fp16 MMA + ldmatrix ----------------
__device__ __forceinline__ void mma_f16(float* d, const uint32_t* a, const uint32_t* b) {
    asm volatile(
        "mma.sync.aligned.m16n8k16.row.col.f32.f16.f16.f32 "
        "{%0,%1,%2,%3}, {%4,%5,%6,%7}, {%8,%9}, {%0,%1,%2,%3};"
        : "+f"(d[0]), "+f"(d[1]), "+f"(d[2]), "+f"(d[3])
        : "r"(a[0]), "r"(a[1]), "r"(a[2]), "r"(a[3]), "r"(b[0]), "r"(b[1]));
}
__device__ __forceinline__ void ldsm_x4(uint32_t* r, uint32_t addr) {
    asm volatile("ldmatrix.sync.aligned.m8n8.x4.shared.b16 {%0,%1,%2,%3}, [%4];"
                 : "=r"(r[0]), "=r"(r[1]), "=r"(r[2]), "=r"(r[3]) : "r"(addr));
}

// ---------------- cp.async helpers ----------------
__device__ __forceinline__ uint32_t smem_u32(const void* p) {
    uint32_t a;
    asm("{ .reg .u64 t; cvta.to.shared.u64 t, %1; cvt.u32.u64 %0, t; }" : "=r"(a) : "l"(p));
    return a;
}
__device__ __forceinline__ void cpa16(uint32_t dst, const void* src, bool pred) {
    int sz = pred ? 16 : 0;
    asm volatile("cp.async.cg.shared.global [%0], [%1], 16, %2;"
                 :: "r"(dst), "l"(src), "r"(sz));
}
#define CPA_COMMIT() asm volatile("cp.async.commit_group;" ::: "memory")
#define CPA_WAIT(n)  asm volatile("cp.async.wait_group %0;" :: "n"(n) : "memory")

// ---------------- init ----------------
__global__ void gnn_init_kernel(int Nn) {
    int i = blockIdx.x * blockDim.x + threadIdx.x;
    if (i < Nn) { g_deg[i] = 0; g_cnt[i] = 0; }
    if (i == 0) g_cursor = 0;
}

// ---------------- fused: fp32->fp16 x  +  edge in-degree count ----------------
__global__ void convx_deg_kernel(const float* __restrict__ x,
                                 const int* __restrict__ ei,
                                 int Nn, int E, int ET) {
    int i = blockIdx.x * blockDim.x + threadIdx.x;
    int tot = Nn * 64;
    if (i < tot) {
        float4 v = ((const float4*)x)[i];
        __half2* ph = (__half2*)g_xhi;
        ph[i * 2 + 0] = __floats2half2_rn(v.x, v.y);
        ph[i * 2 + 1] = __floats2half2_rn(v.z, v.w);
    }
    if (i < ET) {
        int d = (i < E) ? clampi(ei[(size_t)E + i], Nn) : (i - E);
        atomicAdd(&g_deg[d], 1);
    }
}

// ---------------- fused: W -> bhi, W1 -> w1hi/lo, CSR offsets ----------------
__global__ void convw_off_kernel(const float* __restrict__ W,
                                 const float* __restrict__ W1, int Nn) {
    int idx = blockIdx.x * blockDim.x + threadIdx.x;
    if (idx < 256 * 256) {
        int n = idx & 255, k = idx >> 8;
        g_bhi[n * 256 + k] = __float2half_rn(W[k * 256 + n]);
    }
    if (idx < 64 * 256) {
        int n = idx & 63, k = idx >> 6;
        float w = W1[k * 64 + n];
        __half h = __float2half_rn(w);
        __half l = __float2half_rn(w - __half2float(h));
        g_w1hi[n * 256 + k] = h;
        g_w1lo[n * 256 + k] = l;
    }
    if (idx < Nn)
        g_off[idx] = atomicAdd(&g_cursor, g_deg[idx]);
}

// ---------------- tensor GEMM (1-term fp16) + fused attention epilogue ----------------
#define APAD    72
#define TILE_EL (128 * APAD)
#define STAGE_EL (2 * TILE_EL)
#define GEMM_SMEM_BYTES (2 * STAGE_EL * 2)   // 73728

__global__ void __launch_bounds__(512, 1)
gemm_mma_kernel(const float* __restrict__ att_src,
                const float* __restrict__ att_dst, int Nn) {
    extern __shared__ __half sm[];
    int tid  = threadIdx.x;
    int wid  = tid >> 5;
    int lane = tid & 31;
    int gid  = lane >> 2;
    int tig  = lane & 3;
    int wm   = (wid & 3) * 32;
    int wn   = (wid >> 2) * 32;
    int m0 = blockIdx.x * 128;
    int n0 = blockIdx.y * 128;

    float acc[2][4][4];
#pragma unroll
    for (int mt = 0; mt < 2; mt++)
#pragma unroll
        for (int nt = 0; nt < 4; nt++)
#pragma unroll
            for (int q = 0; q < 4; q++) acc[mt][nt][q] = 0.f;

    uint32_t aoff = (uint32_t)((wm + ((lane >> 3) & 1) * 8 + (lane & 7)) * APAD
                               + (lane >> 4) * 8) * 2;
    uint32_t boff = (uint32_t)((wn + (lane >> 4) * 8 + (lane & 7)) * APAD
                               + ((lane >> 3) & 1) * 8) * 2;

    auto stage_load = [&](int st, int kk) {
        __half* base = sm + st * STAGE_EL;
        uint32_t sA = smem_u32(base);
        uint32_t sB = sA + TILE_EL * 2;
#pragma unroll
        for (int j0 = 0; j0 < 1024; j0 += 512) {
            int j = j0 + tid;
            int r = j >> 3, u = (j & 7) * 8;
            uint32_t so = (uint32_t)(r * APAD + u) * 2;
            bool am = (m0 + r) < Nn;
            size_t ga = (size_t)(m0 + r) * 256 + kk + u;
            size_t gb = (size_t)(n0 + r) * 256 + kk + u;
            cpa16(sA + so, g_xhi + ga, am);
            cpa16(sB + so, g_bhi + gb, true);
        }
        CPA_COMMIT();
    };

    stage_load(0, 0);

    for (int c = 0; c < 4; c++) {
        if (c < 3) stage_load((c + 1) & 1, (c + 1) * 64);
        if (c < 3) { CPA_WAIT(1); } else { CPA_WAIT(0); }
        __syncthreads();

        uint32_t base = smem_u32(sm + (c & 1) * STAGE_EL);
        uint32_t aHi = base + aoff;
        uint32_t bHi = base + TILE_EL * 2 + boff;

#pragma unroll
        for (int ks = 0; ks < 64; ks += 16) {
            uint32_t ahi[2][4], bhi[2][4];
#pragma unroll
            for (int mt = 0; mt < 2; mt++) {
                uint32_t d = (uint32_t)(mt * 16 * APAD + ks) * 2;
                ldsm_x4(ahi[mt], aHi + d);
            }
#pragma unroll
            for (int p = 0; p < 2; p++) {
                uint32_t d = (uint32_t)(p * 16 * APAD + ks) * 2;
                ldsm_x4(bhi[p], bHi + d);
            }
#pragma unroll
            for (int mt = 0; mt < 2; mt++)
#pragma unroll
                for (int nt = 0; nt < 4; nt++)
                    mma_f16(acc[mt][nt], ahi[mt], &bhi[nt >> 1][(nt & 1) * 2]);
        }
        __syncthreads();
    }

    // ---- epilogue 1: store h as fp16 ----
#pragma unroll
    for (int mt = 0; mt < 2; mt++) {
        int row = m0 + wm + mt * 16 + gid;
#pragma unroll
        for (int nt = 0; nt < 4; nt++) {
            int col = n0 + wn + nt * 8 + tig * 2;
            if (row < Nn)
                *(__half2*)(g_hh + (size_t)row * 256 + col) =
                    __floats2half2_rn(acc[mt][nt][0], acc[mt][nt][1]);
            if (row + 8 < Nn)
                *(__half2*)(g_hh + (size_t)(row + 8) * 256 + col) =
                    __floats2half2_rn(acc[mt][nt][2], acc[mt][nt][3]);
        }
    }

    // ---- epilogue 2: fused attention logits ----
    float* sA = (float*)sm;          // [128][2]
    float* sD = sA + 256;            // [128][2]
    if (tid < 256) { sA[tid] = 0.f; sD[tid] = 0.f; }
    __syncthreads();

    int lh = wn >> 6;                // local head 0/1 (warp-uniform)
    const float* ats = att_src + (blockIdx.y * 2 + lh) * 64;
    const float* atd = att_dst + (blockIdx.y * 2 + lh) * 64;

#pragma unroll
    for (int mt = 0; mt < 2; mt++) {
        float s0 = 0.f, d0 = 0.f, s1 = 0.f, d1 = 0.f;
#pragma unroll
        for (int nt = 0; nt < 4; nt++)
#pragma unroll
            for (int q = 0; q < 2; q++) {
                int cc = (wn & 63) + nt * 8 + tig * 2 + q;
                float ws = __ldg(ats + cc);
                float wd = __ldg(atd + cc);
                s0 = fmaf(acc[mt][nt][q], ws, s0);
                d0 = fmaf(acc[mt][nt][q], wd, d0);
                s1 = fmaf(acc[mt][nt][q + 2], ws, s1);
                d1 = fmaf(acc[mt][nt][q + 2], wd, d1);
            }
#pragma unroll
        for (int off = 1; off <= 2; off <<= 1) {
            s0 += __shfl_xor_sync(0xffffffffu, s0, off);
            d0 += __shfl_xor_sync(0xffffffffu, d0, off);
            s1 += __shfl_xor_sync(0xffffffffu, s1, off);
            d1 += __shfl_xor_sync(0xffffffffu, d1, off);
        }
        if (tig == 0) {
            int r0 = wm + mt * 16 + gid;
            atomicAdd(&sA[r0 * 2 + lh], s0);
            atomicAdd(&sD[r0 * 2 + lh], d0);
            atomicAdd(&sA[(r0 + 8) * 2 + lh], s1);
            atomicAdd(&sD[(r0 + 8) * 2 + lh], d1);
        }
    }
    __syncthreads();
    if (tid < 256) {
        int r = tid >> 1, h2 = tid & 1;
        int grow = m0 + r;
        if (grow < Nn) {
            int gh = blockIdx.y * 2 + h2;
            g_asrc[grow * 4 + gh] = sA[r * 2 + h2];
            g_adst[grow * 4 + gh] = sD[r * 2 + h2];
        }
    }
}

// ---------------- edge pass: exp(leaky(logit)) -> CSR slots (fp16) ----------------
__global__ void edge_fill_kernel(const int* __restrict__ ei, int E, int ET, int Nn) {
    int e = blockIdx.x * blockDim.x + threadIdx.x;
    if (e >= ET) return;
    int s, d;
    if (e < E) { s = clampi(ei[e], Nn); d = clampi(ei[(size_t)E + e], Nn); }
    else       { s = d = e - E; }
    float4 as = *(const float4*)(g_asrc + (size_t)s * Hh);
    float4 ad = *(const float4*)(g_adst + (size_t)d * Hh);
    float v[4];
    v[0] = as.x + ad.x; v[1] = as.y + ad.y; v[2] = as.z + ad.z; v[3] = as.w + ad.w;
#pragma unroll
    for (int h = 0; h < 4; h++) {
        float lv = (v[h] > 0.f) ? v[h] : NEG * v[h];
        v[h] = __expf(lv);
    }
    int slot = g_off[d] + atomicAdd(&g_cnt[d], 1);
    g_csr_src[slot] = s;
    uint2 pv;
    *(__half2*)&pv.x = __floats2half2_rn(v[0], v[1]);
    *(__half2*)&pv.y = __floats2half2_rn(v[2], v[3]);
    *(uint2*)(g_eeh + (size_t)slot * Hh) = pv;
}

// ---------------- aggregation: 32 threads/node, fp16 gather/weights, fp16 out ----------------
__global__ void agg_kernel(const float* __restrict__ bias_conv, int Nn) {
    int node = blockIdx.x * 8 + (threadIdx.x >> 5);
    int l    = threadIdx.x & 31;
    if (node >= Nn) return;
    int beg = g_off[node];
    int deg = g_deg[node];
    int hd  = l >> 3;

    float acc[8];
#pragma unroll
    for (int q = 0; q < 8; q++) acc[q] = 0.f;
    float den = 0.f;
#pragma unroll 2
    for (int i = 0; i < deg; i++) {
        int slot = beg + i;
        int s    = g_csr_src[slot];
        float a  = __half2float(g_eeh[(size_t)slot * Hh + hd]);
        uint4 hv = *(const uint4*)(g_hh + (size_t)s * 256 + l * 8);
        __half2 p0 = *(__half2*)&hv.x, p1 = *(__half2*)&hv.y;
        __half2 p2 = *(__half2*)&hv.z, p3 = *(__half2*)&hv.w;
        float2 f0 = __half22float2(p0), f1 = __half22float2(p1);
        float2 f2 = __half22float2(p2), f3 = __half22float2(p3);
        den += a;
        acc[0] = fmaf(a, f0.x, acc[0]); acc[1] = fmaf(a, f0.y, acc[1]);
        acc[2] = fmaf(a, f1.x, acc[2]); acc[3] = fmaf(a, f1.y, acc[3]);
        acc[4] = fmaf(a, f2.x, acc[4]); acc[5] = fmaf(a, f2.y, acc[5]);
        acc[6] = fmaf(a, f3.x, acc[6]); acc[7] = fmaf(a, f3.y, acc[7]);
    }
    float r = 1.f / den;
    float4 b0 = *(const float4*)(bias_conv + l * 8);
    float4 b1 = *(const float4*)(bias_conv + l * 8 + 4);
    float o[8];
    o[0] = fmaxf(fmaf(acc[0], r, b0.x), 0.f);
    o[1] = fmaxf(fmaf(acc[1], r, b0.y), 0.f);
    o[2] = fmaxf(fmaf(acc[2], r, b0.z), 0.f);
    o[3] = fmaxf(fmaf(acc[3], r, b0.w), 0.f);
    o[4] = fmaxf(fmaf(acc[4], r, b1.x), 0.f);
    o[5] = fmaxf(fmaf(acc[5], r, b1.y), 0.f);
    o[6] = fmaxf(fmaf(acc[6], r, b1.z), 0.f);
    o[7] = fmaxf(fmaf(acc[7], r, b1.w), 0.f);
    uint4 ov;
    ((__half2*)&ov)[0] = __floats2half2_rn(o[0], o[1]);
    ((__half2*)&ov)[1] = __floats2half2_rn(o[2], o[3]);
    ((__half2*)&ov)[2] = __floats2half2_rn(o[4], o[5]);
    ((__half2*)&ov)[3] = __floats2half2_rn(o[6], o[7]);
    *(uint4*)(g_agg + (size_t)node * HC + l * 8) = ov;
}

// ---------------- fused MLP via tensor cores ----------------
// hid = relu(g_agg @ W1 + b1)  [mma, 2-term W1 split]  then out = hid @ W2 + b2.
// CTA: 128 rows; 8 warps 4x2 (warp tile 32x32); K=256 in 4 chunks.
#define MTILE_A   (128 * APAD)
#define MTILE_B   (64 * APAD)
#define MSTAGE_EL (MTILE_A + 2 * MTILE_B)
#define MLP_SMEM_BYTES (2 * MSTAGE_EL * 2)   // 73728

__global__ void __launch_bounds__(256, 1)
mlp_mma_kernel(const float* __restrict__ b1,
               const float* __restrict__ W2, const float* __restrict__ b2,
               float* __restrict__ out, int M) {
    extern __shared__ __half sm[];
    int tid  = threadIdx.x;
    int wid  = tid >> 5;
    int lane = tid & 31;
    int gid  = lane >> 2;
    int tig  = lane & 3;
    int wm   = (wid & 3) * 32;
    int wn   = (wid >> 2) * 32;
    int m0 = blockIdx.x * 128;

    float acc[2][4][4];
#pragma unroll
    for (int mt = 0; mt < 2; mt++)
#pragma unroll
        for (int nt = 0; nt < 4; nt++)
#pragma unroll
            for (int q = 0; q < 4; q++) acc[mt][nt][q] = 0.f;

    uint32_t aoff = (uint32_t)((wm + ((lane >> 3) & 1) * 8 + (lane & 7)) * APAD
                               + (lane >> 4) * 8) * 2;
    uint32_t boff = (uint32_t)((wn + (lane >> 4) * 8 + (lane & 7)) * APAD
                               + ((lane >> 3) & 1) * 8) * 2;

    auto stage_load = [&](int st, int kk) {
        __half* base = sm + st * MSTAGE_EL;
        uint32_t sA  = smem_u32(base);
        uint32_t sBh = sA + MTILE_A * 2;
        uint32_t sBl = sBh + MTILE_B * 2;
#pragma unroll
        for (int j0 = 0; j0 < 1024; j0 += 256) {
            int j = j0 + tid;
            int r = j >> 3, u = (j & 7) * 8;
            uint32_t so = (uint32_t)(r * APAD + u) * 2;
            bool am = (m0 + r) < M;
            cpa16(sA + so, g_agg + (size_t)(m0 + r) * 256 + kk + u, am);
        }
#pragma unroll
        for (int j0 = 0; j0 < 512; j0 += 256) {
            int j = j0 + tid;
            int r = j >> 3, u = (j & 7) * 8;
            uint32_t so = (uint32_t)(r * APAD + u) * 2;
            cpa16(sBh + so, g_w1hi + (size_t)r * 256 + kk + u, true);
            cpa16(sBl + so, g_w1lo + (size_t)r * 256 + kk + u, true);
        }
        CPA_COMMIT();
    };

    stage_load(0, 0);

    for (int c = 0; c < 4; c++) {
        if (c < 3) stage_load((c + 1) & 1, (c + 1) * 64);
        if (c < 3) { CPA_WAIT(1); } else { CPA_WAIT(0); }
        __syncthreads();

        uint32_t base = smem_u32(sm + (c & 1) * MSTAGE_EL);
        uint32_t aA  = base + aoff;
        uint32_t bHi = base + MTILE_A * 2 + boff;
        uint32_t bLo = bHi + MTILE_B * 2;

#pragma unroll
        for (int ks = 0; ks < 64; ks += 16) {
            uint32_t av[2][4], bh[2][4], bl[2][4];
#pragma unroll
            for (int mt = 0; mt < 2; mt++) {
                uint32_t d = (uint32_t)(mt * 16 * APAD + ks) * 2;
                ldsm_x4(av[mt], aA + d);
            }
#pragma unroll
            for (int p = 0; p < 2; p++) {
                uint32_t d = (uint32_t)(p * 16 * APAD + ks) * 2;
                ldsm_x4(bh[p], bHi + d);
                ldsm_x4(bl[p], bLo + d);
            }
#pragma unroll
            for (int mt = 0; mt < 2; mt++)
#pragma unroll
                for (int nt = 0; nt < 4; nt++)
                    mma_f16(acc[mt][nt], av[mt], &bh[nt >> 1][(nt & 1) * 2]);
#pragma unroll
            for (int mt = 0; mt < 2; mt++)
#pragma unroll
                for (int nt = 0; nt < 4; nt++)
                    mma_f16(acc[mt][nt], av[mt], &bl[nt >> 1][(nt & 1) * 2]);
        }
        __syncthreads();
    }

    // ---- epilogue: bias+relu -> sHid (smem fp16), then per-thread mlp2 ----
    __half* sHid = sm;                          // [128][66]
    float*  sW2  = (float*)(sm + 8448);         // [64][40]
    float*  sb2  = sW2 + 2560;                  // [40]

    for (int i = tid; i < 2560; i += 256) sW2[i] = W2[i];
    if (tid < 40) sb2[tid] = b2[tid];

#pragma unroll
    for (int mt = 0; mt < 2; mt++) {
        int rl = wm + mt * 16 + gid;
#pragma unroll
        for (int nt = 0; nt < 4; nt++) {
            int col = wn + nt * 8 + tig * 2;
            float bc0 = __ldg(b1 + col), bc1 = __ldg(b1 + col + 1);
            *(__half2*)(sHid + rl * 66 + col) =
                __floats2half2_rn(fmaxf(acc[mt][nt][0] + bc0, 0.f),
                                  fmaxf(acc[mt][nt][1] + bc1, 0.f));
            *(__half2*)(sHid + (rl + 8) * 66 + col) =
                __floats2half2_rn(fmaxf(acc[mt][nt][2] + bc0, 0.f),
                                  fmaxf(acc[mt][nt][3] + bc1, 0.f));
        }
    }
    __syncthreads();

    int row  = tid & 127;
    int half_ = tid >> 7;          // 0/1: which 20 output cols
    int node = m0 + row;
    if (node >= M) return;

    unsigned long long acc2[10];
#pragma unroll
    for (int j = 0; j < 10; j++) {
        float2 bv = *(const float2*)(sb2 + half_ * 20 + j * 2);
        acc2[j] = pk2(bv.x, bv.y);
    }
#pragma unroll 4
    for (int k = 0; k < HIDD; k++) {
        float xv = __half2float(sHid[row * 66 + k]);
        unsigned long long xp = pk2(xv, xv);
        const float2* wrow = (const float2*)(sW2 + k * OUTC + half_ * 20);
#pragma unroll
        for (int j = 0; j < 10; j++) {
            float2 w = wrow[j];
            acc2[j] = ffma2(xp, pk2(w.x, w.y), acc2[j]);
        }
    }
    float* orow = out + (size_t)node * OUTC + half_ * 20;
#pragma unroll
    for (int j = 0; j < 10; j++) {
        float2 v = upk2(acc2[j]);
        *(float2*)(orow + j * 2) = v;
    }
}

// ---------------- launch ----------------
extern "C" void kernel_launch(void* const* d_in, const int* in_sizes, int n_in,
                              void* d_out, int out_size) {
    const float* x         = (const float*)d_in[0];
    const int*   ei        = (const int*)d_in[1];      // int32
    const float* W         = (const float*)d_in[2];
    const float* att_src   = (const float*)d_in[3];
    const float* att_dst   = (const float*)d_in[4];
    const float* bias_conv = (const float*)d_in[5];
    const float* W1        = (const float*)d_in[6];
    const float* b1        = (const float*)d_in[7];
    const float* W2        = (const float*)d_in[8];
    const float* b2        = (const float*)d_in[9];
    float*       out       = (float*)d_out;

    int Nn = in_sizes[0] / INC;
    int E  = in_sizes[1] / 2;
    int ET = E + Nn;

    cudaFuncSetAttribute(gemm_mma_kernel,
                         cudaFuncAttributeMaxDynamicSharedMemorySize, GEMM_SMEM_BYTES);
    cudaFuncSetAttribute(mlp_mma_kernel,
                         cudaFuncAttributeMaxDynamicSharedMemorySize, MLP_SMEM_BYTES);

    gnn_init_kernel<<<(Nn + 255) / 256, 256>>>(Nn);

    int t1 = Nn * 64; if (ET > t1) t1 = ET;
    convx_deg_kernel<<<(t1 + 255) / 256, 256>>>(x, ei, Nn, E, ET);
    convw_off_kernel<<<(256 * 256 + 255) / 256, 256>>>(W, W1, Nn);

    dim3 gt((Nn + 127) / 128, 2);
    gemm_mma_kernel<<<gt, 512, GEMM_SMEM_BYTES>>>(att_src, att_dst, Nn);

    edge_fill_kernel<<<(ET + 255) / 256, 256>>>(ei, E, ET, Nn);

    agg_kernel<<<(Nn + 7) / 8, 256>>>(bias_conv, Nn);

    mlp_mma_kernel<<<(Nn + 127) / 128, 256, MLP_SMEM_BYTES>>>(b1, W2, b2, out, Nn);
}

// round 15
// speedup vs baseline: 5.6809x; 1.0673x over previous
#include <cuda_runtime.h>
#include <cuda_fp16.h>
#include <cstdint>
#include <math.h>

#define Hh   4
#define Cc   64
#define HC   256
#define INC  256
#define HIDD 64
#define OUTC 40
#define NEG  0.2f

#define N_MAX  50048
#define E_MAX  800000
#define ET_MAX (E_MAX + N_MAX)

// ---------------- static scratch ----------------
__device__ __align__(16) __half g_hh[(size_t)N_MAX * HC];    // h in fp16
__device__ __align__(16) __half g_agg[(size_t)N_MAX * HC];   // relu(agg/den+bias), fp16
__device__ float g_asrc[N_MAX * Hh];
__device__ float g_adst[N_MAX * Hh];
__device__ int   g_deg[N_MAX];
__device__ int   g_cnt[N_MAX];
__device__ int   g_off[N_MAX];
__device__ int   g_cursor;
__device__ int   g_csr_src[ET_MAX];
__device__ __align__(16) __half g_eeh[(size_t)ET_MAX * Hh];  // exp(logit), fp16

// fp16 operands for tensor-core GEMMs
__device__ __align__(16) __half g_xhi[(size_t)N_MAX * 256];
__device__ __align__(16) __half g_bhi[256 * 256];            // B[n,k] = W[k,n]
__device__ __align__(16) __half g_w1hi[64 * 256];            // W1[k,n] -> [n,k] hi
__device__ __align__(16) __half g_w1lo[64 * 256];            // lo

__device__ __forceinline__ int clampi(int v, int n) {
    return (v < 0) ? 0 : ((v >= n) ? n - 1 : v);
}

// ---------------- packed fp32x2 helpers ----------------
__device__ __forceinline__ unsigned long long pk2(float lo, float hi) {
    unsigned long long r;
    asm("mov.b64 %0, {%1, %2};" : "=l"(r) : "f"(lo), "f"(hi));
    return r;
}
__device__ __forceinline__ float2 upk2(unsigned long long v) {
    float lo, hi;
    asm("mov.b64 {%0, %1}, %2;" : "=f"(lo), "=f"(hi) : "l"(v));
    return make_float2(lo, hi);
}
__device__ __forceinline__ unsigned long long ffma2(unsigned long long a,
                                                    unsigned long long b,
                                                    unsigned long long c) {
    unsigned long long d;
    asm("fma.rn.f32x2 %0, %1, %2, %3;" : "=l"(d) : "l"(a), "l"(b), "l"(c));
    return d;
}

// ---------------- warp-level fp16 MMA + ldmatrix ----------------
__device__ __forceinline__ void mma_f16(float* d, const uint32_t* a, const uint32_t* b) {
    asm volatile(
        "mma.sync.aligned.m16n8k16.row.col.f32.f16.f16.f32 "
        "{%0,%1,%2,%3}, {%4,%5,%6,%7}, {%8,%9}, {%0,%1,%2,%3};"
        : "+f"(d[0]), "+f"(d[1]), "+f"(d[2]), "+f"(d[3])
        : "r"(a[0]), "r"(a[1]), "r"(a[2]), "r"(a[3]), "r"(b[0]), "r"(b[1]));
}
__device__ __forceinline__ void ldsm_x4(uint32_t* r, uint32_t addr) {
    asm volatile("ldmatrix.sync.aligned.m8n8.x4.shared.b16 {%0,%1,%2,%3}, [%4];"
                 : "=r"(r[0]), "=r"(r[1]), "=r"(r[2]), "=r"(r[3]) : "r"(addr));
}

// ---------------- cp.async helpers ----------------
__device__ __forceinline__ uint32_t smem_u32(const void* p) {
    uint32_t a;
    asm("{ .reg .u64 t; cvta.to.shared.u64 t, %1; cvt.u32.u64 %0, t; }" : "=r"(a) : "l"(p));
    return a;
}
__device__ __forceinline__ void cpa16(uint32_t dst, const void* src, bool pred) {
    int sz = pred ? 16 : 0;
    asm volatile("cp.async.cg.shared.global [%0], [%1], 16, %2;"
                 :: "r"(dst), "l"(src), "r"(sz));
}
#define CPA_COMMIT() asm volatile("cp.async.commit_group;" ::: "memory")
#define CPA_WAIT(n)  asm volatile("cp.async.wait_group %0;" :: "n"(n) : "memory")

// ---------------- init ----------------
__global__ void gnn_init_kernel(int Nn) {
    int i = blockIdx.x * blockDim.x + threadIdx.x;
    if (i < Nn) { g_deg[i] = 0; g_cnt[i] = 0; }
    if (i == 0) g_cursor = 0;
}

// ---------------- fused: fp32->fp16 x  +  edge in-degree count ----------------
__global__ void convx_deg_kernel(const float* __restrict__ x,
                                 const int* __restrict__ ei,
                                 int Nn, int E, int ET) {
    int i = blockIdx.x * blockDim.x + threadIdx.x;
    int tot = Nn * 64;
    if (i < tot) {
        float4 v = ((const float4*)x)[i];
        __half2* ph = (__half2*)g_xhi;
        ph[i * 2 + 0] = __floats2half2_rn(v.x, v.y);
        ph[i * 2 + 1] = __floats2half2_rn(v.z, v.w);
    }
    if (i < ET) {
        int d = (i < E) ? clampi(ei[(size_t)E + i], Nn) : (i - E);
        atomicAdd(&g_deg[d], 1);
    }
}

// ---------------- fused: W -> bhi, W1 -> w1hi/lo, CSR offsets ----------------
__global__ void convw_off_kernel(const float* __restrict__ W,
                                 const float* __restrict__ W1, int Nn) {
    int idx = blockIdx.x * blockDim.x + threadIdx.x;
    if (idx < 256 * 256) {
        int n = idx & 255, k = idx >> 8;
        g_bhi[n * 256 + k] = __float2half_rn(W[k * 256 + n]);
    }
    if (idx < 64 * 256) {
        int n = idx & 63, k = idx >> 6;
        float w = W1[k * 64 + n];
        __half h = __float2half_rn(w);
        __half l = __float2half_rn(w - __half2float(h));
        g_w1hi[n * 256 + k] = h;
        g_w1lo[n * 256 + k] = l;
    }
    if (idx < Nn)
        g_off[idx] = atomicAdd(&g_cursor, g_deg[idx]);
}

// ---------------- tensor GEMM (1-term fp16) + fused attention epilogue ----------------
// 256 threads, 8 warps 4m x 2n (warp tile 32x64), 2 CTAs/SM for overlap.
#define APAD    72
#define TILE_EL (128 * APAD)
#define STAGE_EL (2 * TILE_EL)
#define GEMM_SMEM_BYTES (2 * STAGE_EL * 2)   // 73728

__global__ void __launch_bounds__(256, 2)
gemm_mma_kernel(const float* __restrict__ att_src,
                const float* __restrict__ att_dst, int Nn) {
    extern __shared__ __half sm[];
    int tid  = threadIdx.x;
    int wid  = tid >> 5;
    int lane = tid & 31;
    int gid  = lane >> 2;
    int tig  = lane & 3;
    int wm   = (wid & 3) * 32;
    int wn   = (wid >> 2) * 64;
    int m0 = blockIdx.x * 128;
    int n0 = blockIdx.y * 128;

    float acc[2][8][4];
#pragma unroll
    for (int mt = 0; mt < 2; mt++)
#pragma unroll
        for (int nt = 0; nt < 8; nt++)
#pragma unroll
            for (int q = 0; q < 4; q++) acc[mt][nt][q] = 0.f;

    uint32_t aoff = (uint32_t)((wm + ((lane >> 3) & 1) * 8 + (lane & 7)) * APAD
                               + (lane >> 4) * 8) * 2;
    uint32_t boff = (uint32_t)((wn + (lane >> 4) * 8 + (lane & 7)) * APAD
                               + ((lane >> 3) & 1) * 8) * 2;

    auto stage_load = [&](int st, int kk) {
        __half* base = sm + st * STAGE_EL;
        uint32_t sA = smem_u32(base);
        uint32_t sB = sA + TILE_EL * 2;
#pragma unroll
        for (int j0 = 0; j0 < 1024; j0 += 256) {
            int j = j0 + tid;
            int r = j >> 3, u = (j & 7) * 8;
            uint32_t so = (uint32_t)(r * APAD + u) * 2;
            bool am = (m0 + r) < Nn;
            size_t ga = (size_t)(m0 + r) * 256 + kk + u;
            size_t gb = (size_t)(n0 + r) * 256 + kk + u;
            cpa16(sA + so, g_xhi + ga, am);
            cpa16(sB + so, g_bhi + gb, true);
        }
        CPA_COMMIT();
    };

    stage_load(0, 0);

    for (int c = 0; c < 4; c++) {
        if (c < 3) stage_load((c + 1) & 1, (c + 1) * 64);
        if (c < 3) { CPA_WAIT(1); } else { CPA_WAIT(0); }
        __syncthreads();

        uint32_t base = smem_u32(sm + (c & 1) * STAGE_EL);
        uint32_t aHi = base + aoff;
        uint32_t bHi = base + TILE_EL * 2 + boff;

#pragma unroll
        for (int ks = 0; ks < 64; ks += 16) {
            uint32_t ahi[2][4], bhi[4][4];
#pragma unroll
            for (int mt = 0; mt < 2; mt++) {
                uint32_t d = (uint32_t)(mt * 16 * APAD + ks) * 2;
                ldsm_x4(ahi[mt], aHi + d);
            }
#pragma unroll
            for (int p = 0; p < 4; p++) {
                uint32_t d = (uint32_t)(p * 16 * APAD + ks) * 2;
                ldsm_x4(bhi[p], bHi + d);
            }
#pragma unroll
            for (int mt = 0; mt < 2; mt++)
#pragma unroll
                for (int nt = 0; nt < 8; nt++)
                    mma_f16(acc[mt][nt], ahi[mt], &bhi[nt >> 1][(nt & 1) * 2]);
        }
        __syncthreads();
    }

    // ---- epilogue 1: store h as fp16 ----
#pragma unroll
    for (int mt = 0; mt < 2; mt++) {
        int row = m0 + wm + mt * 16 + gid;
#pragma unroll
        for (int nt = 0; nt < 8; nt++) {
            int col = n0 + wn + nt * 8 + tig * 2;
            if (row < Nn)
                *(__half2*)(g_hh + (size_t)row * 256 + col) =
                    __floats2half2_rn(acc[mt][nt][0], acc[mt][nt][1]);
            if (row + 8 < Nn)
                *(__half2*)(g_hh + (size_t)(row + 8) * 256 + col) =
                    __floats2half2_rn(acc[mt][nt][2], acc[mt][nt][3]);
        }
    }

    // ---- epilogue 2: fused attention logits ----
    float* sA = (float*)sm;          // [128][2]
    float* sD = sA + 256;            // [128][2]
    if (tid < 256) { sA[tid] = 0.f; sD[tid] = 0.f; }
    __syncthreads();

    int lh = wn >> 6;                // local head 0/1 (warp-uniform)
    const float* ats = att_src + (blockIdx.y * 2 + lh) * 64;
    const float* atd = att_dst + (blockIdx.y * 2 + lh) * 64;

#pragma unroll
    for (int mt = 0; mt < 2; mt++) {
        float s0 = 0.f, d0 = 0.f, s1 = 0.f, d1 = 0.f;
#pragma unroll
        for (int nt = 0; nt < 8; nt++)
#pragma unroll
            for (int q = 0; q < 2; q++) {
                int cc = nt * 8 + tig * 2 + q;   // 0..63 within head
                float ws = __ldg(ats + cc);
                float wd = __ldg(atd + cc);
                s0 = fmaf(acc[mt][nt][q], ws, s0);
                d0 = fmaf(acc[mt][nt][q], wd, d0);
                s1 = fmaf(acc[mt][nt][q + 2], ws, s1);
                d1 = fmaf(acc[mt][nt][q + 2], wd, d1);
            }
#pragma unroll
        for (int off = 1; off <= 2; off <<= 1) {
            s0 += __shfl_xor_sync(0xffffffffu, s0, off);
            d0 += __shfl_xor_sync(0xffffffffu, d0, off);
            s1 += __shfl_xor_sync(0xffffffffu, s1, off);
            d1 += __shfl_xor_sync(0xffffffffu, d1, off);
        }
        if (tig == 0) {
            int r0 = wm + mt * 16 + gid;
            atomicAdd(&sA[r0 * 2 + lh], s0);
            atomicAdd(&sD[r0 * 2 + lh], d0);
            atomicAdd(&sA[(r0 + 8) * 2 + lh], s1);
            atomicAdd(&sD[(r0 + 8) * 2 + lh], d1);
        }
    }
    __syncthreads();
    if (tid < 256) {
        int r = tid >> 1, h2 = tid & 1;
        int grow = m0 + r;
        if (grow < Nn) {
            int gh = blockIdx.y * 2 + h2;
            g_asrc[grow * 4 + gh] = sA[r * 2 + h2];
            g_adst[grow * 4 + gh] = sD[r * 2 + h2];
        }
    }
}

// ---------------- edge pass: exp(leaky(logit)) -> CSR slots (fp16) ----------------
__global__ void edge_fill_kernel(const int* __restrict__ ei, int E, int ET, int Nn) {
    int e = blockIdx.x * blockDim.x + threadIdx.x;
    if (e >= ET) return;
    int s, d;
    if (e < E) { s = clampi(ei[e], Nn); d = clampi(ei[(size_t)E + e], Nn); }
    else       { s = d = e - E; }
    float4 as = *(const float4*)(g_asrc + (size_t)s * Hh);
    float4 ad = *(const float4*)(g_adst + (size_t)d * Hh);
    float v[4];
    v[0] = as.x + ad.x; v[1] = as.y + ad.y; v[2] = as.z + ad.z; v[3] = as.w + ad.w;
#pragma unroll
    for (int h = 0; h < 4; h++) {
        float lv = (v[h] > 0.f) ? v[h] : NEG * v[h];
        v[h] = __expf(lv);
    }
    int slot = g_off[d] + atomicAdd(&g_cnt[d], 1);
    g_csr_src[slot] = s;
    uint2 pv;
    *(__half2*)&pv.x = __floats2half2_rn(v[0], v[1]);
    *(__half2*)&pv.y = __floats2half2_rn(v[2], v[3]);
    *(uint2*)(g_eeh + (size_t)slot * Hh) = pv;
}

// ---------------- aggregation: 32 threads/node, fp16 gather/weights, fp16 out ----------------
__global__ void agg_kernel(const float* __restrict__ bias_conv, int Nn) {
    int node = blockIdx.x * 8 + (threadIdx.x >> 5);
    int l    = threadIdx.x & 31;
    if (node >= Nn) return;
    int beg = g_off[node];
    int deg = g_deg[node];
    int hd  = l >> 3;

    float acc[8];
#pragma unroll
    for (int q = 0; q < 8; q++) acc[q] = 0.f;
    float den = 0.f;
#pragma unroll 2
    for (int i = 0; i < deg; i++) {
        int slot = beg + i;
        int s    = g_csr_src[slot];
        float a  = __half2float(g_eeh[(size_t)slot * Hh + hd]);
        uint4 hv = *(const uint4*)(g_hh + (size_t)s * 256 + l * 8);
        __half2 p0 = *(__half2*)&hv.x, p1 = *(__half2*)&hv.y;
        __half2 p2 = *(__half2*)&hv.z, p3 = *(__half2*)&hv.w;
        float2 f0 = __half22float2(p0), f1 = __half22float2(p1);
        float2 f2 = __half22float2(p2), f3 = __half22float2(p3);
        den += a;
        acc[0] = fmaf(a, f0.x, acc[0]); acc[1] = fmaf(a, f0.y, acc[1]);
        acc[2] = fmaf(a, f1.x, acc[2]); acc[3] = fmaf(a, f1.y, acc[3]);
        acc[4] = fmaf(a, f2.x, acc[4]); acc[5] = fmaf(a, f2.y, acc[5]);
        acc[6] = fmaf(a, f3.x, acc[6]); acc[7] = fmaf(a, f3.y, acc[7]);
    }
    float r = 1.f / den;
    float4 b0 = *(const float4*)(bias_conv + l * 8);
    float4 b1 = *(const float4*)(bias_conv + l * 8 + 4);
    float o[8];
    o[0] = fmaxf(fmaf(acc[0], r, b0.x), 0.f);
    o[1] = fmaxf(fmaf(acc[1], r, b0.y), 0.f);
    o[2] = fmaxf(fmaf(acc[2], r, b0.z), 0.f);
    o[3] = fmaxf(fmaf(acc[3], r, b0.w), 0.f);
    o[4] = fmaxf(fmaf(acc[4], r, b1.x), 0.f);
    o[5] = fmaxf(fmaf(acc[5], r, b1.y), 0.f);
    o[6] = fmaxf(fmaf(acc[6], r, b1.z), 0.f);
    o[7] = fmaxf(fmaf(acc[7], r, b1.w), 0.f);
    uint4 ov;
    ((__half2*)&ov)[0] = __floats2half2_rn(o[0], o[1]);
    ((__half2*)&ov)[1] = __floats2half2_rn(o[2], o[3]);
    ((__half2*)&ov)[2] = __floats2half2_rn(o[4], o[5]);
    ((__half2*)&ov)[3] = __floats2half2_rn(o[6], o[7]);
    *(uint4*)(g_agg + (size_t)node * HC + l * 8) = ov;
}

// ---------------- fused MLP via tensor cores (2 CTAs/SM) ----------------
#define MTILE_A   (128 * APAD)
#define MTILE_B   (64 * APAD)
#define MSTAGE_EL (MTILE_A + 2 * MTILE_B)
#define MLP_SMEM_BYTES (2 * MSTAGE_EL * 2)   // 73728

__global__ void __launch_bounds__(256, 2)
mlp_mma_kernel(const float* __restrict__ b1,
               const float* __restrict__ W2, const float* __restrict__ b2,
               float* __restrict__ out, int M) {
    extern __shared__ __half sm[];
    int tid  = threadIdx.x;
    int wid  = tid >> 5;
    int lane = tid & 31;
    int gid  = lane >> 2;
    int tig  = lane & 3;
    int wm   = (wid & 3) * 32;
    int wn   = (wid >> 2) * 32;
    int m0 = blockIdx.x * 128;

    float acc[2][4][4];
#pragma unroll
    for (int mt = 0; mt < 2; mt++)
#pragma unroll
        for (int nt = 0; nt < 4; nt++)
#pragma unroll
            for (int q = 0; q < 4; q++) acc[mt][nt][q] = 0.f;

    uint32_t aoff = (uint32_t)((wm + ((lane >> 3) & 1) * 8 + (lane & 7)) * APAD
                               + (lane >> 4) * 8) * 2;
    uint32_t boff = (uint32_t)((wn + (lane >> 4) * 8 + (lane & 7)) * APAD
                               + ((lane >> 3) & 1) * 8) * 2;

    auto stage_load = [&](int st, int kk) {
        __half* base = sm + st * MSTAGE_EL;
        uint32_t sA  = smem_u32(base);
        uint32_t sBh = sA + MTILE_A * 2;
        uint32_t sBl = sBh + MTILE_B * 2;
#pragma unroll
        for (int j0 = 0; j0 < 1024; j0 += 256) {
            int j = j0 + tid;
            int r = j >> 3, u = (j & 7) * 8;
            uint32_t so = (uint32_t)(r * APAD + u) * 2;
            bool am = (m0 + r) < M;
            cpa16(sA + so, g_agg + (size_t)(m0 + r) * 256 + kk + u, am);
        }
#pragma unroll
        for (int j0 = 0; j0 < 512; j0 += 256) {
            int j = j0 + tid;
            int r = j >> 3, u = (j & 7) * 8;
            uint32_t so = (uint32_t)(r * APAD + u) * 2;
            cpa16(sBh + so, g_w1hi + (size_t)r * 256 + kk + u, true);
            cpa16(sBl + so, g_w1lo + (size_t)r * 256 + kk + u, true);
        }
        CPA_COMMIT();
    };

    stage_load(0, 0);

    for (int c = 0; c < 4; c++) {
        if (c < 3) stage_load((c + 1) & 1, (c + 1) * 64);
        if (c < 3) { CPA_WAIT(1); } else { CPA_WAIT(0); }
        __syncthreads();

        uint32_t base = smem_u32(sm + (c & 1) * MSTAGE_EL);
        uint32_t aA  = base + aoff;
        uint32_t bHi = base + MTILE_A * 2 + boff;
        uint32_t bLo = bHi + MTILE_B * 2;

#pragma unroll
        for (int ks = 0; ks < 64; ks += 16) {
            uint32_t av[2][4], bh[2][4], bl[2][4];
#pragma unroll
            for (int mt = 0; mt < 2; mt++) {
                uint32_t d = (uint32_t)(mt * 16 * APAD + ks) * 2;
                ldsm_x4(av[mt], aA + d);
            }
#pragma unroll
            for (int p = 0; p < 2; p++) {
                uint32_t d = (uint32_t)(p * 16 * APAD + ks) * 2;
                ldsm_x4(bh[p], bHi + d);
                ldsm_x4(bl[p], bLo + d);
            }
#pragma unroll
            for (int mt = 0; mt < 2; mt++)
#pragma unroll
                for (int nt = 0; nt < 4; nt++)
                    mma_f16(acc[mt][nt], av[mt], &bh[nt >> 1][(nt & 1) * 2]);
#pragma unroll
            for (int mt = 0; mt < 2; mt++)
#pragma unroll
                for (int nt = 0; nt < 4; nt++)
                    mma_f16(acc[mt][nt], av[mt], &bl[nt >> 1][(nt & 1) * 2]);
        }
        __syncthreads();
    }

    // ---- epilogue: bias+relu -> sHid (smem fp16), then per-thread mlp2 ----
    __half* sHid = sm;                          // [128][66]
    float*  sW2  = (float*)(sm + 8448);         // [64][40]
    float*  sb2  = sW2 + 2560;                  // [40]

    for (int i = tid; i < 2560; i += 256) sW2[i] = W2[i];
    if (tid < 40) sb2[tid] = b2[tid];

#pragma unroll
    for (int mt = 0; mt < 2; mt++) {
        int rl = wm + mt * 16 + gid;
#pragma unroll
        for (int nt = 0; nt < 4; nt++) {
            int col = wn + nt * 8 + tig * 2;
            float bc0 = __ldg(b1 + col), bc1 = __ldg(b1 + col + 1);
            *(__half2*)(sHid + rl * 66 + col) =
                __floats2half2_rn(fmaxf(acc[mt][nt][0] + bc0, 0.f),
                                  fmaxf(acc[mt][nt][1] + bc1, 0.f));
            *(__half2*)(sHid + (rl + 8) * 66 + col) =
                __floats2half2_rn(fmaxf(acc[mt][nt][2] + bc0, 0.f),
                                  fmaxf(acc[mt][nt][3] + bc1, 0.f));
        }
    }
    __syncthreads();

    int row  = tid & 127;
    int half_ = tid >> 7;          // 0/1: which 20 output cols
    int node = m0 + row;
    if (node >= M) return;

    unsigned long long acc2[10];
#pragma unroll
    for (int j = 0; j < 10; j++) {
        float2 bv = *(const float2*)(sb2 + half_ * 20 + j * 2);
        acc2[j] = pk2(bv.x, bv.y);
    }
#pragma unroll 4
    for (int k = 0; k < HIDD; k++) {
        float xv = __half2float(sHid[row * 66 + k]);
        unsigned long long xp = pk2(xv, xv);
        const float2* wrow = (const float2*)(sW2 + k * OUTC + half_ * 20);
#pragma unroll
        for (int j = 0; j < 10; j++) {
            float2 w = wrow[j];
            acc2[j] = ffma2(xp, pk2(w.x, w.y), acc2[j]);
        }
    }
    float* orow = out + (size_t)node * OUTC + half_ * 20;
#pragma unroll
    for (int j = 0; j < 10; j++) {
        float2 v = upk2(acc2[j]);
        *(float2*)(orow + j * 2) = v;
    }
}

// ---------------- launch ----------------
extern "C" void kernel_launch(void* const* d_in, const int* in_sizes, int n_in,
                              void* d_out, int out_size) {
    const float* x         = (const float*)d_in[0];
    const int*   ei        = (const int*)d_in[1];      // int32
    const float* W         = (const float*)d_in[2];
    const float* att_src   = (const float*)d_in[3];
    const float* att_dst   = (const float*)d_in[4];
    const float* bias_conv = (const float*)d_in[5];
    const float* W1        = (const float*)d_in[6];
    const float* b1        = (const float*)d_in[7];
    const float* W2        = (const float*)d_in[8];
    const float* b2        = (const float*)d_in[9];
    float*       out       = (float*)d_out;

    int Nn = in_sizes[0] / INC;
    int E  = in_sizes[1] / 2;
    int ET = E + Nn;

    cudaFuncSetAttribute(gemm_mma_kernel,
                         cudaFuncAttributeMaxDynamicSharedMemorySize, GEMM_SMEM_BYTES);
    cudaFuncSetAttribute(mlp_mma_kernel,
                         cudaFuncAttributeMaxDynamicSharedMemorySize, MLP_SMEM_BYTES);

    gnn_init_kernel<<<(Nn + 255) / 256, 256>>>(Nn);

    int t1 = Nn * 64; if (ET > t1) t1 = ET;
    convx_deg_kernel<<<(t1 + 255) / 256, 256>>>(x, ei, Nn, E, ET);
    convw_off_kernel<<<(256 * 256 + 255) / 256, 256>>>(W, W1, Nn);

    dim3 gt((Nn + 127) / 128, 2);
    gemm_mma_kernel<<<gt, 256, GEMM_SMEM_BYTES>>>(att_src, att_dst, Nn);

    edge_fill_kernel<<<(ET + 255) / 256, 256>>>(ei, E, ET, Nn);

    agg_kernel<<<(Nn + 7) / 8, 256>>>(bias_conv, Nn);

    mlp_mma_kernel<<<(Nn + 127) / 128, 256, MLP_SMEM_BYTES>>>(b1, W2, b2, out, Nn);
}